// round 1
// baseline (speedup 1.0000x reference)
#include <cuda_runtime.h>
#include <math.h>

// Problem constants
#define BATCH 4
#define SEQ   2048
#define DM    768
#define NH    12
#define HD    64
#define MROWS (BATCH*SEQ)   // 8192
#define BHT   (BATCH*NH)    // 48

// Scratch (allocation-free rule: __device__ globals)
__device__ float g_Q[(size_t)BHT*SEQ*HD];   // [b,h,s,d], pre-scaled by 1/sqrt(64)
__device__ float g_K[(size_t)BHT*SEQ*HD];
__device__ float g_V[(size_t)BHT*SEQ*HD];
__device__ float g_OH[(size_t)MROWS*DM];    // attention out, [b,s, h*64+d]

// ---------------------------------------------------------------------------
// Kernel 1: QKV projection.  C[8192x768] = x[8192x768] @ W[768x768]
// 128x64 block tile, BK=16, 256 threads, 8x4 microtile.
// blockIdx.z selects Wq/Wk/Wv; epilogue writes [b,h,s,d] layout.
// ---------------------------------------------------------------------------
__global__ __launch_bounds__(256) void qkv_gemm(
    const float* __restrict__ x,
    const float* __restrict__ Wq,
    const float* __restrict__ Wk,
    const float* __restrict__ Wv)
{
    __shared__ float As[16][132];   // transposed A tile, padded
    __shared__ float Bs[16][64];

    int which = blockIdx.z;
    const float* W = (which == 0) ? Wq : (which == 1 ? Wk : Wv);
    float* dst = (which == 0) ? g_Q : (which == 1 ? g_K : g_V);
    const float alpha = (which == 0) ? 0.125f : 1.0f;   // 1/sqrt(64)

    int tid  = threadIdx.x;
    int trow = tid >> 4;   // 0..15 -> rows trow*8
    int tcol = tid & 15;   // 0..15 -> cols tcol*4
    int m0 = blockIdx.y * 128;
    int n0 = blockIdx.x * 64;

    float acc[8][4];
    #pragma unroll
    for (int i = 0; i < 8; i++)
        #pragma unroll
        for (int j = 0; j < 4; j++) acc[i][j] = 0.f;

    for (int k0 = 0; k0 < DM; k0 += 16) {
        #pragma unroll
        for (int t = 0; t < 2; t++) {
            int i  = tid + t * 256;      // 0..511 float4 slots (128 rows x 4)
            int r  = i >> 2;
            int c4 = (i & 3) * 4;
            float4 v = *reinterpret_cast<const float4*>(
                x + (size_t)(m0 + r) * DM + k0 + c4);
            As[c4 + 0][r] = v.x; As[c4 + 1][r] = v.y;
            As[c4 + 2][r] = v.z; As[c4 + 3][r] = v.w;
        }
        {
            int r  = tid >> 4;
            int c4 = (tid & 15) * 4;
            *reinterpret_cast<float4*>(&Bs[r][c4]) =
                *reinterpret_cast<const float4*>(W + (size_t)(k0 + r) * DM + n0 + c4);
        }
        __syncthreads();
        #pragma unroll
        for (int kk = 0; kk < 16; kk++) {
            float4 a0 = *reinterpret_cast<const float4*>(&As[kk][trow * 8]);
            float4 a1 = *reinterpret_cast<const float4*>(&As[kk][trow * 8 + 4]);
            float4 b4 = *reinterpret_cast<const float4*>(&Bs[kk][tcol * 4]);
            float a[8] = {a0.x, a0.y, a0.z, a0.w, a1.x, a1.y, a1.z, a1.w};
            float b[4] = {b4.x, b4.y, b4.z, b4.w};
            #pragma unroll
            for (int i = 0; i < 8; i++)
                #pragma unroll
                for (int j = 0; j < 4; j++) acc[i][j] += a[i] * b[j];
        }
        __syncthreads();
    }

    int h = blockIdx.x;   // BN=64 -> one head per block column
    #pragma unroll
    for (int i = 0; i < 8; i++) {
        int m = m0 + trow * 8 + i;
        int b = m >> 11;
        int s = m & 2047;
        float4 v = make_float4(acc[i][0] * alpha, acc[i][1] * alpha,
                               acc[i][2] * alpha, acc[i][3] * alpha);
        *reinterpret_cast<float4*>(
            dst + (((size_t)(b * NH + h)) * SEQ + s) * HD + tcol * 4) = v;
    }
}

// ---------------------------------------------------------------------------
// Kernel 2: logits_raw[bh, q, k] = Q[bh,q,:] . K[bh,k,:]   (K-dim = 64)
// 64x64 tile per block, full K in smem, 256 threads, 4x4 microtile.
// Writes directly into d_out logits region (RAW, no mask).
// ---------------------------------------------------------------------------
__global__ __launch_bounds__(256) void logits_gemm(float* __restrict__ logits)
{
    __shared__ float Qs[64][80];   // Qs[d][q_local]
    __shared__ float Ks[64][80];   // Ks[d][k_local]

    int bh = blockIdx.z;
    int q0 = blockIdx.y * 64;
    int k0 = blockIdx.x * 64;
    const float* Qb = g_Q + (size_t)bh * SEQ * HD;
    const float* Kb = g_K + (size_t)bh * SEQ * HD;
    int tid = threadIdx.x;

    #pragma unroll
    for (int t = 0; t < 4; t++) {
        int i  = tid + t * 256;   // 0..1023
        int r  = i >> 4;          // 0..63
        int c4 = (i & 15) * 4;    // 0..60
        float4 q = *reinterpret_cast<const float4*>(Qb + (size_t)(q0 + r) * HD + c4);
        Qs[c4 + 0][r] = q.x; Qs[c4 + 1][r] = q.y;
        Qs[c4 + 2][r] = q.z; Qs[c4 + 3][r] = q.w;
        float4 k = *reinterpret_cast<const float4*>(Kb + (size_t)(k0 + r) * HD + c4);
        Ks[c4 + 0][r] = k.x; Ks[c4 + 1][r] = k.y;
        Ks[c4 + 2][r] = k.z; Ks[c4 + 3][r] = k.w;
    }
    __syncthreads();

    int trow = tid >> 4;
    int tcol = tid & 15;
    float acc[4][4];
    #pragma unroll
    for (int i = 0; i < 4; i++)
        #pragma unroll
        for (int j = 0; j < 4; j++) acc[i][j] = 0.f;

    #pragma unroll
    for (int d = 0; d < 64; d++) {
        float4 a4 = *reinterpret_cast<const float4*>(&Qs[d][trow * 4]);
        float4 b4 = *reinterpret_cast<const float4*>(&Ks[d][tcol * 4]);
        float a[4] = {a4.x, a4.y, a4.z, a4.w};
        float b[4] = {b4.x, b4.y, b4.z, b4.w};
        #pragma unroll
        for (int i = 0; i < 4; i++)
            #pragma unroll
            for (int j = 0; j < 4; j++) acc[i][j] += a[i] * b[j];
    }

    float* Cb = logits + ((size_t)bh * SEQ + q0) * SEQ + k0;
    #pragma unroll
    for (int i = 0; i < 4; i++) {
        float4 v = make_float4(acc[i][0], acc[i][1], acc[i][2], acc[i][3]);
        *reinterpret_cast<float4*>(Cb + (size_t)(trow * 4 + i) * SEQ + tcol * 4) = v;
    }
}

// ---------------------------------------------------------------------------
// Kernel 3: flash-style softmax(logits+mask) @ V, single pass over logits.
// Block = (b,h, 32-row q-tile). 256 threads: thread = r*8+c,
// r=row (0..31), c=d-group (0..7, 8 floats each). Online max/sum.
// ---------------------------------------------------------------------------
__global__ __launch_bounds__(256) void attn_pv(const float* __restrict__ logits,
                                               const float* __restrict__ q_mask)
{
    __shared__ float Vs[64][64];
    __shared__ float Ps[32][72];
    __shared__ float Ms[64];

    int bh = blockIdx.y;
    int b  = bh / NH;
    int h  = bh - b * NH;
    int q0 = blockIdx.x * 32;
    int tid = threadIdx.x;
    int r = tid >> 3;   // 0..31
    int c = tid & 7;    // 0..7

    float qm = q_mask[(size_t)b * SEQ + q0 + r];
    const float* Vb = g_V + (size_t)bh * SEQ * HD;
    const float* Lrow = logits + ((size_t)bh * SEQ + q0 + r) * SEQ;

    float acc[8];
    #pragma unroll
    for (int j = 0; j < 8; j++) acc[j] = 0.f;
    float mrun = -3.0e38f, srun = 0.f;

    for (int kt = 0; kt < SEQ / 64; kt++) {
        int k0 = kt * 64;
        // logits for this thread's 8 columns -> registers
        float4 l0 = *reinterpret_cast<const float4*>(Lrow + k0 + c * 8);
        float4 l1 = *reinterpret_cast<const float4*>(Lrow + k0 + c * 8 + 4);
        // V tile -> smem
        #pragma unroll
        for (int t = 0; t < 4; t++) {
            int i  = tid + t * 256;
            int rv = i >> 4;
            int c4 = (i & 15) * 4;
            *reinterpret_cast<float4*>(&Vs[rv][c4]) =
                *reinterpret_cast<const float4*>(Vb + (size_t)(k0 + rv) * HD + c4);
        }
        if (tid < 64) Ms[tid] = q_mask[(size_t)b * SEQ + k0 + tid];
        __syncthreads();

        float le[8] = {l0.x, l0.y, l0.z, l0.w, l1.x, l1.y, l1.z, l1.w};
        float tmax = -3.0e38f;
        #pragma unroll
        for (int j = 0; j < 8; j++) {
            float km = Ms[c * 8 + j];
            le[j] += -100000.0f * (1.0f - qm * km);
            tmax = fmaxf(tmax, le[j]);
        }
        tmax = fmaxf(tmax, __shfl_xor_sync(0xffffffffu, tmax, 1));
        tmax = fmaxf(tmax, __shfl_xor_sync(0xffffffffu, tmax, 2));
        tmax = fmaxf(tmax, __shfl_xor_sync(0xffffffffu, tmax, 4));

        float mnew = fmaxf(mrun, tmax);
        float rescale = __expf(mrun - mnew);
        #pragma unroll
        for (int j = 0; j < 8; j++) acc[j] *= rescale;
        srun *= rescale;

        float psum = 0.f;
        #pragma unroll
        for (int j = 0; j < 8; j++) {
            float p = __expf(le[j] - mnew);
            Ps[r][c * 8 + j] = p;
            psum += p;
        }
        mrun = mnew;
        psum += __shfl_xor_sync(0xffffffffu, psum, 1);
        psum += __shfl_xor_sync(0xffffffffu, psum, 2);
        psum += __shfl_xor_sync(0xffffffffu, psum, 4);
        srun += psum;
        __syncwarp();   // Ps produced/consumed within the same warp

        #pragma unroll 8
        for (int kk = 0; kk < 64; kk++) {
            float p = Ps[r][kk];
            float4 v0 = *reinterpret_cast<const float4*>(&Vs[kk][c * 8]);
            float4 v1 = *reinterpret_cast<const float4*>(&Vs[kk][c * 8 + 4]);
            acc[0] += p * v0.x; acc[1] += p * v0.y;
            acc[2] += p * v0.z; acc[3] += p * v0.w;
            acc[4] += p * v1.x; acc[5] += p * v1.y;
            acc[6] += p * v1.z; acc[7] += p * v1.w;
        }
        __syncthreads();
    }

    float inv = 1.0f / srun;
    float* dst = g_OH + ((size_t)b * SEQ + q0 + r) * DM + h * HD + c * 8;
    float4 o0 = make_float4(acc[0] * inv, acc[1] * inv, acc[2] * inv, acc[3] * inv);
    float4 o1 = make_float4(acc[4] * inv, acc[5] * inv, acc[6] * inv, acc[7] * inv);
    *reinterpret_cast<float4*>(dst)     = o0;
    *reinterpret_cast<float4*>(dst + 4) = o1;
}

// ---------------------------------------------------------------------------
// Kernel 4: out[8192x768] = g_OH @ Wo   (same tiling as kernel 1, plain store)
// ---------------------------------------------------------------------------
__global__ __launch_bounds__(256) void out_gemm(const float* __restrict__ Wo,
                                                float* __restrict__ out)
{
    __shared__ float As[16][132];
    __shared__ float Bs[16][64];

    int tid  = threadIdx.x;
    int trow = tid >> 4;
    int tcol = tid & 15;
    int m0 = blockIdx.y * 128;
    int n0 = blockIdx.x * 64;

    float acc[8][4];
    #pragma unroll
    for (int i = 0; i < 8; i++)
        #pragma unroll
        for (int j = 0; j < 4; j++) acc[i][j] = 0.f;

    for (int k0 = 0; k0 < DM; k0 += 16) {
        #pragma unroll
        for (int t = 0; t < 2; t++) {
            int i  = tid + t * 256;
            int r  = i >> 2;
            int c4 = (i & 3) * 4;
            float4 v = *reinterpret_cast<const float4*>(
                g_OH + (size_t)(m0 + r) * DM + k0 + c4);
            As[c4 + 0][r] = v.x; As[c4 + 1][r] = v.y;
            As[c4 + 2][r] = v.z; As[c4 + 3][r] = v.w;
        }
        {
            int r  = tid >> 4;
            int c4 = (tid & 15) * 4;
            *reinterpret_cast<float4*>(&Bs[r][c4]) =
                *reinterpret_cast<const float4*>(Wo + (size_t)(k0 + r) * DM + n0 + c4);
        }
        __syncthreads();
        #pragma unroll
        for (int kk = 0; kk < 16; kk++) {
            float4 a0 = *reinterpret_cast<const float4*>(&As[kk][trow * 8]);
            float4 a1 = *reinterpret_cast<const float4*>(&As[kk][trow * 8 + 4]);
            float4 b4 = *reinterpret_cast<const float4*>(&Bs[kk][tcol * 4]);
            float a[8] = {a0.x, a0.y, a0.z, a0.w, a1.x, a1.y, a1.z, a1.w};
            float b[4] = {b4.x, b4.y, b4.z, b4.w};
            #pragma unroll
            for (int i = 0; i < 8; i++)
                #pragma unroll
                for (int j = 0; j < 4; j++) acc[i][j] += a[i] * b[j];
        }
        __syncthreads();
    }

    #pragma unroll
    for (int i = 0; i < 8; i++) {
        int m = m0 + trow * 8 + i;
        float4 v = make_float4(acc[i][0], acc[i][1], acc[i][2], acc[i][3]);
        *reinterpret_cast<float4*>(out + (size_t)m * DM + n0 + tcol * 4) = v;
    }
}

// ---------------------------------------------------------------------------
// Launch. Output layout: [out (4*2048*768 floats)] then [logits_raw (48*2048*2048)]
// ---------------------------------------------------------------------------
extern "C" void kernel_launch(void* const* d_in, const int* in_sizes, int n_in,
                              void* d_out, int out_size)
{
    const float* x  = (const float*)d_in[0];
    const float* qm = (const float*)d_in[1];
    const float* Wq = (const float*)d_in[2];
    const float* Wk = (const float*)d_in[3];
    const float* Wv = (const float*)d_in[4];
    const float* Wo = (const float*)d_in[5];

    float* out    = (float*)d_out;
    float* logits = out + (size_t)MROWS * DM;

    qkv_gemm   <<<dim3(12, 64, 3),  256>>>(x, Wq, Wk, Wv);
    logits_gemm<<<dim3(32, 32, 48), 256>>>(logits);
    attn_pv    <<<dim3(64, 48),     256>>>(logits, qm);
    out_gemm   <<<dim3(12, 64),     256>>>(Wo, out);
}

// round 2
// speedup vs baseline: 2.1386x; 2.1386x over previous
#include <cuda_runtime.h>
#include <math.h>

#define BATCH 4
#define SEQ   2048
#define DM    768
#define NH    12
#define HD    64
#define MROWS (BATCH*SEQ)   // 8192
#define BHT   (BATCH*NH)    // 48

typedef unsigned long long ull;

// ---------------- packed f32x2 helpers (sm_103a FFMA2 path) ----------------
__device__ __forceinline__ ull pk2(float lo, float hi) {
    ull r; asm("mov.b64 %0, {%1,%2};" : "=l"(r) : "f"(lo), "f"(hi)); return r;
}
__device__ __forceinline__ ull rep2(float a) {
    ull r; asm("mov.b64 %0, {%1,%1};" : "=l"(r) : "f"(a)); return r;
}
__device__ __forceinline__ void fma2(ull& d, ull a, ull b) {
    asm("fma.rn.f32x2 %0, %1, %2, %0;" : "+l"(d) : "l"(a), "l"(b));
}
__device__ __forceinline__ void mul2(ull& d, ull a) {
    asm("mul.rn.f32x2 %0, %0, %1;" : "+l"(d) : "l"(a));
}
__device__ __forceinline__ float2 upk(ull v) {
    float2 f; asm("mov.b64 {%0,%1}, %2;" : "=f"(f.x), "=f"(f.y) : "l"(v)); return f;
}

// Scratch
__device__ float g_Q[(size_t)BHT*SEQ*HD];   // [b,h,s,d], pre-scaled by 1/8
__device__ float g_K[(size_t)BHT*SEQ*HD];
__device__ float g_V[(size_t)BHT*SEQ*HD];
__device__ float g_OH[(size_t)MROWS*DM];    // attention out, [b,s, h*64+d]

// ---------------------------------------------------------------------------
// Kernel 1: QKV projection. C[8192x768] = x @ W. 128x128 tile, BK=16,
// 256 threads, 8x8 microtile, FFMA2. Epilogue -> [b,h,s,d].
// ---------------------------------------------------------------------------
__global__ __launch_bounds__(256) void qkv_gemm(
    const float* __restrict__ x,
    const float* __restrict__ Wq,
    const float* __restrict__ Wk,
    const float* __restrict__ Wv)
{
    __shared__ float As[16][132];   // transposed A tile, padded
    __shared__ float Bs[16][128];

    int which = blockIdx.z;
    const float* W = (which == 0) ? Wq : (which == 1 ? Wk : Wv);
    float* dst = (which == 0) ? g_Q : (which == 1 ? g_K : g_V);
    const float alpha = (which == 0) ? 0.125f : 1.0f;

    int tid  = threadIdx.x;
    int trow = tid >> 4;   // rows trow*8
    int tcol = tid & 15;   // cols tcol*8
    int m0 = blockIdx.y * 128;
    int n0 = blockIdx.x * 128;

    ull acc[8][4];
    #pragma unroll
    for (int i = 0; i < 8; i++)
        #pragma unroll
        for (int j = 0; j < 4; j++) acc[i][j] = 0ull;

    for (int k0 = 0; k0 < DM; k0 += 16) {
        #pragma unroll
        for (int t = 0; t < 2; t++) {
            int i  = tid + t * 256;    // 0..511
            int r  = i >> 2;           // 0..127
            int c4 = (i & 3) * 4;
            float4 v = *reinterpret_cast<const float4*>(
                x + (size_t)(m0 + r) * DM + k0 + c4);
            As[c4 + 0][r] = v.x; As[c4 + 1][r] = v.y;
            As[c4 + 2][r] = v.z; As[c4 + 3][r] = v.w;
        }
        #pragma unroll
        for (int t = 0; t < 2; t++) {
            int i  = tid + t * 256;    // 0..511
            int r  = i >> 5;           // 0..15
            int c4 = (i & 31) * 4;
            *reinterpret_cast<float4*>(&Bs[r][c4]) =
                *reinterpret_cast<const float4*>(W + (size_t)(k0 + r) * DM + n0 + c4);
        }
        __syncthreads();
        #pragma unroll
        for (int kk = 0; kk < 16; kk++) {
            float4 a0 = *reinterpret_cast<const float4*>(&As[kk][trow * 8]);
            float4 a1 = *reinterpret_cast<const float4*>(&As[kk][trow * 8 + 4]);
            float4 b0 = *reinterpret_cast<const float4*>(&Bs[kk][tcol * 8]);
            float4 b1 = *reinterpret_cast<const float4*>(&Bs[kk][tcol * 8 + 4]);
            ull bp[4] = {pk2(b0.x, b0.y), pk2(b0.z, b0.w),
                         pk2(b1.x, b1.y), pk2(b1.z, b1.w)};
            float av[8] = {a0.x, a0.y, a0.z, a0.w, a1.x, a1.y, a1.z, a1.w};
            #pragma unroll
            for (int i = 0; i < 8; i++) {
                ull ap = rep2(av[i]);
                fma2(acc[i][0], ap, bp[0]);
                fma2(acc[i][1], ap, bp[1]);
                fma2(acc[i][2], ap, bp[2]);
                fma2(acc[i][3], ap, bp[3]);
            }
        }
        __syncthreads();
    }

    int nbase = n0 + tcol * 8;
    int h  = nbase >> 6;
    int d0 = nbase & 63;
    #pragma unroll
    for (int i = 0; i < 8; i++) {
        int m = m0 + trow * 8 + i;
        int b = m >> 11;
        int s = m & 2047;
        float2 v0 = upk(acc[i][0]), v1 = upk(acc[i][1]);
        float2 v2 = upk(acc[i][2]), v3 = upk(acc[i][3]);
        float* p = dst + (((size_t)(b * NH + h)) * SEQ + s) * HD + d0;
        *reinterpret_cast<float4*>(p) =
            make_float4(v0.x * alpha, v0.y * alpha, v1.x * alpha, v1.y * alpha);
        *reinterpret_cast<float4*>(p + 4) =
            make_float4(v2.x * alpha, v2.y * alpha, v3.x * alpha, v3.y * alpha);
    }
}

// ---------------------------------------------------------------------------
// Kernel 2: fused flash attention. Per block: (bh, 64-row q tile).
// Loop over 64-col k tiles: S = Q·K^T (write raw to logits), mask, online
// softmax, P·V accumulate. 256 threads, 4x4 microtiles, FFMA2.
// ---------------------------------------------------------------------------
__global__ __launch_bounds__(256) void flash_attn(
    const float* __restrict__ q_mask, float* __restrict__ logits)
{
    __shared__ float Qs[64 * 64];   // transposed [d][q]
    __shared__ float KV[64 * 64];   // K transposed [d][k], then V natural [k][d]
    __shared__ float Ps[64 * 64];   // P [q][k]

    int bh = blockIdx.y;
    int b  = bh / NH;
    int h  = bh - b * NH;
    int q0 = blockIdx.x * 64;
    int tid  = threadIdx.x;
    int trow = tid >> 4;   // 0..15 -> rows trow*4
    int tcol = tid & 15;   // 0..15 -> cols tcol*4

    const float* Qb = g_Q + (size_t)bh * SEQ * HD;
    const float* Kb = g_K + (size_t)bh * SEQ * HD;
    const float* Vb = g_V + (size_t)bh * SEQ * HD;

    // Q tile -> smem transposed; lane-major-row mapping = conflict-free STS
    #pragma unroll
    for (int t = 0; t < 4; t++) {
        int i  = tid + t * 256;
        int r  = i & 63;
        int c4 = (i >> 6) * 4;
        float4 v = *reinterpret_cast<const float4*>(Qb + (size_t)(q0 + r) * HD + c4);
        Qs[(c4 + 0) * 64 + r] = v.x; Qs[(c4 + 1) * 64 + r] = v.y;
        Qs[(c4 + 2) * 64 + r] = v.z; Qs[(c4 + 3) * 64 + r] = v.w;
    }
    float qm[4];
    #pragma unroll
    for (int i = 0; i < 4; i++)
        qm[i] = q_mask[(size_t)b * SEQ + q0 + trow * 4 + i];

    ull acc[4][2];
    float mrow[4], srow[4];
    #pragma unroll
    for (int i = 0; i < 4; i++) {
        acc[i][0] = 0ull; acc[i][1] = 0ull;
        mrow[i] = -3.0e38f; srow[i] = 0.f;
    }

    float* Lbase = logits + ((size_t)bh * SEQ + q0 + trow * 4) * SEQ + tcol * 4;

    for (int k0 = 0; k0 < SEQ; k0 += 64) {
        __syncthreads();   // previous V reads complete before overwriting KV
        // K tile -> smem transposed (conflict-free mapping)
        #pragma unroll
        for (int t = 0; t < 4; t++) {
            int i  = tid + t * 256;
            int r  = i & 63;
            int c4 = (i >> 6) * 4;
            float4 v = *reinterpret_cast<const float4*>(Kb + (size_t)(k0 + r) * HD + c4);
            KV[(c4 + 0) * 64 + r] = v.x; KV[(c4 + 1) * 64 + r] = v.y;
            KV[(c4 + 2) * 64 + r] = v.z; KV[(c4 + 3) * 64 + r] = v.w;
        }
        float4 km4 = *reinterpret_cast<const float4*>(
            q_mask + (size_t)b * SEQ + k0 + tcol * 4);
        __syncthreads();

        // S = Q·K^T (4x4 microtile, FFMA2)
        ull sp[4][2];
        #pragma unroll
        for (int i = 0; i < 4; i++) { sp[i][0] = 0ull; sp[i][1] = 0ull; }
        #pragma unroll 16
        for (int kk = 0; kk < 64; kk++) {
            float4 a4 = *reinterpret_cast<const float4*>(&Qs[kk * 64 + trow * 4]);
            float4 b4 = *reinterpret_cast<const float4*>(&KV[kk * 64 + tcol * 4]);
            ull b0 = pk2(b4.x, b4.y), b1 = pk2(b4.z, b4.w);
            ull a0 = rep2(a4.x), a1 = rep2(a4.y), a2 = rep2(a4.z), a3 = rep2(a4.w);
            fma2(sp[0][0], a0, b0); fma2(sp[0][1], a0, b1);
            fma2(sp[1][0], a1, b0); fma2(sp[1][1], a1, b1);
            fma2(sp[2][0], a2, b0); fma2(sp[2][1], a2, b1);
            fma2(sp[3][0], a3, b0); fma2(sp[3][1], a3, b1);
        }

        float km[4] = {km4.x, km4.y, km4.z, km4.w};
        #pragma unroll
        for (int i = 0; i < 4; i++) {
            float2 u0 = upk(sp[i][0]), u1 = upk(sp[i][1]);
            float sv[4] = {u0.x, u0.y, u1.x, u1.y};
            // raw logits out
            *reinterpret_cast<float4*>(Lbase + (size_t)i * SEQ + k0) =
                make_float4(sv[0], sv[1], sv[2], sv[3]);
            // mask + row max
            float le[4], rmax = -3.0e38f;
            #pragma unroll
            for (int j = 0; j < 4; j++) {
                le[j] = sv[j] - 100000.0f * (1.0f - qm[i] * km[j]);
                rmax = fmaxf(rmax, le[j]);
            }
            rmax = fmaxf(rmax, __shfl_xor_sync(0xffffffffu, rmax, 1));
            rmax = fmaxf(rmax, __shfl_xor_sync(0xffffffffu, rmax, 2));
            rmax = fmaxf(rmax, __shfl_xor_sync(0xffffffffu, rmax, 4));
            rmax = fmaxf(rmax, __shfl_xor_sync(0xffffffffu, rmax, 8));

            float mnew = fmaxf(mrow[i], rmax);
            float rs = __expf(mrow[i] - mnew);
            float p[4], psum = 0.f;
            #pragma unroll
            for (int j = 0; j < 4; j++) {
                p[j] = __expf(le[j] - mnew);
                psum += p[j];
            }
            psum += __shfl_xor_sync(0xffffffffu, psum, 1);
            psum += __shfl_xor_sync(0xffffffffu, psum, 2);
            psum += __shfl_xor_sync(0xffffffffu, psum, 4);
            psum += __shfl_xor_sync(0xffffffffu, psum, 8);
            srow[i] = srow[i] * rs + psum;
            mrow[i] = mnew;
            ull rp = rep2(rs);
            mul2(acc[i][0], rp);
            mul2(acc[i][1], rp);
            *reinterpret_cast<float4*>(&Ps[(trow * 4 + i) * 64 + tcol * 4]) =
                make_float4(p[0], p[1], p[2], p[3]);
        }
        __syncthreads();   // Ps visible; K reads done -> reuse KV for V

        // V tile -> smem natural [k][d]
        #pragma unroll
        for (int t = 0; t < 4; t++) {
            int i  = tid + t * 256;
            int r  = i >> 4;
            int c4 = (i & 15) * 4;
            *reinterpret_cast<float4*>(&KV[r * 64 + c4]) =
                *reinterpret_cast<const float4*>(Vb + (size_t)(k0 + r) * HD + c4);
        }
        __syncthreads();

        // acc += P·V
        #pragma unroll 16
        for (int kk = 0; kk < 64; kk++) {
            float4 b4 = *reinterpret_cast<const float4*>(&KV[kk * 64 + tcol * 4]);
            ull b0 = pk2(b4.x, b4.y), b1 = pk2(b4.z, b4.w);
            #pragma unroll
            for (int i = 0; i < 4; i++) {
                ull ap = rep2(Ps[(trow * 4 + i) * 64 + kk]);
                fma2(acc[i][0], ap, b0);
                fma2(acc[i][1], ap, b1);
            }
        }
    }

    #pragma unroll
    for (int i = 0; i < 4; i++) {
        float inv = 1.0f / srow[i];
        float2 x0 = upk(acc[i][0]), x1 = upk(acc[i][1]);
        *reinterpret_cast<float4*>(
            g_OH + ((size_t)b * SEQ + q0 + trow * 4 + i) * DM + h * HD + tcol * 4) =
            make_float4(x0.x * inv, x0.y * inv, x1.x * inv, x1.y * inv);
    }
}

// ---------------------------------------------------------------------------
// Kernel 3: out = g_OH @ Wo. Same tiling as kernel 1, plain row-major store.
// ---------------------------------------------------------------------------
__global__ __launch_bounds__(256) void out_gemm(const float* __restrict__ Wo,
                                                float* __restrict__ out)
{
    __shared__ float As[16][132];
    __shared__ float Bs[16][128];

    int tid  = threadIdx.x;
    int trow = tid >> 4;
    int tcol = tid & 15;
    int m0 = blockIdx.y * 128;
    int n0 = blockIdx.x * 128;

    ull acc[8][4];
    #pragma unroll
    for (int i = 0; i < 8; i++)
        #pragma unroll
        for (int j = 0; j < 4; j++) acc[i][j] = 0ull;

    for (int k0 = 0; k0 < DM; k0 += 16) {
        #pragma unroll
        for (int t = 0; t < 2; t++) {
            int i  = tid + t * 256;
            int r  = i >> 2;
            int c4 = (i & 3) * 4;
            float4 v = *reinterpret_cast<const float4*>(
                g_OH + (size_t)(m0 + r) * DM + k0 + c4);
            As[c4 + 0][r] = v.x; As[c4 + 1][r] = v.y;
            As[c4 + 2][r] = v.z; As[c4 + 3][r] = v.w;
        }
        #pragma unroll
        for (int t = 0; t < 2; t++) {
            int i  = tid + t * 256;
            int r  = i >> 5;
            int c4 = (i & 31) * 4;
            *reinterpret_cast<float4*>(&Bs[r][c4]) =
                *reinterpret_cast<const float4*>(Wo + (size_t)(k0 + r) * DM + n0 + c4);
        }
        __syncthreads();
        #pragma unroll
        for (int kk = 0; kk < 16; kk++) {
            float4 a0 = *reinterpret_cast<const float4*>(&As[kk][trow * 8]);
            float4 a1 = *reinterpret_cast<const float4*>(&As[kk][trow * 8 + 4]);
            float4 b0 = *reinterpret_cast<const float4*>(&Bs[kk][tcol * 8]);
            float4 b1 = *reinterpret_cast<const float4*>(&Bs[kk][tcol * 8 + 4]);
            ull bp[4] = {pk2(b0.x, b0.y), pk2(b0.z, b0.w),
                         pk2(b1.x, b1.y), pk2(b1.z, b1.w)};
            float av[8] = {a0.x, a0.y, a0.z, a0.w, a1.x, a1.y, a1.z, a1.w};
            #pragma unroll
            for (int i = 0; i < 8; i++) {
                ull ap = rep2(av[i]);
                fma2(acc[i][0], ap, bp[0]);
                fma2(acc[i][1], ap, bp[1]);
                fma2(acc[i][2], ap, bp[2]);
                fma2(acc[i][3], ap, bp[3]);
            }
        }
        __syncthreads();
    }

    #pragma unroll
    for (int i = 0; i < 8; i++) {
        int m = m0 + trow * 8 + i;
        float2 v0 = upk(acc[i][0]), v1 = upk(acc[i][1]);
        float2 v2 = upk(acc[i][2]), v3 = upk(acc[i][3]);
        float* p = out + (size_t)m * DM + n0 + tcol * 8;
        *reinterpret_cast<float4*>(p)     = make_float4(v0.x, v0.y, v1.x, v1.y);
        *reinterpret_cast<float4*>(p + 4) = make_float4(v2.x, v2.y, v3.x, v3.y);
    }
}

// ---------------------------------------------------------------------------
// Launch. Output: [out (4*2048*768)] then [logits_raw (48*2048*2048)]
// ---------------------------------------------------------------------------
extern "C" void kernel_launch(void* const* d_in, const int* in_sizes, int n_in,
                              void* d_out, int out_size)
{
    const float* x  = (const float*)d_in[0];
    const float* qm = (const float*)d_in[1];
    const float* Wq = (const float*)d_in[2];
    const float* Wk = (const float*)d_in[3];
    const float* Wv = (const float*)d_in[4];
    const float* Wo = (const float*)d_in[5];

    float* out    = (float*)d_out;
    float* logits = out + (size_t)MROWS * DM;

    qkv_gemm  <<<dim3(6, 64, 3), 256>>>(x, Wq, Wk, Wv);
    flash_attn<<<dim3(32, 48),   256>>>(qm, logits);
    out_gemm  <<<dim3(6, 64),    256>>>(Wo, out);
}

// round 4
// speedup vs baseline: 2.4430x; 1.1423x over previous
#include <cuda_runtime.h>
#include <math.h>
#include <stdint.h>

#define BATCH 4
#define SEQ   2048
#define DM    768
#define NH    12
#define HD    64
#define MROWS (BATCH*SEQ)   // 8192
#define BHT   (BATCH*NH)    // 48

typedef unsigned long long ull;

// ---------------- packed f32x2 helpers (sm_103a FFMA2 path) ----------------
__device__ __forceinline__ ull pk2(float lo, float hi) {
    ull r; asm("mov.b64 %0, {%1,%2};" : "=l"(r) : "f"(lo), "f"(hi)); return r;
}
__device__ __forceinline__ ull rep2(float a) {
    ull r; asm("mov.b64 %0, {%1,%1};" : "=l"(r) : "f"(a)); return r;
}
__device__ __forceinline__ void fma2(ull& d, ull a, ull b) {
    asm("fma.rn.f32x2 %0, %1, %2, %0;" : "+l"(d) : "l"(a), "l"(b));
}
__device__ __forceinline__ void mul2(ull& d, ull a) {
    asm("mul.rn.f32x2 %0, %0, %1;" : "+l"(d) : "l"(a));
}
__device__ __forceinline__ float2 upk(ull v) {
    float2 f; asm("mov.b64 {%0,%1}, %2;" : "=f"(f.x), "=f"(f.y) : "l"(v)); return f;
}
__device__ __forceinline__ uint32_t s2u(const void* p) {
    uint32_t a;
    asm("{ .reg .u64 t; cvta.to.shared.u64 t, %1; cvt.u32.u64 %0, t; }"
        : "=r"(a) : "l"(p));
    return a;
}
// cp.async 16B (sm_80 baseline PTX — safe on compute_103)
__device__ __forceinline__ void cpa16(uint32_t dst, const void* src) {
    asm volatile("cp.async.cg.shared.global [%0], [%1], 16;"
                 :: "r"(dst), "l"(src) : "memory");
}
#define CP_COMMIT() asm volatile("cp.async.commit_group;" ::: "memory")
#define CP_WAIT1()  asm volatile("cp.async.wait_group 1;" ::: "memory")
#define CP_WAIT2()  asm volatile("cp.async.wait_group 2;" ::: "memory")

// Scratch
__device__ float g_Q[(size_t)BHT*SEQ*HD];   // [b,h,s,d], pre-scaled by 1/8
__device__ float g_K[(size_t)BHT*SEQ*HD];   // TRANSPOSED: [b,h,d,s]
__device__ float g_V[(size_t)BHT*SEQ*HD];   // [b,h,s,d]
__device__ float g_OH[(size_t)MROWS*DM];    // attention out, [b,s, h*64+d]

// ---------------------------------------------------------------------------
// FFMA2 GEMM: C[8192x768] = A @ W. 128x128 tile, BK=32, 256 thr, 8x8 micro.
// mode 0: W=Wq -> g_Q (alpha=1/8, [b,h,s,d])
// mode 1: W=Wk -> g_K ([b,h,d,s] transposed, scalar stores)
// mode 2: W=Wv -> g_V ([b,h,s,d])
// mode 3: A=g_OH, W=Wo -> lin_out row-major
// ---------------------------------------------------------------------------
__global__ __launch_bounds__(256) void ffma_gemm(
    const float* __restrict__ Ain,
    const float* __restrict__ W0, const float* __restrict__ W1,
    const float* __restrict__ W2,
    float* __restrict__ lin_out, int base_mode)
{
    __shared__ float As[32][132];   // transposed A tile, padded
    __shared__ float Bs[32][128];

    int mode = base_mode + blockIdx.z;
    const float* W = (mode == 0) ? W0 : (mode == 1) ? W1 : (mode == 2) ? W2 : W0;
    const float* A = (mode == 3) ? (const float*)g_OH : Ain;

    int tid  = threadIdx.x;
    int trow = tid >> 4;   // rows trow*8
    int tcol = tid & 15;   // cols tcol*8
    int m0 = blockIdx.y * 128;
    int n0 = blockIdx.x * 128;

    ull acc[8][4];
    #pragma unroll
    for (int i = 0; i < 8; i++)
        #pragma unroll
        for (int j = 0; j < 4; j++) acc[i][j] = 0ull;

    for (int k0 = 0; k0 < DM; k0 += 32) {
        #pragma unroll
        for (int t = 0; t < 4; t++) {
            int i  = tid + t * 256;    // 0..1023
            int r  = i >> 3;           // 0..127
            int c4 = (i & 7) * 4;      // 0..28
            float4 v = *reinterpret_cast<const float4*>(
                A + (size_t)(m0 + r) * DM + k0 + c4);
            As[c4 + 0][r] = v.x; As[c4 + 1][r] = v.y;
            As[c4 + 2][r] = v.z; As[c4 + 3][r] = v.w;
        }
        #pragma unroll
        for (int t = 0; t < 4; t++) {
            int i  = tid + t * 256;
            int r  = i >> 5;           // 0..31
            int c4 = (i & 31) * 4;     // 0..124
            *reinterpret_cast<float4*>(&Bs[r][c4]) =
                *reinterpret_cast<const float4*>(W + (size_t)(k0 + r) * DM + n0 + c4);
        }
        __syncthreads();
        #pragma unroll 8
        for (int kk = 0; kk < 32; kk++) {
            float4 a0 = *reinterpret_cast<const float4*>(&As[kk][trow * 8]);
            float4 a1 = *reinterpret_cast<const float4*>(&As[kk][trow * 8 + 4]);
            float4 b0 = *reinterpret_cast<const float4*>(&Bs[kk][tcol * 8]);
            float4 b1 = *reinterpret_cast<const float4*>(&Bs[kk][tcol * 8 + 4]);
            ull bp[4] = {pk2(b0.x, b0.y), pk2(b0.z, b0.w),
                         pk2(b1.x, b1.y), pk2(b1.z, b1.w)};
            float av[8] = {a0.x, a0.y, a0.z, a0.w, a1.x, a1.y, a1.z, a1.w};
            #pragma unroll
            for (int i = 0; i < 8; i++) {
                ull ap = rep2(av[i]);
                fma2(acc[i][0], ap, bp[0]);
                fma2(acc[i][1], ap, bp[1]);
                fma2(acc[i][2], ap, bp[2]);
                fma2(acc[i][3], ap, bp[3]);
            }
        }
        __syncthreads();
    }

    if (mode == 3) {
        #pragma unroll
        for (int i = 0; i < 8; i++) {
            int m = m0 + trow * 8 + i;
            float2 v0 = upk(acc[i][0]), v1 = upk(acc[i][1]);
            float2 v2 = upk(acc[i][2]), v3 = upk(acc[i][3]);
            float* p = lin_out + (size_t)m * DM + n0 + tcol * 8;
            *reinterpret_cast<float4*>(p)     = make_float4(v0.x, v0.y, v1.x, v1.y);
            *reinterpret_cast<float4*>(p + 4) = make_float4(v2.x, v2.y, v3.x, v3.y);
        }
        return;
    }

    int nbase = n0 + tcol * 8;
    int h  = nbase >> 6;
    int d0 = nbase & 63;
    if (mode == 1) {
        // K transposed store: g_K[((b*NH+h)*HD + d)*SEQ + s]
        #pragma unroll
        for (int i = 0; i < 8; i++) {
            int m = m0 + trow * 8 + i;
            int b = m >> 11, s = m & 2047;
            float2 v0 = upk(acc[i][0]), v1 = upk(acc[i][1]);
            float2 v2 = upk(acc[i][2]), v3 = upk(acc[i][3]);
            float vals[8] = {v0.x, v0.y, v1.x, v1.y, v2.x, v2.y, v3.x, v3.y};
            float* kb = g_K + (size_t)(b * NH + h) * HD * SEQ + s;
            #pragma unroll
            for (int j = 0; j < 8; j++)
                kb[(size_t)(d0 + j) * SEQ] = vals[j];
        }
    } else {
        float alpha = (mode == 0) ? 0.125f : 1.0f;
        float* dst = (mode == 0) ? g_Q : g_V;
        #pragma unroll
        for (int i = 0; i < 8; i++) {
            int m = m0 + trow * 8 + i;
            int b = m >> 11, s = m & 2047;
            float2 v0 = upk(acc[i][0]), v1 = upk(acc[i][1]);
            float2 v2 = upk(acc[i][2]), v3 = upk(acc[i][3]);
            float* p = dst + (((size_t)(b * NH + h)) * SEQ + s) * HD + d0;
            *reinterpret_cast<float4*>(p) =
                make_float4(v0.x * alpha, v0.y * alpha, v1.x * alpha, v1.y * alpha);
            *reinterpret_cast<float4*>(p + 4) =
                make_float4(v2.x * alpha, v2.y * alpha, v3.x * alpha, v3.y * alpha);
        }
    }
}

// ---------------------------------------------------------------------------
// Flash attention: 128q x 64k tiles, 256 thr, 8x4 microtiles, cp.async
// double-buffered K + just-in-time V, warp-local P handoff (3 barriers/tile).
// Writes raw logits to d_out; O (normalized) to g_OH.
// smem (floats): Qs[64][128] | Ks0[64][64] | Ks1[64][64] | Vs[64][64] | Ps[128][64]
// ---------------------------------------------------------------------------
__global__ __launch_bounds__(256, 2) void flash_attn(
    const float* __restrict__ q_mask, float* __restrict__ logits)
{
    extern __shared__ float sm[];
    float* Qs  = sm;             // 8192 floats
    float* Ks0 = sm + 8192;      // 4096
    float* Ks1 = sm + 12288;     // 4096
    float* Vs  = sm + 16384;     // 4096
    float* Ps  = sm + 20480;     // 8192  (total 28672 floats = 112KB)

    int bh = blockIdx.y;
    int b  = bh / NH;
    int h  = bh - b * NH;
    int q0 = blockIdx.x * 128;
    int tid  = threadIdx.x;
    int trow = tid >> 4;   // 0..15 -> q rows trow*8..+7
    int tcol = tid & 15;   // 0..15 -> cols tcol*4

    const float* Qb = g_Q + (size_t)bh * SEQ * HD;
    const float* Kb = g_K + (size_t)bh * SEQ * HD;   // [d][s]
    const float* Vb = g_V + (size_t)bh * SEQ * HD;   // [s][d]
    uint32_t sKs0 = s2u(Ks0), sKs1 = s2u(Ks1), sVs = s2u(Vs);

    // prologue: K(0) via cp.async
    #pragma unroll
    for (int t = 0; t < 4; t++) {
        int j = tid + t * 256;
        int d = j >> 4, s4 = (j & 15) * 4;
        cpa16(sKs0 + (uint32_t)(d * 64 + s4) * 4, Kb + (size_t)d * SEQ + s4);
    }
    CP_COMMIT();

    // Q -> smem transposed [d][q] (conflict-free lane-major stores)
    #pragma unroll
    for (int t = 0; t < 8; t++) {
        int i  = tid + t * 256;
        int r  = i & 127;
        int c4 = (i >> 7) * 4;
        float4 v = *reinterpret_cast<const float4*>(Qb + (size_t)(q0 + r) * HD + c4);
        Qs[(c4 + 0) * 128 + r] = v.x; Qs[(c4 + 1) * 128 + r] = v.y;
        Qs[(c4 + 2) * 128 + r] = v.z; Qs[(c4 + 3) * 128 + r] = v.w;
    }

    float qm[8];
    #pragma unroll
    for (int i = 0; i < 8; i++)
        qm[i] = q_mask[(size_t)b * SEQ + q0 + trow * 8 + i];

    ull acc[8][2];
    float mrow[8], srow[8];
    #pragma unroll
    for (int i = 0; i < 8; i++) {
        acc[i][0] = 0ull; acc[i][1] = 0ull;
        mrow[i] = -3.0e38f; srow[i] = 0.f;
    }

    float* Lbase = logits + ((size_t)bh * SEQ + q0 + trow * 8) * SEQ + tcol * 4;
    const float* kmrow = q_mask + (size_t)b * SEQ;

    for (int t = 0; t < 32; t++) {
        int k0 = t * 64;
        const float* KsCur = (t & 1) ? Ks1 : Ks0;
        uint32_t kbufN = (t & 1) ? sKs0 : sKs1;

        __syncthreads();   // PV(t-1) complete: Vs and Ks[next] free
        // V(t)
        #pragma unroll
        for (int u = 0; u < 4; u++) {
            int j = tid + u * 256;
            int r = j >> 4, c4 = (j & 15) * 4;
            cpa16(sVs + (uint32_t)(r * 64 + c4) * 4,
                  Vb + (size_t)(k0 + r) * HD + c4);
        }
        CP_COMMIT();
        // K(t+1)
        if (t + 1 < 32) {
            int k1 = k0 + 64;
            #pragma unroll
            for (int u = 0; u < 4; u++) {
                int j = tid + u * 256;
                int d = j >> 4, s4 = (j & 15) * 4;
                cpa16(kbufN + (uint32_t)(d * 64 + s4) * 4,
                      Kb + (size_t)d * SEQ + k1 + s4);
            }
        }
        CP_COMMIT();

        float4 km4 = *reinterpret_cast<const float4*>(kmrow + k0 + tcol * 4);
        CP_WAIT2();        // K(t) done (pending: V(t), K(t+1))
        __syncthreads();

        // ---- S = Q.K^T  (8x4 micro, FFMA2) ----
        ull sp[8][2];
        #pragma unroll
        for (int i = 0; i < 8; i++) { sp[i][0] = 0ull; sp[i][1] = 0ull; }
        #pragma unroll 8
        for (int kk = 0; kk < 64; kk++) {
            float4 a0 = *reinterpret_cast<const float4*>(&Qs[kk * 128 + trow * 8]);
            float4 a1 = *reinterpret_cast<const float4*>(&Qs[kk * 128 + trow * 8 + 4]);
            float4 bq = *reinterpret_cast<const float4*>(&KsCur[kk * 64 + tcol * 4]);
            ull b0 = pk2(bq.x, bq.y), b1 = pk2(bq.z, bq.w);
            float av[8] = {a0.x, a0.y, a0.z, a0.w, a1.x, a1.y, a1.z, a1.w};
            #pragma unroll
            for (int i = 0; i < 8; i++) {
                ull ap = rep2(av[i]);
                fma2(sp[i][0], ap, b0);
                fma2(sp[i][1], ap, b1);
            }
        }

        // ---- raw logits out + mask + online softmax ----
        float km[4] = {km4.x, km4.y, km4.z, km4.w};
        #pragma unroll
        for (int i = 0; i < 8; i++) {
            float2 u0 = upk(sp[i][0]), u1 = upk(sp[i][1]);
            float sv[4] = {u0.x, u0.y, u1.x, u1.y};
            *reinterpret_cast<float4*>(Lbase + (size_t)i * SEQ + k0) =
                make_float4(sv[0], sv[1], sv[2], sv[3]);
            float le[4], rmax = -3.0e38f;
            #pragma unroll
            for (int j = 0; j < 4; j++) {
                le[j] = sv[j] - 100000.0f * (1.0f - qm[i] * km[j]);
                rmax = fmaxf(rmax, le[j]);
            }
            rmax = fmaxf(rmax, __shfl_xor_sync(0xffffffffu, rmax, 1));
            rmax = fmaxf(rmax, __shfl_xor_sync(0xffffffffu, rmax, 2));
            rmax = fmaxf(rmax, __shfl_xor_sync(0xffffffffu, rmax, 4));
            rmax = fmaxf(rmax, __shfl_xor_sync(0xffffffffu, rmax, 8));

            float mnew = fmaxf(mrow[i], rmax);
            float rs = __expf(mrow[i] - mnew);
            float p[4], psum = 0.f;
            #pragma unroll
            for (int j = 0; j < 4; j++) {
                p[j] = __expf(le[j] - mnew);
                psum += p[j];
            }
            psum += __shfl_xor_sync(0xffffffffu, psum, 1);
            psum += __shfl_xor_sync(0xffffffffu, psum, 2);
            psum += __shfl_xor_sync(0xffffffffu, psum, 4);
            psum += __shfl_xor_sync(0xffffffffu, psum, 8);
            srow[i] = srow[i] * rs + psum;
            mrow[i] = mnew;
            ull rp = rep2(rs);
            mul2(acc[i][0], rp);
            mul2(acc[i][1], rp);
            *reinterpret_cast<float4*>(&Ps[(trow * 8 + i) * 64 + tcol * 4]) =
                make_float4(p[0], p[1], p[2], p[3]);
        }

        CP_WAIT1();        // V(t) done (pending: K(t+1))
        __syncthreads();   // V visible to all; Ps is warp-local (covered too)

        // ---- acc += P.V (8x4 micro, 4-k inner, FFMA2) ----
        #pragma unroll 4
        for (int k4 = 0; k4 < 16; k4++) {
            ull vb[4][2];
            #pragma unroll
            for (int j = 0; j < 4; j++) {
                float4 v = *reinterpret_cast<const float4*>(
                    &Vs[(k4 * 4 + j) * 64 + tcol * 4]);
                vb[j][0] = pk2(v.x, v.y);
                vb[j][1] = pk2(v.z, v.w);
            }
            #pragma unroll
            for (int i = 0; i < 8; i++) {
                float4 pf = *reinterpret_cast<const float4*>(
                    &Ps[(trow * 8 + i) * 64 + k4 * 4]);
                ull p0 = rep2(pf.x), p1 = rep2(pf.y);
                ull p2 = rep2(pf.z), p3 = rep2(pf.w);
                fma2(acc[i][0], p0, vb[0][0]); fma2(acc[i][1], p0, vb[0][1]);
                fma2(acc[i][0], p1, vb[1][0]); fma2(acc[i][1], p1, vb[1][1]);
                fma2(acc[i][0], p2, vb[2][0]); fma2(acc[i][1], p2, vb[2][1]);
                fma2(acc[i][0], p3, vb[3][0]); fma2(acc[i][1], p3, vb[3][1]);
            }
        }
    }

    #pragma unroll
    for (int i = 0; i < 8; i++) {
        float inv = 1.0f / srow[i];
        float2 x0 = upk(acc[i][0]), x1 = upk(acc[i][1]);
        *reinterpret_cast<float4*>(
            g_OH + ((size_t)b * SEQ + q0 + trow * 8 + i) * DM + h * HD + tcol * 4) =
            make_float4(x0.x * inv, x0.y * inv, x1.x * inv, x1.y * inv);
    }
}

// ---------------------------------------------------------------------------
// Launch. Output: [out (4*2048*768)] then [logits_raw (48*2048*2048)]
// ---------------------------------------------------------------------------
extern "C" void kernel_launch(void* const* d_in, const int* in_sizes, int n_in,
                              void* d_out, int out_size)
{
    const float* x  = (const float*)d_in[0];
    const float* qm = (const float*)d_in[1];
    const float* Wq = (const float*)d_in[2];
    const float* Wk = (const float*)d_in[3];
    const float* Wv = (const float*)d_in[4];
    const float* Wo = (const float*)d_in[5];

    float* out    = (float*)d_out;
    float* logits = out + (size_t)MROWS * DM;

    const int FLASH_SMEM = 28672 * 4;   // 112KB
    cudaFuncSetAttribute(flash_attn,
                         cudaFuncAttributeMaxDynamicSharedMemorySize, FLASH_SMEM);

    ffma_gemm <<<dim3(6, 64, 3), 256>>>(x, Wq, Wk, Wv, nullptr, 0);
    flash_attn<<<dim3(16, 48), 256, FLASH_SMEM>>>(qm, logits);
    ffma_gemm <<<dim3(6, 64, 1), 256>>>(nullptr, Wo, Wo, Wo, out, 3);
}

// round 5
// speedup vs baseline: 3.2339x; 1.3237x over previous
#include <cuda_runtime.h>
#include <math.h>
#include <stdint.h>

#define BATCH 4
#define SEQ   2048
#define DM    768
#define NH    12
#define HD    64
#define MROWS (BATCH*SEQ)   // 8192
#define BHT   (BATCH*NH)    // 48

typedef unsigned long long ull;

// ---------------- packed f32x2 helpers (FFMA2, used by flash) --------------
__device__ __forceinline__ ull pk2(float lo, float hi) {
    ull r; asm("mov.b64 %0, {%1,%2};" : "=l"(r) : "f"(lo), "f"(hi)); return r;
}
__device__ __forceinline__ ull rep2(float a) {
    ull r; asm("mov.b64 %0, {%1,%1};" : "=l"(r) : "f"(a)); return r;
}
__device__ __forceinline__ void fma2(ull& d, ull a, ull b) {
    asm("fma.rn.f32x2 %0, %1, %2, %0;" : "+l"(d) : "l"(a), "l"(b));
}
__device__ __forceinline__ void mul2(ull& d, ull a) {
    asm("mul.rn.f32x2 %0, %0, %1;" : "+l"(d) : "l"(a));
}
__device__ __forceinline__ float2 upk(ull v) {
    float2 f; asm("mov.b64 {%0,%1}, %2;" : "=f"(f.x), "=f"(f.y) : "l"(v)); return f;
}
__device__ __forceinline__ uint32_t s2u(const void* p) {
    uint32_t a;
    asm("{ .reg .u64 t; cvta.to.shared.u64 t, %1; cvt.u32.u64 %0, t; }"
        : "=r"(a) : "l"(p));
    return a;
}
// cp.async 16B (sm_80 PTX)
__device__ __forceinline__ void cpa16(uint32_t dst, const void* src) {
    asm volatile("cp.async.cg.shared.global [%0], [%1], 16;"
                 :: "r"(dst), "l"(src) : "memory");
}
#define CP_COMMIT() asm volatile("cp.async.commit_group;" ::: "memory")
#define CP_WAIT1()  asm volatile("cp.async.wait_group 1;" ::: "memory")
#define CP_WAIT2()  asm volatile("cp.async.wait_group 2;" ::: "memory")

// ---------------- mma.sync helpers (sm_80 PTX, legacy HMMA on sm_103) ------
__device__ __forceinline__ void ldsm_x4(uint32_t* r, uint32_t addr) {
    asm volatile("ldmatrix.sync.aligned.m8n8.x4.shared.b16 {%0,%1,%2,%3}, [%4];"
                 : "=r"(r[0]), "=r"(r[1]), "=r"(r[2]), "=r"(r[3]) : "r"(addr));
}
__device__ __forceinline__ void ldsm_x4t(uint32_t* r, uint32_t addr) {
    asm volatile("ldmatrix.sync.aligned.m8n8.x4.trans.shared.b16 {%0,%1,%2,%3}, [%4];"
                 : "=r"(r[0]), "=r"(r[1]), "=r"(r[2]), "=r"(r[3]) : "r"(addr));
}
__device__ __forceinline__ void mma16816(float* c, const uint32_t* a, const uint32_t* b) {
    asm volatile(
        "mma.sync.aligned.m16n8k16.row.col.f32.bf16.bf16.f32 "
        "{%0,%1,%2,%3}, {%4,%5,%6,%7}, {%8,%9}, {%0,%1,%2,%3};"
        : "+f"(c[0]), "+f"(c[1]), "+f"(c[2]), "+f"(c[3])
        : "r"(a[0]), "r"(a[1]), "r"(a[2]), "r"(a[3]), "r"(b[0]), "r"(b[1]));
}
// split float4 -> bf16 hi/lo pairs and STS (8B each)
__device__ __forceinline__ void cvtsts(float4 v, uint32_t* baseH, uint32_t* baseL, int idx) {
    uint32_t ph0, ph1, pl0, pl1;
    asm("cvt.rn.bf16x2.f32 %0, %1, %2;" : "=r"(ph0) : "f"(v.y), "f"(v.x));
    asm("cvt.rn.bf16x2.f32 %0, %1, %2;" : "=r"(ph1) : "f"(v.w), "f"(v.z));
    float rx = v.x - __uint_as_float(ph0 << 16);
    float ry = v.y - __uint_as_float(ph0 & 0xffff0000u);
    float rz = v.z - __uint_as_float(ph1 << 16);
    float rw = v.w - __uint_as_float(ph1 & 0xffff0000u);
    asm("cvt.rn.bf16x2.f32 %0, %1, %2;" : "=r"(pl0) : "f"(ry), "f"(rx));
    asm("cvt.rn.bf16x2.f32 %0, %1, %2;" : "=r"(pl1) : "f"(rw), "f"(rz));
    *reinterpret_cast<uint2*>(baseH + idx) = make_uint2(ph0, ph1);
    *reinterpret_cast<uint2*>(baseL + idx) = make_uint2(pl0, pl1);
}

// Scratch
__device__ float g_Q[(size_t)BHT*SEQ*HD];   // [b,h,s,d], pre-scaled by 1/8
__device__ float g_K[(size_t)BHT*SEQ*HD];   // TRANSPOSED: [b,h,d,s]
__device__ float g_V[(size_t)BHT*SEQ*HD];   // [b,h,s,d]
__device__ float g_OH[(size_t)MROWS*DM];    // attention out, [b,s, h*64+d]

// ---------------------------------------------------------------------------
// bf16-split mma.sync GEMM: C[8192x768] = A @ W.
// 128x128 CTA tile, BK=32, 8 warps (2M x 4N), warp tile 64x32, m16n8k16.
// 2-term split: Ah*Bh + Ah*Bl + Al*Bh (3 mma per logical mma).
// mode 0: W=Wq -> g_Q (alpha=1/8, [b,h,s,d])
// mode 1: W=Wk -> g_K ([b,h,d,s] transposed)
// mode 2: W=Wv -> g_V
// mode 3: A=g_OH, W=Wo -> lin_out row-major
// ---------------------------------------------------------------------------
__global__ __launch_bounds__(256) void mma_gemm(
    const float* __restrict__ Ain,
    const float* __restrict__ W0, const float* __restrict__ W1,
    const float* __restrict__ W2,
    float* __restrict__ lin_out, int base_mode)
{
    // A tiles: 128 rows x 40 bf16 (pad 8) = 20 u32/row. B: 32 rows x 136 bf16 = 68 u32/row.
    __shared__ __align__(16) uint32_t sAh[128 * 20];
    __shared__ __align__(16) uint32_t sAl[128 * 20];
    __shared__ __align__(16) uint32_t sBh[32 * 68];
    __shared__ __align__(16) uint32_t sBl[32 * 68];

    int mode = base_mode + blockIdx.z;
    const float* W = (mode == 0) ? W0 : (mode == 1) ? W1 : (mode == 2) ? W2 : W0;
    const float* A = (mode == 3) ? (const float*)g_OH : Ain;

    int tid  = threadIdx.x;
    int wid  = tid >> 5, lane = tid & 31;
    int warpM = wid & 1, warpN = wid >> 1;    // 2 x 4 warp grid
    int m0 = blockIdx.y * 128, n0 = blockIdx.x * 128;

    float acc[4][4][4];
    #pragma unroll
    for (int i = 0; i < 4; i++)
        #pragma unroll
        for (int j = 0; j < 4; j++)
            #pragma unroll
            for (int k = 0; k < 4; k++) acc[i][j][k] = 0.f;

    uint32_t aBase  = s2u(sAh), alBase = s2u(sAl);
    uint32_t bBase  = s2u(sBh), blBase = s2u(sBl);
    // per-lane ldmatrix byte offsets
    uint32_t aLane = (uint32_t)((lane & 15) * 80 + (lane >> 4) * 16 + warpM * 64 * 80);
    uint32_t bLane = (uint32_t)((lane & 15) * 272 + (lane >> 4) * 16 + warpN * 64);

    // chunk 0 load + convert + STS
    #pragma unroll
    for (int it = 0; it < 4; it++) {
        int i = tid + it * 256;
        int r = i >> 3, c4 = (i & 7) * 4;
        float4 v = *reinterpret_cast<const float4*>(A + (size_t)(m0 + r) * DM + c4);
        cvtsts(v, sAh, sAl, r * 20 + (c4 >> 1));
        int rb = i >> 5, cb = (i & 31) * 4;
        float4 w = *reinterpret_cast<const float4*>(W + (size_t)rb * DM + n0 + cb);
        cvtsts(w, sBh, sBl, rb * 68 + (cb >> 1));
    }
    __syncthreads();

    for (int c = 0; c < 24; c++) {
        float4 av[4], bv[4];
        if (c < 23) {
            int k0n = (c + 1) * 32;
            #pragma unroll
            for (int it = 0; it < 4; it++) {
                int i = tid + it * 256;
                int r = i >> 3, c4 = (i & 7) * 4;
                av[it] = *reinterpret_cast<const float4*>(
                    A + (size_t)(m0 + r) * DM + k0n + c4);
                int rb = i >> 5, cb = (i & 31) * 4;
                bv[it] = *reinterpret_cast<const float4*>(
                    W + (size_t)(k0n + rb) * DM + n0 + cb);
            }
        }
        // compute: 2 k-steps of 16
        #pragma unroll
        for (int ks = 0; ks < 2; ks++) {
            uint32_t bh[4][2], bl[4][2];
            #pragma unroll
            for (int np = 0; np < 2; np++) {
                uint32_t r4[4];
                ldsm_x4t(r4, bBase + bLane + ks * 4352 + np * 32);
                bh[np*2][0] = r4[0]; bh[np*2][1] = r4[1];
                bh[np*2+1][0] = r4[2]; bh[np*2+1][1] = r4[3];
                ldsm_x4t(r4, blBase + bLane + ks * 4352 + np * 32);
                bl[np*2][0] = r4[0]; bl[np*2][1] = r4[1];
                bl[np*2+1][0] = r4[2]; bl[np*2+1][1] = r4[3];
            }
            #pragma unroll
            for (int mt = 0; mt < 4; mt++) {
                uint32_t ah[4], al4[4];
                ldsm_x4(ah,  aBase  + aLane + mt * 1280 + ks * 32);
                ldsm_x4(al4, alBase + aLane + mt * 1280 + ks * 32);
                #pragma unroll
                for (int nt = 0; nt < 4; nt++) {
                    mma16816(acc[mt][nt], ah,  bh[nt]);
                    mma16816(acc[mt][nt], ah,  bl[nt]);
                    mma16816(acc[mt][nt], al4, bh[nt]);
                }
            }
        }
        __syncthreads();
        if (c < 23) {
            #pragma unroll
            for (int it = 0; it < 4; it++) {
                int i = tid + it * 256;
                int r = i >> 3, c4 = (i & 7) * 4;
                cvtsts(av[it], sAh, sAl, r * 20 + (c4 >> 1));
                int rb = i >> 5, cb = (i & 31) * 4;
                cvtsts(bv[it], sBh, sBl, rb * 68 + (cb >> 1));
            }
            __syncthreads();
        }
    }

    // epilogue from C fragments: rows (lane>>2), (lane>>2)+8; cols 2*(lane&3)
    int rl = lane >> 2, cl = (lane & 3) * 2;
    if (mode == 3) {
        #pragma unroll
        for (int mt = 0; mt < 4; mt++) {
            int m = m0 + warpM * 64 + mt * 16 + rl;
            #pragma unroll
            for (int nt = 0; nt < 4; nt++) {
                int n = n0 + warpN * 32 + nt * 8 + cl;
                *reinterpret_cast<float2*>(lin_out + (size_t)m * DM + n) =
                    make_float2(acc[mt][nt][0], acc[mt][nt][1]);
                *reinterpret_cast<float2*>(lin_out + (size_t)(m + 8) * DM + n) =
                    make_float2(acc[mt][nt][2], acc[mt][nt][3]);
            }
        }
    } else if (mode == 1) {
        #pragma unroll
        for (int mt = 0; mt < 4; mt++) {
            int m = m0 + warpM * 64 + mt * 16 + rl;
            int b = m >> 11, s = m & 2047;
            #pragma unroll
            for (int nt = 0; nt < 4; nt++) {
                int n = n0 + warpN * 32 + nt * 8 + cl;
                int h = n >> 6, d = n & 63;
                float* kb = g_K + (size_t)(b * NH + h) * HD * SEQ;
                kb[(size_t)d * SEQ + s]           = acc[mt][nt][0];
                kb[(size_t)(d + 1) * SEQ + s]     = acc[mt][nt][1];
                kb[(size_t)d * SEQ + s + 8]       = acc[mt][nt][2];
                kb[(size_t)(d + 1) * SEQ + s + 8] = acc[mt][nt][3];
            }
        }
    } else {
        float alpha = (mode == 0) ? 0.125f : 1.0f;
        float* dst = (mode == 0) ? g_Q : g_V;
        #pragma unroll
        for (int mt = 0; mt < 4; mt++) {
            int m = m0 + warpM * 64 + mt * 16 + rl;
            int b = m >> 11, s = m & 2047;
            #pragma unroll
            for (int nt = 0; nt < 4; nt++) {
                int n = n0 + warpN * 32 + nt * 8 + cl;
                int h = n >> 6, d = n & 63;
                float* p = dst + (((size_t)(b * NH + h)) * SEQ + s) * HD + d;
                *reinterpret_cast<float2*>(p) =
                    make_float2(acc[mt][nt][0] * alpha, acc[mt][nt][1] * alpha);
                *reinterpret_cast<float2*>(p + (size_t)8 * HD) =
                    make_float2(acc[mt][nt][2] * alpha, acc[mt][nt][3] * alpha);
            }
        }
    }
}

// ---------------------------------------------------------------------------
// Flash attention (unchanged from round 4): 128q x 64k tiles, FFMA2,
// cp.async double-buffered K + JIT V. Raw logits -> d_out, O -> g_OH.
// ---------------------------------------------------------------------------
__global__ __launch_bounds__(256, 2) void flash_attn(
    const float* __restrict__ q_mask, float* __restrict__ logits)
{
    extern __shared__ float sm[];
    float* Qs  = sm;             // 8192 floats
    float* Ks0 = sm + 8192;      // 4096
    float* Ks1 = sm + 12288;     // 4096
    float* Vs  = sm + 16384;     // 4096
    float* Ps  = sm + 20480;     // 8192

    int bh = blockIdx.y;
    int b  = bh / NH;
    int h  = bh - b * NH;
    int q0 = blockIdx.x * 128;
    int tid  = threadIdx.x;
    int trow = tid >> 4;
    int tcol = tid & 15;

    const float* Qb = g_Q + (size_t)bh * SEQ * HD;
    const float* Kb = g_K + (size_t)bh * SEQ * HD;   // [d][s]
    const float* Vb = g_V + (size_t)bh * SEQ * HD;   // [s][d]
    uint32_t sKs0 = s2u(Ks0), sKs1 = s2u(Ks1), sVs = s2u(Vs);

    #pragma unroll
    for (int t = 0; t < 4; t++) {
        int j = tid + t * 256;
        int d = j >> 4, s4 = (j & 15) * 4;
        cpa16(sKs0 + (uint32_t)(d * 64 + s4) * 4, Kb + (size_t)d * SEQ + s4);
    }
    CP_COMMIT();

    #pragma unroll
    for (int t = 0; t < 8; t++) {
        int i  = tid + t * 256;
        int r  = i & 127;
        int c4 = (i >> 7) * 4;
        float4 v = *reinterpret_cast<const float4*>(Qb + (size_t)(q0 + r) * HD + c4);
        Qs[(c4 + 0) * 128 + r] = v.x; Qs[(c4 + 1) * 128 + r] = v.y;
        Qs[(c4 + 2) * 128 + r] = v.z; Qs[(c4 + 3) * 128 + r] = v.w;
    }

    float qm[8];
    #pragma unroll
    for (int i = 0; i < 8; i++)
        qm[i] = q_mask[(size_t)b * SEQ + q0 + trow * 8 + i];

    ull acc[8][2];
    float mrow[8], srow[8];
    #pragma unroll
    for (int i = 0; i < 8; i++) {
        acc[i][0] = 0ull; acc[i][1] = 0ull;
        mrow[i] = -3.0e38f; srow[i] = 0.f;
    }

    float* Lbase = logits + ((size_t)bh * SEQ + q0 + trow * 8) * SEQ + tcol * 4;
    const float* kmrow = q_mask + (size_t)b * SEQ;

    for (int t = 0; t < 32; t++) {
        int k0 = t * 64;
        const float* KsCur = (t & 1) ? Ks1 : Ks0;
        uint32_t kbufN = (t & 1) ? sKs0 : sKs1;

        __syncthreads();
        #pragma unroll
        for (int u = 0; u < 4; u++) {
            int j = tid + u * 256;
            int r = j >> 4, c4 = (j & 15) * 4;
            cpa16(sVs + (uint32_t)(r * 64 + c4) * 4,
                  Vb + (size_t)(k0 + r) * HD + c4);
        }
        CP_COMMIT();
        if (t + 1 < 32) {
            int k1 = k0 + 64;
            #pragma unroll
            for (int u = 0; u < 4; u++) {
                int j = tid + u * 256;
                int d = j >> 4, s4 = (j & 15) * 4;
                cpa16(kbufN + (uint32_t)(d * 64 + s4) * 4,
                      Kb + (size_t)d * SEQ + k1 + s4);
            }
        }
        CP_COMMIT();

        float4 km4 = *reinterpret_cast<const float4*>(kmrow + k0 + tcol * 4);
        CP_WAIT2();
        __syncthreads();

        ull sp[8][2];
        #pragma unroll
        for (int i = 0; i < 8; i++) { sp[i][0] = 0ull; sp[i][1] = 0ull; }
        #pragma unroll 8
        for (int kk = 0; kk < 64; kk++) {
            float4 a0 = *reinterpret_cast<const float4*>(&Qs[kk * 128 + trow * 8]);
            float4 a1 = *reinterpret_cast<const float4*>(&Qs[kk * 128 + trow * 8 + 4]);
            float4 bq = *reinterpret_cast<const float4*>(&KsCur[kk * 64 + tcol * 4]);
            ull b0 = pk2(bq.x, bq.y), b1 = pk2(bq.z, bq.w);
            float av[8] = {a0.x, a0.y, a0.z, a0.w, a1.x, a1.y, a1.z, a1.w};
            #pragma unroll
            for (int i = 0; i < 8; i++) {
                ull ap = rep2(av[i]);
                fma2(sp[i][0], ap, b0);
                fma2(sp[i][1], ap, b1);
            }
        }

        float km[4] = {km4.x, km4.y, km4.z, km4.w};
        #pragma unroll
        for (int i = 0; i < 8; i++) {
            float2 u0 = upk(sp[i][0]), u1 = upk(sp[i][1]);
            float sv[4] = {u0.x, u0.y, u1.x, u1.y};
            *reinterpret_cast<float4*>(Lbase + (size_t)i * SEQ + k0) =
                make_float4(sv[0], sv[1], sv[2], sv[3]);
            float le[4], rmax = -3.0e38f;
            #pragma unroll
            for (int j = 0; j < 4; j++) {
                le[j] = sv[j] - 100000.0f * (1.0f - qm[i] * km[j]);
                rmax = fmaxf(rmax, le[j]);
            }
            rmax = fmaxf(rmax, __shfl_xor_sync(0xffffffffu, rmax, 1));
            rmax = fmaxf(rmax, __shfl_xor_sync(0xffffffffu, rmax, 2));
            rmax = fmaxf(rmax, __shfl_xor_sync(0xffffffffu, rmax, 4));
            rmax = fmaxf(rmax, __shfl_xor_sync(0xffffffffu, rmax, 8));

            float mnew = fmaxf(mrow[i], rmax);
            float rs = __expf(mrow[i] - mnew);
            float p[4], psum = 0.f;
            #pragma unroll
            for (int j = 0; j < 4; j++) {
                p[j] = __expf(le[j] - mnew);
                psum += p[j];
            }
            psum += __shfl_xor_sync(0xffffffffu, psum, 1);
            psum += __shfl_xor_sync(0xffffffffu, psum, 2);
            psum += __shfl_xor_sync(0xffffffffu, psum, 4);
            psum += __shfl_xor_sync(0xffffffffu, psum, 8);
            srow[i] = srow[i] * rs + psum;
            mrow[i] = mnew;
            ull rp = rep2(rs);
            mul2(acc[i][0], rp);
            mul2(acc[i][1], rp);
            *reinterpret_cast<float4*>(&Ps[(trow * 8 + i) * 64 + tcol * 4]) =
                make_float4(p[0], p[1], p[2], p[3]);
        }

        CP_WAIT1();
        __syncthreads();

        #pragma unroll 4
        for (int k4 = 0; k4 < 16; k4++) {
            ull vb[4][2];
            #pragma unroll
            for (int j = 0; j < 4; j++) {
                float4 v = *reinterpret_cast<const float4*>(
                    &Vs[(k4 * 4 + j) * 64 + tcol * 4]);
                vb[j][0] = pk2(v.x, v.y);
                vb[j][1] = pk2(v.z, v.w);
            }
            #pragma unroll
            for (int i = 0; i < 8; i++) {
                float4 pf = *reinterpret_cast<const float4*>(
                    &Ps[(trow * 8 + i) * 64 + k4 * 4]);
                ull p0 = rep2(pf.x), p1 = rep2(pf.y);
                ull p2 = rep2(pf.z), p3 = rep2(pf.w);
                fma2(acc[i][0], p0, vb[0][0]); fma2(acc[i][1], p0, vb[0][1]);
                fma2(acc[i][0], p1, vb[1][0]); fma2(acc[i][1], p1, vb[1][1]);
                fma2(acc[i][0], p2, vb[2][0]); fma2(acc[i][1], p2, vb[2][1]);
                fma2(acc[i][0], p3, vb[3][0]); fma2(acc[i][1], p3, vb[3][1]);
            }
        }
    }

    #pragma unroll
    for (int i = 0; i < 8; i++) {
        float inv = 1.0f / srow[i];
        float2 x0 = upk(acc[i][0]), x1 = upk(acc[i][1]);
        *reinterpret_cast<float4*>(
            g_OH + ((size_t)b * SEQ + q0 + trow * 8 + i) * DM + h * HD + tcol * 4) =
            make_float4(x0.x * inv, x0.y * inv, x1.x * inv, x1.y * inv);
    }
}

// ---------------------------------------------------------------------------
// Launch. Output: [out (4*2048*768)] then [logits_raw (48*2048*2048)]
// ---------------------------------------------------------------------------
extern "C" void kernel_launch(void* const* d_in, const int* in_sizes, int n_in,
                              void* d_out, int out_size)
{
    const float* x  = (const float*)d_in[0];
    const float* qm = (const float*)d_in[1];
    const float* Wq = (const float*)d_in[2];
    const float* Wk = (const float*)d_in[3];
    const float* Wv = (const float*)d_in[4];
    const float* Wo = (const float*)d_in[5];

    float* out    = (float*)d_out;
    float* logits = out + (size_t)MROWS * DM;

    const int FLASH_SMEM = 28672 * 4;   // 112KB
    cudaFuncSetAttribute(flash_attn,
                         cudaFuncAttributeMaxDynamicSharedMemorySize, FLASH_SMEM);

    mma_gemm  <<<dim3(6, 64, 3), 256>>>(x, Wq, Wk, Wv, nullptr, 0);
    flash_attn<<<dim3(16, 48), 256, FLASH_SMEM>>>(qm, logits);
    mma_gemm  <<<dim3(6, 64, 1), 256>>>(nullptr, Wo, Wo, Wo, out, 3);
}

// round 7
// speedup vs baseline: 5.2190x; 1.6138x over previous
#include <cuda_runtime.h>
#include <math.h>
#include <stdint.h>

#define BATCH 4
#define SEQ   2048
#define DM    768
#define NH    12
#define HD    64
#define MROWS (BATCH*SEQ)   // 8192
#define BHT   (BATCH*NH)    // 48

// ---------------- misc helpers ----------------
__device__ __forceinline__ uint32_t s2u(const void* p) {
    uint32_t a;
    asm("{ .reg .u64 t; cvta.to.shared.u64 t, %1; cvt.u32.u64 %0, t; }"
        : "=r"(a) : "l"(p));
    return a;
}
// cp.async 16B (sm_80 PTX)
__device__ __forceinline__ void cpa16(uint32_t dst, const void* src) {
    asm volatile("cp.async.cg.shared.global [%0], [%1], 16;"
                 :: "r"(dst), "l"(src) : "memory");
}
#define CP_COMMIT() asm volatile("cp.async.commit_group;" ::: "memory")
#define CP_WAIT1()  asm volatile("cp.async.wait_group 1;" ::: "memory")
#define CP_WAIT2()  asm volatile("cp.async.wait_group 2;" ::: "memory")

// ---------------- mma.sync helpers (sm_80 PTX, legacy HMMA) ----------------
__device__ __forceinline__ void ldsm_x4(uint32_t* r, uint32_t addr) {
    asm volatile("ldmatrix.sync.aligned.m8n8.x4.shared.b16 {%0,%1,%2,%3}, [%4];"
                 : "=r"(r[0]), "=r"(r[1]), "=r"(r[2]), "=r"(r[3]) : "r"(addr));
}
__device__ __forceinline__ void ldsm_x4t(uint32_t* r, uint32_t addr) {
    asm volatile("ldmatrix.sync.aligned.m8n8.x4.trans.shared.b16 {%0,%1,%2,%3}, [%4];"
                 : "=r"(r[0]), "=r"(r[1]), "=r"(r[2]), "=r"(r[3]) : "r"(addr));
}
__device__ __forceinline__ void mma16816(float* c, const uint32_t* a, const uint32_t* b) {
    asm volatile(
        "mma.sync.aligned.m16n8k16.row.col.f32.bf16.bf16.f32 "
        "{%0,%1,%2,%3}, {%4,%5,%6,%7}, {%8,%9}, {%0,%1,%2,%3};"
        : "+f"(c[0]), "+f"(c[1]), "+f"(c[2]), "+f"(c[3])
        : "r"(a[0]), "r"(a[1]), "r"(a[2]), "r"(a[3]), "r"(b[0]), "r"(b[1]));
}
// split (a,b) -> bf16x2 hi word + residual lo word (lo half = a)
__device__ __forceinline__ void split2(float a, float b, uint32_t& h, uint32_t& l) {
    asm("cvt.rn.bf16x2.f32 %0, %1, %2;" : "=r"(h) : "f"(b), "f"(a));
    float ra = a - __uint_as_float(h << 16);
    float rb = b - __uint_as_float(h & 0xffff0000u);
    asm("cvt.rn.bf16x2.f32 %0, %1, %2;" : "=r"(l) : "f"(rb), "f"(ra));
}
// split float4 -> bf16 hi/lo pairs and STS (8B each) — used by mma_gemm loads
__device__ __forceinline__ void cvtsts(float4 v, uint32_t* baseH, uint32_t* baseL, int idx) {
    uint32_t ph0, ph1, pl0, pl1;
    split2(v.x, v.y, ph0, pl0);
    split2(v.z, v.w, ph1, pl1);
    *reinterpret_cast<uint2*>(baseH + idx) = make_uint2(ph0, ph1);
    *reinterpret_cast<uint2*>(baseL + idx) = make_uint2(pl0, pl1);
}

// Scratch: Q/K/V as packed bf16 hi/lo ([b,h,s,d], 32 u32 per row). Q pre-scaled 1/8.
__device__ uint32_t g_Qh[(size_t)BHT*SEQ*HD/2];
__device__ uint32_t g_Ql[(size_t)BHT*SEQ*HD/2];
__device__ uint32_t g_Kh[(size_t)BHT*SEQ*HD/2];
__device__ uint32_t g_Kl[(size_t)BHT*SEQ*HD/2];
__device__ uint32_t g_Vh[(size_t)BHT*SEQ*HD/2];
__device__ uint32_t g_Vl[(size_t)BHT*SEQ*HD/2];
__device__ float    g_OH[(size_t)MROWS*DM];      // attention out f32, [b,s,h*64+d]

// ---------------------------------------------------------------------------
// bf16-split mma.sync GEMM: C[8192x768] = A @ W.
// 128x128 CTA tile, BK=32, 8 warps (2M x 4N), m16n8k16, 3-term split.
// mode 0/1/2: A=x, W=Wq/Wk/Wv -> g_{Q,K,V}{h,l} bf16 (Q scaled 1/8)
// mode 3:     A=g_OH (f32), W=Wo -> lin_out f32 row-major
// ---------------------------------------------------------------------------
__global__ __launch_bounds__(256) void mma_gemm(
    const float* __restrict__ Ain,
    const float* __restrict__ W0, const float* __restrict__ W1,
    const float* __restrict__ W2,
    float* __restrict__ lin_out, int base_mode)
{
    __shared__ __align__(16) uint32_t sAh[128 * 20];
    __shared__ __align__(16) uint32_t sAl[128 * 20];
    __shared__ __align__(16) uint32_t sBh[32 * 68];
    __shared__ __align__(16) uint32_t sBl[32 * 68];

    int mode = base_mode + blockIdx.z;
    const float* W = (mode == 0) ? W0 : (mode == 1) ? W1 : (mode == 2) ? W2 : W0;
    const float* A = (mode == 3) ? (const float*)g_OH : Ain;

    int tid  = threadIdx.x;
    int wid  = tid >> 5, lane = tid & 31;
    int warpM = wid & 1, warpN = wid >> 1;
    int m0 = blockIdx.y * 128, n0 = blockIdx.x * 128;

    float acc[4][4][4];
    #pragma unroll
    for (int i = 0; i < 4; i++)
        #pragma unroll
        for (int j = 0; j < 4; j++)
            #pragma unroll
            for (int k = 0; k < 4; k++) acc[i][j][k] = 0.f;

    uint32_t aBase  = s2u(sAh), alBase = s2u(sAl);
    uint32_t bBase  = s2u(sBh), blBase = s2u(sBl);
    uint32_t aLane = (uint32_t)((lane & 15) * 80 + (lane >> 4) * 16 + warpM * 64 * 80);
    uint32_t bLane = (uint32_t)((lane & 15) * 272 + (lane >> 4) * 16 + warpN * 64);

    #pragma unroll
    for (int it = 0; it < 4; it++) {
        int i = tid + it * 256;
        int r = i >> 3, c4 = (i & 7) * 4;
        float4 v = *reinterpret_cast<const float4*>(A + (size_t)(m0 + r) * DM + c4);
        cvtsts(v, sAh, sAl, r * 20 + (c4 >> 1));
        int rb = i >> 5, cb = (i & 31) * 4;
        float4 w = *reinterpret_cast<const float4*>(W + (size_t)rb * DM + n0 + cb);
        cvtsts(w, sBh, sBl, rb * 68 + (cb >> 1));
    }
    __syncthreads();

    for (int c = 0; c < 24; c++) {
        float4 av[4], bv[4];
        if (c < 23) {
            int k0n = (c + 1) * 32;
            #pragma unroll
            for (int it = 0; it < 4; it++) {
                int i = tid + it * 256;
                int r = i >> 3, c4 = (i & 7) * 4;
                av[it] = *reinterpret_cast<const float4*>(
                    A + (size_t)(m0 + r) * DM + k0n + c4);
                int rb = i >> 5, cb = (i & 31) * 4;
                bv[it] = *reinterpret_cast<const float4*>(
                    W + (size_t)(k0n + rb) * DM + n0 + cb);
            }
        }
        #pragma unroll
        for (int ks = 0; ks < 2; ks++) {
            uint32_t bh[4][2], bl[4][2];
            #pragma unroll
            for (int np = 0; np < 2; np++) {
                uint32_t r4[4];
                ldsm_x4t(r4, bBase + bLane + ks * 4352 + np * 32);
                bh[np*2][0] = r4[0]; bh[np*2][1] = r4[1];
                bh[np*2+1][0] = r4[2]; bh[np*2+1][1] = r4[3];
                ldsm_x4t(r4, blBase + bLane + ks * 4352 + np * 32);
                bl[np*2][0] = r4[0]; bl[np*2][1] = r4[1];
                bl[np*2+1][0] = r4[2]; bl[np*2+1][1] = r4[3];
            }
            #pragma unroll
            for (int mt = 0; mt < 4; mt++) {
                uint32_t ah[4], al4[4];
                ldsm_x4(ah,  aBase  + aLane + mt * 1280 + ks * 32);
                ldsm_x4(al4, alBase + aLane + mt * 1280 + ks * 32);
                #pragma unroll
                for (int nt = 0; nt < 4; nt++) {
                    mma16816(acc[mt][nt], ah,  bh[nt]);
                    mma16816(acc[mt][nt], ah,  bl[nt]);
                    mma16816(acc[mt][nt], al4, bh[nt]);
                }
            }
        }
        __syncthreads();
        if (c < 23) {
            #pragma unroll
            for (int it = 0; it < 4; it++) {
                int i = tid + it * 256;
                int r = i >> 3, c4 = (i & 7) * 4;
                cvtsts(av[it], sAh, sAl, r * 20 + (c4 >> 1));
                int rb = i >> 5, cb = (i & 31) * 4;
                cvtsts(bv[it], sBh, sBl, rb * 68 + (cb >> 1));
            }
            __syncthreads();
        }
    }

    int rl = lane >> 2, cl = (lane & 3) * 2;
    if (mode == 3) {
        #pragma unroll
        for (int mt = 0; mt < 4; mt++) {
            int m = m0 + warpM * 64 + mt * 16 + rl;
            #pragma unroll
            for (int nt = 0; nt < 4; nt++) {
                int n = n0 + warpN * 32 + nt * 8 + cl;
                *reinterpret_cast<float2*>(lin_out + (size_t)m * DM + n) =
                    make_float2(acc[mt][nt][0], acc[mt][nt][1]);
                *reinterpret_cast<float2*>(lin_out + (size_t)(m + 8) * DM + n) =
                    make_float2(acc[mt][nt][2], acc[mt][nt][3]);
            }
        }
    } else {
        float alpha = (mode == 0) ? 0.125f : 1.0f;
        uint32_t* dh = (mode == 0) ? g_Qh : (mode == 1) ? g_Kh : g_Vh;
        uint32_t* dl = (mode == 0) ? g_Ql : (mode == 1) ? g_Kl : g_Vl;
        #pragma unroll
        for (int mt = 0; mt < 4; mt++) {
            int m = m0 + warpM * 64 + mt * 16 + rl;
            int b = m >> 11, s = m & 2047;
            #pragma unroll
            for (int nt = 0; nt < 4; nt++) {
                int n = n0 + warpN * 32 + nt * 8 + cl;
                int h = n >> 6, d = n & 63;
                size_t base = ((size_t)(b * NH + h) * SEQ + s) * 32 + (d >> 1);
                uint32_t hi, lo;
                split2(acc[mt][nt][0] * alpha, acc[mt][nt][1] * alpha, hi, lo);
                dh[base] = hi; dl[base] = lo;
                split2(acc[mt][nt][2] * alpha, acc[mt][nt][3] * alpha, hi, lo);
                dh[base + 8 * 32] = hi; dl[base + 8 * 32] = lo;
            }
        }
    }
}

// ---------------------------------------------------------------------------
// Flash attention via mma.sync: CTA = 128q x head; 8 warps x m16 rows.
// Per 64-col k-tile: S = Q.K^T (3-term bf16 split), raw logits -> gmem,
// mask + online softmax on fragments, P packed to bf16 hi/lo in regs,
// O += P.V (3-term split). cp.async: K double-buffered + JIT V.
// Mask applied cancellation-free: u = 1 - qm*km (exact 0), le = fma(-1e5, u, s).
// ---------------------------------------------------------------------------
__global__ __launch_bounds__(256, 1) void flash_mma(
    const float* __restrict__ q_mask, float* __restrict__ logits)
{
    extern __shared__ uint32_t sm32[];
    uint32_t sb = s2u(sm32);
    // byte offsets (rows padded to 144B = 72 bf16)
    const uint32_t oQH = 0, oQL = 18432;
    const uint32_t oKH0 = 36864, oKL0 = 46080, oKH1 = 55296, oKL1 = 64512;
    const uint32_t oVH = 73728, oVL = 82944, oKM = 92160;
    float* smKM = reinterpret_cast<float*>(sm32) + oKM / 4;

    int bh = blockIdx.y;
    int b  = bh / NH;
    int h  = bh - b * NH;
    int q0 = blockIdx.x * 128;
    int tid = threadIdx.x;
    int w = tid >> 5, lane = tid & 31;
    int rq = lane >> 2, cq = lane & 3;

    // prologue: Q tile + K(0) via cp.async
    #pragma unroll
    for (int it = 0; it < 4; it++) {
        int i = tid + it * 256;
        int r = i >> 3, ch = i & 7;
        size_t src = ((size_t)(bh * SEQ + q0 + r)) * 32 + ch * 4;
        cpa16(sb + oQH + r * 144 + ch * 16, g_Qh + src);
        cpa16(sb + oQL + r * 144 + ch * 16, g_Ql + src);
    }
    #pragma unroll
    for (int it = 0; it < 2; it++) {
        int i = tid + it * 256;
        int r = i >> 3, ch = i & 7;
        size_t src = ((size_t)(bh * SEQ + r)) * 32 + ch * 4;
        cpa16(sb + oKH0 + r * 144 + ch * 16, g_Kh + src);
        cpa16(sb + oKL0 + r * 144 + ch * 16, g_Kl + src);
    }
    CP_COMMIT();

    int rowA = 16 * w + rq;
    float qmA = q_mask[(size_t)b * SEQ + q0 + rowA];
    float qmB = q_mask[(size_t)b * SEQ + q0 + rowA + 8];
    float mA = -3.0e38f, mB = -3.0e38f, sA = 0.f, sB = 0.f;
    float o[8][4];
    #pragma unroll
    for (int i = 0; i < 8; i++)
        #pragma unroll
        for (int j = 0; j < 4; j++) o[i][j] = 0.f;
    uint32_t qh[4][4], ql[4][4];

    float* LA = logits + ((size_t)bh * SEQ + q0 + rowA) * SEQ + 2 * cq;
    float* LB = LA + (size_t)8 * SEQ;

    for (int t = 0; t < 32; t++) {
        int k0 = t * 64;
        __syncthreads();   // previous V/Km consumers done
        if (tid < 16)
            *reinterpret_cast<float4*>(smKM + tid * 4) =
                *reinterpret_cast<const float4*>(q_mask + (size_t)b * SEQ + k0 + tid * 4);
        // V(t)
        #pragma unroll
        for (int it = 0; it < 2; it++) {
            int i = tid + it * 256;
            int r = i >> 3, ch = i & 7;
            size_t src = ((size_t)(bh * SEQ + k0 + r)) * 32 + ch * 4;
            cpa16(sb + oVH + r * 144 + ch * 16, g_Vh + src);
            cpa16(sb + oVL + r * 144 + ch * 16, g_Vl + src);
        }
        CP_COMMIT();
        // K(t+1)
        if (t + 1 < 32) {
            uint32_t kh = ((t + 1) & 1) ? oKH1 : oKH0;
            uint32_t kl = ((t + 1) & 1) ? oKL1 : oKL0;
            int k1 = k0 + 64;
            #pragma unroll
            for (int it = 0; it < 2; it++) {
                int i = tid + it * 256;
                int r = i >> 3, ch = i & 7;
                size_t src = ((size_t)(bh * SEQ + k1 + r)) * 32 + ch * 4;
                cpa16(sb + kh + r * 144 + ch * 16, g_Kh + src);
                cpa16(sb + kl + r * 144 + ch * 16, g_Kl + src);
            }
        }
        CP_COMMIT();
        CP_WAIT2();        // K(t) (+Q on t=0) arrived
        __syncthreads();

        if (t == 0) {
            uint32_t qoff = (uint32_t)((16 * w + (lane & 15)) * 144 + (lane >> 4) * 16);
            #pragma unroll
            for (int ks = 0; ks < 4; ks++) {
                ldsm_x4(qh[ks], sb + oQH + qoff + ks * 32);
                ldsm_x4(ql[ks], sb + oQL + qoff + ks * 32);
            }
        }

        // ---- S = Q.K^T ----
        uint32_t kb  = sb + ((t & 1) ? oKH1 : oKH0);
        uint32_t klb = sb + ((t & 1) ? oKL1 : oKL0);
        float s[8][4];
        #pragma unroll
        for (int i = 0; i < 8; i++)
            #pragma unroll
            for (int j = 0; j < 4; j++) s[i][j] = 0.f;
        #pragma unroll
        for (int g = 0; g < 4; g++) {
            uint32_t koff = (uint32_t)((16 * g + (lane & 15)) * 144 + (lane >> 4) * 16);
            #pragma unroll
            for (int ks = 0; ks < 4; ks++) {
                uint32_t r4[4], l4[4];
                ldsm_x4(r4, kb + koff + ks * 32);
                ldsm_x4(l4, klb + koff + ks * 32);
                uint32_t bh0[2] = {r4[0], r4[2]}, bh1[2] = {r4[1], r4[3]};
                uint32_t bl0[2] = {l4[0], l4[2]}, bl1[2] = {l4[1], l4[3]};
                mma16816(s[2*g],   qh[ks], bh0);
                mma16816(s[2*g+1], qh[ks], bh1);
                mma16816(s[2*g],   qh[ks], bl0);
                mma16816(s[2*g+1], qh[ks], bl1);
                mma16816(s[2*g],   ql[ks], bh0);
                mma16816(s[2*g+1], ql[ks], bh1);
            }
        }

        // ---- raw logits ----
        #pragma unroll
        for (int j = 0; j < 8; j++) {
            *reinterpret_cast<float2*>(LA + k0 + 8 * j) = make_float2(s[j][0], s[j][1]);
            *reinterpret_cast<float2*>(LB + k0 + 8 * j) = make_float2(s[j][2], s[j][3]);
        }

        // ---- mask + online softmax (cancellation-free mask) ----
        float mxA = -3.0e38f, mxB = -3.0e38f;
        #pragma unroll
        for (int j = 0; j < 8; j++) {
            float km0 = smKM[8 * j + 2 * cq], km1 = smKM[8 * j + 2 * cq + 1];
            float uA0 = 1.0f - qmA * km0, uA1 = 1.0f - qmA * km1;
            float uB0 = 1.0f - qmB * km0, uB1 = 1.0f - qmB * km1;
            s[j][0] = fmaf(-1e5f, uA0, s[j][0]);
            s[j][1] = fmaf(-1e5f, uA1, s[j][1]);
            s[j][2] = fmaf(-1e5f, uB0, s[j][2]);
            s[j][3] = fmaf(-1e5f, uB1, s[j][3]);
            mxA = fmaxf(mxA, fmaxf(s[j][0], s[j][1]));
            mxB = fmaxf(mxB, fmaxf(s[j][2], s[j][3]));
        }
        mxA = fmaxf(mxA, __shfl_xor_sync(0xffffffffu, mxA, 1));
        mxA = fmaxf(mxA, __shfl_xor_sync(0xffffffffu, mxA, 2));
        mxB = fmaxf(mxB, __shfl_xor_sync(0xffffffffu, mxB, 1));
        mxB = fmaxf(mxB, __shfl_xor_sync(0xffffffffu, mxB, 2));
        float mnA = fmaxf(mA, mxA), mnB = fmaxf(mB, mxB);
        float rsA = __expf(mA - mnA), rsB = __expf(mB - mnB);
        mA = mnA; mB = mnB;
        sA *= rsA; sB *= rsB;
        #pragma unroll
        for (int j = 0; j < 8; j++) {
            s[j][0] = __expf(s[j][0] - mnA);
            s[j][1] = __expf(s[j][1] - mnA);
            s[j][2] = __expf(s[j][2] - mnB);
            s[j][3] = __expf(s[j][3] - mnB);
            sA += s[j][0] + s[j][1];
            sB += s[j][2] + s[j][3];
        }
        #pragma unroll
        for (int dt = 0; dt < 8; dt++) {
            o[dt][0] *= rsA; o[dt][1] *= rsA;
            o[dt][2] *= rsB; o[dt][3] *= rsB;
        }

        CP_WAIT1();        // V(t) arrived
        __syncthreads();

        // ---- O += P.V ----
        #pragma unroll
        for (int ks = 0; ks < 4; ks++) {
            uint32_t pa[4], pl[4];
            split2(s[2*ks][0],   s[2*ks][1],   pa[0], pl[0]);
            split2(s[2*ks][2],   s[2*ks][3],   pa[1], pl[1]);
            split2(s[2*ks+1][0], s[2*ks+1][1], pa[2], pl[2]);
            split2(s[2*ks+1][2], s[2*ks+1][3], pa[3], pl[3]);
            uint32_t voff = (uint32_t)((16 * ks + (lane & 15)) * 144 + (lane >> 4) * 16);
            #pragma unroll
            for (int dg = 0; dg < 4; dg++) {
                uint32_t v4[4], w4[4];
                ldsm_x4t(v4, sb + oVH + voff + dg * 32);
                ldsm_x4t(w4, sb + oVL + voff + dg * 32);
                uint32_t vh0[2] = {v4[0], v4[1]}, vh1[2] = {v4[2], v4[3]};
                uint32_t vl0[2] = {w4[0], w4[1]}, vl1[2] = {w4[2], w4[3]};
                mma16816(o[2*dg],   pa, vh0);
                mma16816(o[2*dg+1], pa, vh1);
                mma16816(o[2*dg],   pa, vl0);
                mma16816(o[2*dg+1], pa, vl1);
                mma16816(o[2*dg],   pl, vh0);
                mma16816(o[2*dg+1], pl, vh1);
            }
        }
    }

    // final sum reduce + normalize + store
    sA += __shfl_xor_sync(0xffffffffu, sA, 1);
    sA += __shfl_xor_sync(0xffffffffu, sA, 2);
    sB += __shfl_xor_sync(0xffffffffu, sB, 1);
    sB += __shfl_xor_sync(0xffffffffu, sB, 2);
    float invA = 1.0f / sA, invB = 1.0f / sB;
    float* OA = g_OH + ((size_t)b * SEQ + q0 + rowA) * DM + h * HD + 2 * cq;
    float* OB = OA + (size_t)8 * DM;
    #pragma unroll
    for (int dt = 0; dt < 8; dt++) {
        *reinterpret_cast<float2*>(OA + 8 * dt) =
            make_float2(o[dt][0] * invA, o[dt][1] * invA);
        *reinterpret_cast<float2*>(OB + 8 * dt) =
            make_float2(o[dt][2] * invB, o[dt][3] * invB);
    }
}

// ---------------------------------------------------------------------------
// Launch. Output: [out (4*2048*768)] then [logits_raw (48*2048*2048)]
// ---------------------------------------------------------------------------
extern "C" void kernel_launch(void* const* d_in, const int* in_sizes, int n_in,
                              void* d_out, int out_size)
{
    const float* x  = (const float*)d_in[0];
    const float* qm = (const float*)d_in[1];
    const float* Wq = (const float*)d_in[2];
    const float* Wk = (const float*)d_in[3];
    const float* Wv = (const float*)d_in[4];
    const float* Wo = (const float*)d_in[5];

    float* out    = (float*)d_out;
    float* logits = out + (size_t)MROWS * DM;

    const int FLASH_SMEM = 92416;
    cudaFuncSetAttribute(flash_mma,
                         cudaFuncAttributeMaxDynamicSharedMemorySize, FLASH_SMEM);

    mma_gemm <<<dim3(6, 64, 3), 256>>>(x, Wq, Wk, Wv, nullptr, 0);
    flash_mma<<<dim3(16, 48), 256, FLASH_SMEM>>>(qm, logits);
    mma_gemm <<<dim3(6, 64, 1), 256>>>(nullptr, Wo, Wo, Wo, out, 3);
}

// round 8
// speedup vs baseline: 5.2939x; 1.0144x over previous
#include <cuda_runtime.h>
#include <math.h>
#include <stdint.h>

#define BATCH 4
#define SEQ   2048
#define DM    768
#define NH    12
#define HD    64
#define MROWS (BATCH*SEQ)   // 8192
#define BHT   (BATCH*NH)    // 48

// ---------------- misc helpers ----------------
__device__ __forceinline__ uint32_t s2u(const void* p) {
    uint32_t a;
    asm("{ .reg .u64 t; cvta.to.shared.u64 t, %1; cvt.u32.u64 %0, t; }"
        : "=r"(a) : "l"(p));
    return a;
}
// cp.async 16B (sm_80 PTX)
__device__ __forceinline__ void cpa16(uint32_t dst, const void* src) {
    asm volatile("cp.async.cg.shared.global [%0], [%1], 16;"
                 :: "r"(dst), "l"(src) : "memory");
}
#define CP_COMMIT() asm volatile("cp.async.commit_group;" ::: "memory")
#define CP_WAIT0()  asm volatile("cp.async.wait_group 0;" ::: "memory")

// ---------------- mma.sync helpers (sm_80 PTX, legacy HMMA) ----------------
__device__ __forceinline__ void ldsm_x4(uint32_t* r, uint32_t addr) {
    asm volatile("ldmatrix.sync.aligned.m8n8.x4.shared.b16 {%0,%1,%2,%3}, [%4];"
                 : "=r"(r[0]), "=r"(r[1]), "=r"(r[2]), "=r"(r[3]) : "r"(addr));
}
__device__ __forceinline__ void ldsm_x4t(uint32_t* r, uint32_t addr) {
    asm volatile("ldmatrix.sync.aligned.m8n8.x4.trans.shared.b16 {%0,%1,%2,%3}, [%4];"
                 : "=r"(r[0]), "=r"(r[1]), "=r"(r[2]), "=r"(r[3]) : "r"(addr));
}
__device__ __forceinline__ void mma16816(float* c, const uint32_t* a, const uint32_t* b) {
    asm volatile(
        "mma.sync.aligned.m16n8k16.row.col.f32.bf16.bf16.f32 "
        "{%0,%1,%2,%3}, {%4,%5,%6,%7}, {%8,%9}, {%0,%1,%2,%3};"
        : "+f"(c[0]), "+f"(c[1]), "+f"(c[2]), "+f"(c[3])
        : "r"(a[0]), "r"(a[1]), "r"(a[2]), "r"(a[3]), "r"(b[0]), "r"(b[1]));
}
// split (a,b) -> bf16x2 hi word + residual lo word (lo half = a)
__device__ __forceinline__ void split2(float a, float b, uint32_t& h, uint32_t& l) {
    asm("cvt.rn.bf16x2.f32 %0, %1, %2;" : "=r"(h) : "f"(b), "f"(a));
    float ra = a - __uint_as_float(h << 16);
    float rb = b - __uint_as_float(h & 0xffff0000u);
    asm("cvt.rn.bf16x2.f32 %0, %1, %2;" : "=r"(l) : "f"(rb), "f"(ra));
}
__device__ __forceinline__ void cvtsts(float4 v, uint32_t* baseH, uint32_t* baseL, int idx) {
    uint32_t ph0, ph1, pl0, pl1;
    split2(v.x, v.y, ph0, pl0);
    split2(v.z, v.w, ph1, pl1);
    *reinterpret_cast<uint2*>(baseH + idx) = make_uint2(ph0, ph1);
    *reinterpret_cast<uint2*>(baseL + idx) = make_uint2(pl0, pl1);
}

// Scratch: Q/K/V as packed bf16 hi/lo ([b,h,s,d], 32 u32 per row). Q pre-scaled 1/8.
__device__ uint32_t g_Qh[(size_t)BHT*SEQ*HD/2];
__device__ uint32_t g_Ql[(size_t)BHT*SEQ*HD/2];
__device__ uint32_t g_Kh[(size_t)BHT*SEQ*HD/2];
__device__ uint32_t g_Kl[(size_t)BHT*SEQ*HD/2];
__device__ uint32_t g_Vh[(size_t)BHT*SEQ*HD/2];
__device__ uint32_t g_Vl[(size_t)BHT*SEQ*HD/2];
__device__ float    g_OH[(size_t)MROWS*DM];      // attention out f32, [b,s,h*64+d]

// ---------------------------------------------------------------------------
// bf16-split mma.sync GEMM: C[8192x768] = A @ W.
// 128x128 CTA tile, BK=32, 8 warps (2M x 4N), m16n8k16, 3-term split.
// Double-buffered smem (1 sync/chunk); MMA sweeps over 8 distinct accs.
// ---------------------------------------------------------------------------
__global__ __launch_bounds__(256) void mma_gemm(
    const float* __restrict__ Ain,
    const float* __restrict__ W0, const float* __restrict__ W1,
    const float* __restrict__ W2,
    float* __restrict__ lin_out, int base_mode)
{
    extern __shared__ uint32_t smg[];
    // per-buffer (u32): Ah 0, Al 2560, Bh 5120, Bl 7296; buf stride 9472
    const uint32_t BUFU = 9472;

    int mode = base_mode + blockIdx.z;
    const float* W = (mode == 0) ? W0 : (mode == 1) ? W1 : (mode == 2) ? W2 : W0;
    const float* A = (mode == 3) ? (const float*)g_OH : Ain;

    int tid  = threadIdx.x;
    int wid  = tid >> 5, lane = tid & 31;
    int warpM = wid & 1, warpN = wid >> 1;
    int m0 = blockIdx.y * 128, n0 = blockIdx.x * 128;

    float acc[4][4][4];
    #pragma unroll
    for (int i = 0; i < 4; i++)
        #pragma unroll
        for (int j = 0; j < 4; j++)
            #pragma unroll
            for (int k = 0; k < 4; k++) acc[i][j][k] = 0.f;

    uint32_t sbg = s2u(smg);
    uint32_t aLane = (uint32_t)((lane & 15) * 80 + (lane >> 4) * 16 + warpM * 5120);
    uint32_t bLane = (uint32_t)((lane & 15) * 272 + (lane >> 4) * 16 + warpN * 64);

    float4 av[4], bv[4];
    // LDG chunk 0, STS buf0
    #pragma unroll
    for (int it = 0; it < 4; it++) {
        int i = tid + it * 256;
        int r = i >> 3, c4 = (i & 7) * 4;
        av[it] = *reinterpret_cast<const float4*>(A + (size_t)(m0 + r) * DM + c4);
        int rb = i >> 5, cb = (i & 31) * 4;
        bv[it] = *reinterpret_cast<const float4*>(W + (size_t)rb * DM + n0 + cb);
    }
    #pragma unroll
    for (int it = 0; it < 4; it++) {
        int i = tid + it * 256;
        int r = i >> 3, c4 = (i & 7) * 4;
        cvtsts(av[it], smg, smg + 2560, r * 20 + (c4 >> 1));
        int rb = i >> 5, cb = (i & 31) * 4;
        cvtsts(bv[it], smg + 5120, smg + 7296, rb * 68 + (cb >> 1));
    }
    // LDG chunk 1 into regs
    #pragma unroll
    for (int it = 0; it < 4; it++) {
        int i = tid + it * 256;
        int r = i >> 3, c4 = (i & 7) * 4;
        av[it] = *reinterpret_cast<const float4*>(A + (size_t)(m0 + r) * DM + 32 + c4);
        int rb = i >> 5, cb = (i & 31) * 4;
        bv[it] = *reinterpret_cast<const float4*>(W + (size_t)(32 + rb) * DM + n0 + cb);
    }
    __syncthreads();

    for (int c = 0; c < 24; c++) {
        // STS data(c+1) into buf (c+1)&1 (regs hold it)
        if (c < 23) {
            uint32_t* base = smg + ((c + 1) & 1) * BUFU;
            #pragma unroll
            for (int it = 0; it < 4; it++) {
                int i = tid + it * 256;
                int r = i >> 3, c4 = (i & 7) * 4;
                cvtsts(av[it], base, base + 2560, r * 20 + (c4 >> 1));
                int rb = i >> 5, cb = (i & 31) * 4;
                cvtsts(bv[it], base + 5120, base + 7296, rb * 68 + (cb >> 1));
            }
        }
        // LDG data(c+2)
        if (c < 22) {
            int k0n = (c + 2) * 32;
            #pragma unroll
            for (int it = 0; it < 4; it++) {
                int i = tid + it * 256;
                int r = i >> 3, c4 = (i & 7) * 4;
                av[it] = *reinterpret_cast<const float4*>(
                    A + (size_t)(m0 + r) * DM + k0n + c4);
                int rb = i >> 5, cb = (i & 31) * 4;
                bv[it] = *reinterpret_cast<const float4*>(
                    W + (size_t)(k0n + rb) * DM + n0 + cb);
            }
        }
        // compute chunk c from buf c&1
        uint32_t off = sbg + (uint32_t)(c & 1) * (BUFU * 4);
        uint32_t aH = off, aL = off + 10240, bH = off + 20480, bL = off + 29184;
        #pragma unroll
        for (int ks = 0; ks < 2; ks++) {
            uint32_t bh[4][2], bl[4][2];
            #pragma unroll
            for (int np = 0; np < 2; np++) {
                uint32_t r4[4];
                ldsm_x4t(r4, bH + bLane + ks * 4352 + np * 32);
                bh[np*2][0] = r4[0]; bh[np*2][1] = r4[1];
                bh[np*2+1][0] = r4[2]; bh[np*2+1][1] = r4[3];
                ldsm_x4t(r4, bL + bLane + ks * 4352 + np * 32);
                bl[np*2][0] = r4[0]; bl[np*2][1] = r4[1];
                bl[np*2+1][0] = r4[2]; bl[np*2+1][1] = r4[3];
            }
            #pragma unroll
            for (int mtp = 0; mtp < 2; mtp++) {
                uint32_t a0h[4], a0l[4], a1h[4], a1l[4];
                ldsm_x4(a0h, aH + aLane + (2*mtp) * 1280 + ks * 32);
                ldsm_x4(a1h, aH + aLane + (2*mtp+1) * 1280 + ks * 32);
                ldsm_x4(a0l, aL + aLane + (2*mtp) * 1280 + ks * 32);
                ldsm_x4(a1l, aL + aLane + (2*mtp+1) * 1280 + ks * 32);
                // pass 1: ah x bh (8 distinct accs)
                #pragma unroll
                for (int nt = 0; nt < 4; nt++) mma16816(acc[2*mtp][nt],   a0h, bh[nt]);
                #pragma unroll
                for (int nt = 0; nt < 4; nt++) mma16816(acc[2*mtp+1][nt], a1h, bh[nt]);
                // pass 2: ah x bl
                #pragma unroll
                for (int nt = 0; nt < 4; nt++) mma16816(acc[2*mtp][nt],   a0h, bl[nt]);
                #pragma unroll
                for (int nt = 0; nt < 4; nt++) mma16816(acc[2*mtp+1][nt], a1h, bl[nt]);
                // pass 3: al x bh
                #pragma unroll
                for (int nt = 0; nt < 4; nt++) mma16816(acc[2*mtp][nt],   a0l, bh[nt]);
                #pragma unroll
                for (int nt = 0; nt < 4; nt++) mma16816(acc[2*mtp+1][nt], a1l, bh[nt]);
            }
        }
        __syncthreads();
    }

    int rl = lane >> 2, cl = (lane & 3) * 2;
    if (mode == 3) {
        #pragma unroll
        for (int mt = 0; mt < 4; mt++) {
            int m = m0 + warpM * 64 + mt * 16 + rl;
            #pragma unroll
            for (int nt = 0; nt < 4; nt++) {
                int n = n0 + warpN * 32 + nt * 8 + cl;
                *reinterpret_cast<float2*>(lin_out + (size_t)m * DM + n) =
                    make_float2(acc[mt][nt][0], acc[mt][nt][1]);
                *reinterpret_cast<float2*>(lin_out + (size_t)(m + 8) * DM + n) =
                    make_float2(acc[mt][nt][2], acc[mt][nt][3]);
            }
        }
    } else {
        float alpha = (mode == 0) ? 0.125f : 1.0f;
        uint32_t* dh = (mode == 0) ? g_Qh : (mode == 1) ? g_Kh : g_Vh;
        uint32_t* dl = (mode == 0) ? g_Ql : (mode == 1) ? g_Kl : g_Vl;
        #pragma unroll
        for (int mt = 0; mt < 4; mt++) {
            int m = m0 + warpM * 64 + mt * 16 + rl;
            int b = m >> 11, s = m & 2047;
            #pragma unroll
            for (int nt = 0; nt < 4; nt++) {
                int n = n0 + warpN * 32 + nt * 8 + cl;
                int h = n >> 6, d = n & 63;
                size_t base = ((size_t)(b * NH + h) * SEQ + s) * 32 + (d >> 1);
                uint32_t hi, lo;
                split2(acc[mt][nt][0] * alpha, acc[mt][nt][1] * alpha, hi, lo);
                dh[base] = hi; dl[base] = lo;
                split2(acc[mt][nt][2] * alpha, acc[mt][nt][3] * alpha, hi, lo);
                dh[base + 8 * 32] = hi; dl[base + 8 * 32] = lo;
            }
        }
    }
}

// ---------------------------------------------------------------------------
// Flash attention via mma.sync: CTA = 128q x head; 8 warps x m16 rows.
// Double-buffered K, V, kmask; ONE sync + ONE cp.async wait per tile.
// MMA sweeps over 8 distinct accumulators. Cancellation-free mask.
// ---------------------------------------------------------------------------
__global__ __launch_bounds__(256, 1) void flash_mma(
    const float* __restrict__ q_mask, float* __restrict__ logits)
{
    extern __shared__ uint32_t sm32[];
    uint32_t sb = s2u(sm32);
    // byte offsets (rows padded to 144B)
    const uint32_t oQH = 0, oQL = 18432;
    const uint32_t oKH[2] = {36864u, 55296u}, oKL[2] = {46080u, 64512u};
    const uint32_t oVH[2] = {73728u, 92160u}, oVL[2] = {82944u, 101376u};
    const uint32_t oKM[2] = {110592u, 110848u};

    int bh = blockIdx.y;
    int b  = bh / NH;
    int h  = bh - b * NH;
    int q0 = blockIdx.x * 128;
    int tid = threadIdx.x;
    int w = tid >> 5, lane = tid & 31;
    int rq = lane >> 2, cq = lane & 3;

    // prologue: Q tile + tile-0 K/V/km, one commit group
    #pragma unroll
    for (int it = 0; it < 4; it++) {
        int i = tid + it * 256;
        int r = i >> 3, ch = i & 7;
        size_t src = ((size_t)(bh * SEQ + q0 + r)) * 32 + ch * 4;
        cpa16(sb + oQH + r * 144 + ch * 16, g_Qh + src);
        cpa16(sb + oQL + r * 144 + ch * 16, g_Ql + src);
    }
    #pragma unroll
    for (int it = 0; it < 2; it++) {
        int i = tid + it * 256;
        int r = i >> 3, ch = i & 7;
        size_t src = ((size_t)(bh * SEQ + r)) * 32 + ch * 4;
        cpa16(sb + oKH[0] + r * 144 + ch * 16, g_Kh + src);
        cpa16(sb + oKL[0] + r * 144 + ch * 16, g_Kl + src);
        cpa16(sb + oVH[0] + r * 144 + ch * 16, g_Vh + src);
        cpa16(sb + oVL[0] + r * 144 + ch * 16, g_Vl + src);
    }
    if (tid < 16)
        cpa16(sb + oKM[0] + tid * 16, q_mask + (size_t)b * SEQ + tid * 4);
    CP_COMMIT();

    int rowA = 16 * w + rq;
    float qmA = q_mask[(size_t)b * SEQ + q0 + rowA];
    float qmB = q_mask[(size_t)b * SEQ + q0 + rowA + 8];
    float mA = -3.0e38f, mB = -3.0e38f, sA = 0.f, sB = 0.f;
    float o[8][4];
    #pragma unroll
    for (int i = 0; i < 8; i++)
        #pragma unroll
        for (int j = 0; j < 4; j++) o[i][j] = 0.f;
    uint32_t qh[4][4], ql[4][4];

    float* LA = logits + ((size_t)bh * SEQ + q0 + rowA) * SEQ + 2 * cq;
    float* LB = LA + (size_t)8 * SEQ;

    for (int t = 0; t < 32; t++) {
        int k0 = t * 64;
        int bi = t & 1;
        CP_WAIT0();        // tile-t group done (per-thread)
        __syncthreads();   // visibility + all warps past tile t-1 (buffers free)

        if (t == 0) {
            uint32_t qoff = (uint32_t)((16 * w + (lane & 15)) * 144 + (lane >> 4) * 16);
            #pragma unroll
            for (int ks = 0; ks < 4; ks++) {
                ldsm_x4(qh[ks], sb + oQH + qoff + ks * 32);
                ldsm_x4(ql[ks], sb + oQL + qoff + ks * 32);
            }
        }
        // issue tile t+1 loads (land during this tile's compute)
        if (t + 1 < 32) {
            int nb = (t + 1) & 1;
            int k1 = k0 + 64;
            #pragma unroll
            for (int it = 0; it < 2; it++) {
                int i = tid + it * 256;
                int r = i >> 3, ch = i & 7;
                size_t src = ((size_t)(bh * SEQ + k1 + r)) * 32 + ch * 4;
                cpa16(sb + oKH[nb] + r * 144 + ch * 16, g_Kh + src);
                cpa16(sb + oKL[nb] + r * 144 + ch * 16, g_Kl + src);
                cpa16(sb + oVH[nb] + r * 144 + ch * 16, g_Vh + src);
                cpa16(sb + oVL[nb] + r * 144 + ch * 16, g_Vl + src);
            }
            if (tid < 16)
                cpa16(sb + oKM[nb] + tid * 16, q_mask + (size_t)b * SEQ + k1 + tid * 4);
            CP_COMMIT();
        }

        // ---- S = Q.K^T (sweeps over 8 distinct accumulators) ----
        uint32_t kbH = sb + oKH[bi], kbL = sb + oKL[bi];
        float s[8][4];
        #pragma unroll
        for (int i = 0; i < 8; i++)
            #pragma unroll
            for (int j = 0; j < 4; j++) s[i][j] = 0.f;
        #pragma unroll
        for (int ks = 0; ks < 4; ks++) {
            uint32_t kf[4][4], lf[4][4];
            #pragma unroll
            for (int g = 0; g < 4; g++) {
                uint32_t koff = (uint32_t)((16 * g + (lane & 15)) * 144
                                           + (lane >> 4) * 16 + ks * 32);
                ldsm_x4(kf[g], kbH + koff);
                ldsm_x4(lf[g], kbL + koff);
            }
            #pragma unroll
            for (int g = 0; g < 4; g++) { uint32_t b2[2] = {kf[g][0], kf[g][2]}; mma16816(s[2*g],   qh[ks], b2); }
            #pragma unroll
            for (int g = 0; g < 4; g++) { uint32_t b2[2] = {kf[g][1], kf[g][3]}; mma16816(s[2*g+1], qh[ks], b2); }
            #pragma unroll
            for (int g = 0; g < 4; g++) { uint32_t b2[2] = {lf[g][0], lf[g][2]}; mma16816(s[2*g],   qh[ks], b2); }
            #pragma unroll
            for (int g = 0; g < 4; g++) { uint32_t b2[2] = {lf[g][1], lf[g][3]}; mma16816(s[2*g+1], qh[ks], b2); }
            #pragma unroll
            for (int g = 0; g < 4; g++) { uint32_t b2[2] = {kf[g][0], kf[g][2]}; mma16816(s[2*g],   ql[ks], b2); }
            #pragma unroll
            for (int g = 0; g < 4; g++) { uint32_t b2[2] = {kf[g][1], kf[g][3]}; mma16816(s[2*g+1], ql[ks], b2); }
        }

        // ---- raw logits ----
        #pragma unroll
        for (int j = 0; j < 8; j++) {
            *reinterpret_cast<float2*>(LA + k0 + 8 * j) = make_float2(s[j][0], s[j][1]);
            *reinterpret_cast<float2*>(LB + k0 + 8 * j) = make_float2(s[j][2], s[j][3]);
        }

        // ---- mask + online softmax (cancellation-free) ----
        const float* smKM = reinterpret_cast<const float*>(
            reinterpret_cast<const char*>(sm32) + oKM[bi]);
        float mxA = -3.0e38f, mxB = -3.0e38f;
        #pragma unroll
        for (int j = 0; j < 8; j++) {
            float km0 = smKM[8 * j + 2 * cq], km1 = smKM[8 * j + 2 * cq + 1];
            float uA0 = 1.0f - qmA * km0, uA1 = 1.0f - qmA * km1;
            float uB0 = 1.0f - qmB * km0, uB1 = 1.0f - qmB * km1;
            s[j][0] = fmaf(-1e5f, uA0, s[j][0]);
            s[j][1] = fmaf(-1e5f, uA1, s[j][1]);
            s[j][2] = fmaf(-1e5f, uB0, s[j][2]);
            s[j][3] = fmaf(-1e5f, uB1, s[j][3]);
            mxA = fmaxf(mxA, fmaxf(s[j][0], s[j][1]));
            mxB = fmaxf(mxB, fmaxf(s[j][2], s[j][3]));
        }
        mxA = fmaxf(mxA, __shfl_xor_sync(0xffffffffu, mxA, 1));
        mxA = fmaxf(mxA, __shfl_xor_sync(0xffffffffu, mxA, 2));
        mxB = fmaxf(mxB, __shfl_xor_sync(0xffffffffu, mxB, 1));
        mxB = fmaxf(mxB, __shfl_xor_sync(0xffffffffu, mxB, 2));
        float mnA = fmaxf(mA, mxA), mnB = fmaxf(mB, mxB);
        float rsA = __expf(mA - mnA), rsB = __expf(mB - mnB);
        mA = mnA; mB = mnB;
        sA *= rsA; sB *= rsB;
        #pragma unroll
        for (int j = 0; j < 8; j++) {
            s[j][0] = __expf(s[j][0] - mnA);
            s[j][1] = __expf(s[j][1] - mnA);
            s[j][2] = __expf(s[j][2] - mnB);
            s[j][3] = __expf(s[j][3] - mnB);
            sA += s[j][0] + s[j][1];
            sB += s[j][2] + s[j][3];
        }
        #pragma unroll
        for (int dt = 0; dt < 8; dt++) {
            o[dt][0] *= rsA; o[dt][1] *= rsA;
            o[dt][2] *= rsB; o[dt][3] *= rsB;
        }

        // ---- O += P.V (V already resident; sweeps over 8 accs) ----
        uint32_t vbH = sb + oVH[bi], vbL = sb + oVL[bi];
        #pragma unroll
        for (int ks = 0; ks < 4; ks++) {
            uint32_t pa[4], pl[4];
            split2(s[2*ks][0],   s[2*ks][1],   pa[0], pl[0]);
            split2(s[2*ks][2],   s[2*ks][3],   pa[1], pl[1]);
            split2(s[2*ks+1][0], s[2*ks+1][1], pa[2], pl[2]);
            split2(s[2*ks+1][2], s[2*ks+1][3], pa[3], pl[3]);
            uint32_t vf[4][4], wf[4][4];
            #pragma unroll
            for (int dg = 0; dg < 4; dg++) {
                uint32_t voff = (uint32_t)((16 * ks + (lane & 15)) * 144
                                           + (lane >> 4) * 16 + dg * 32);
                ldsm_x4t(vf[dg], vbH + voff);
                ldsm_x4t(wf[dg], vbL + voff);
            }
            #pragma unroll
            for (int dg = 0; dg < 4; dg++) { uint32_t b2[2] = {vf[dg][0], vf[dg][1]}; mma16816(o[2*dg],   pa, b2); }
            #pragma unroll
            for (int dg = 0; dg < 4; dg++) { uint32_t b2[2] = {vf[dg][2], vf[dg][3]}; mma16816(o[2*dg+1], pa, b2); }
            #pragma unroll
            for (int dg = 0; dg < 4; dg++) { uint32_t b2[2] = {wf[dg][0], wf[dg][1]}; mma16816(o[2*dg],   pa, b2); }
            #pragma unroll
            for (int dg = 0; dg < 4; dg++) { uint32_t b2[2] = {wf[dg][2], wf[dg][3]}; mma16816(o[2*dg+1], pa, b2); }
            #pragma unroll
            for (int dg = 0; dg < 4; dg++) { uint32_t b2[2] = {vf[dg][0], vf[dg][1]}; mma16816(o[2*dg],   pl, b2); }
            #pragma unroll
            for (int dg = 0; dg < 4; dg++) { uint32_t b2[2] = {vf[dg][2], vf[dg][3]}; mma16816(o[2*dg+1], pl, b2); }
        }
    }

    // final sum reduce + normalize + store
    sA += __shfl_xor_sync(0xffffffffu, sA, 1);
    sA += __shfl_xor_sync(0xffffffffu, sA, 2);
    sB += __shfl_xor_sync(0xffffffffu, sB, 1);
    sB += __shfl_xor_sync(0xffffffffu, sB, 2);
    float invA = 1.0f / sA, invB = 1.0f / sB;
    float* OA = g_OH + ((size_t)b * SEQ + q0 + rowA) * DM + h * HD + 2 * cq;
    float* OB = OA + (size_t)8 * DM;
    #pragma unroll
    for (int dt = 0; dt < 8; dt++) {
        *reinterpret_cast<float2*>(OA + 8 * dt) =
            make_float2(o[dt][0] * invA, o[dt][1] * invA);
        *reinterpret_cast<float2*>(OB + 8 * dt) =
            make_float2(o[dt][2] * invB, o[dt][3] * invB);
    }
}

// ---------------------------------------------------------------------------
// Launch. Output: [out (4*2048*768)] then [logits_raw (48*2048*2048)]
// ---------------------------------------------------------------------------
extern "C" void kernel_launch(void* const* d_in, const int* in_sizes, int n_in,
                              void* d_out, int out_size)
{
    const float* x  = (const float*)d_in[0];
    const float* qm = (const float*)d_in[1];
    const float* Wq = (const float*)d_in[2];
    const float* Wk = (const float*)d_in[3];
    const float* Wv = (const float*)d_in[4];
    const float* Wo = (const float*)d_in[5];

    float* out    = (float*)d_out;
    float* logits = out + (size_t)MROWS * DM;

    const int GEMM_SMEM  = 75776;    // 2 x 9472 u32
    const int FLASH_SMEM = 111104;
    cudaFuncSetAttribute(mma_gemm,
                         cudaFuncAttributeMaxDynamicSharedMemorySize, GEMM_SMEM);
    cudaFuncSetAttribute(flash_mma,
                         cudaFuncAttributeMaxDynamicSharedMemorySize, FLASH_SMEM);

    mma_gemm <<<dim3(6, 64, 3), 256, GEMM_SMEM>>>(x, Wq, Wk, Wv, nullptr, 0);
    flash_mma<<<dim3(16, 48), 256, FLASH_SMEM>>>(qm, logits);
    mma_gemm <<<dim3(6, 64, 1), 256, GEMM_SMEM>>>(nullptr, Wo, Wo, Wo, out, 3);
}

// round 9
// speedup vs baseline: 7.0951x; 1.3402x over previous
#include <cuda_runtime.h>
#include <cuda_fp16.h>
#include <math.h>
#include <stdint.h>

#define BATCH 4
#define SEQ   2048
#define DM    768
#define NH    12
#define HD    64
#define MROWS (BATCH*SEQ)   // 8192
#define BHT   (BATCH*NH)    // 48

// ---------------- misc helpers ----------------
__device__ __forceinline__ uint32_t s2u(const void* p) {
    uint32_t a;
    asm("{ .reg .u64 t; cvta.to.shared.u64 t, %1; cvt.u32.u64 %0, t; }"
        : "=r"(a) : "l"(p));
    return a;
}
// cp.async 16B (sm_80 PTX)
__device__ __forceinline__ void cpa16(uint32_t dst, const void* src) {
    asm volatile("cp.async.cg.shared.global [%0], [%1], 16;"
                 :: "r"(dst), "l"(src) : "memory");
}
#define CP_COMMIT() asm volatile("cp.async.commit_group;" ::: "memory")
#define CP_WAIT0()  asm volatile("cp.async.wait_group 0;" ::: "memory")

// ---------------- mma.sync helpers (sm_80 PTX, legacy HMMA) ----------------
__device__ __forceinline__ void ldsm_x4(uint32_t* r, uint32_t addr) {
    asm volatile("ldmatrix.sync.aligned.m8n8.x4.shared.b16 {%0,%1,%2,%3}, [%4];"
                 : "=r"(r[0]), "=r"(r[1]), "=r"(r[2]), "=r"(r[3]) : "r"(addr));
}
__device__ __forceinline__ void ldsm_x4t(uint32_t* r, uint32_t addr) {
    asm volatile("ldmatrix.sync.aligned.m8n8.x4.trans.shared.b16 {%0,%1,%2,%3}, [%4];"
                 : "=r"(r[0]), "=r"(r[1]), "=r"(r[2]), "=r"(r[3]) : "r"(addr));
}
// bf16 mma (projection GEMMs, 3-term split)
__device__ __forceinline__ void mma_bf16(float* c, const uint32_t* a, const uint32_t* b) {
    asm volatile(
        "mma.sync.aligned.m16n8k16.row.col.f32.bf16.bf16.f32 "
        "{%0,%1,%2,%3}, {%4,%5,%6,%7}, {%8,%9}, {%0,%1,%2,%3};"
        : "+f"(c[0]), "+f"(c[1]), "+f"(c[2]), "+f"(c[3])
        : "r"(a[0]), "r"(a[1]), "r"(a[2]), "r"(a[3]), "r"(b[0]), "r"(b[1]));
}
// fp16 mma (flash)
__device__ __forceinline__ void mma_f16(float* c, const uint32_t* a, const uint32_t* b) {
    asm volatile(
        "mma.sync.aligned.m16n8k16.row.col.f32.f16.f16.f32 "
        "{%0,%1,%2,%3}, {%4,%5,%6,%7}, {%8,%9}, {%0,%1,%2,%3};"
        : "+f"(c[0]), "+f"(c[1]), "+f"(c[2]), "+f"(c[3])
        : "r"(a[0]), "r"(a[1]), "r"(a[2]), "r"(a[3]), "r"(b[0]), "r"(b[1]));
}
// bf16 split (a,b) -> hi word + residual lo word (low half = a)
__device__ __forceinline__ void split2(float a, float b, uint32_t& h, uint32_t& l) {
    asm("cvt.rn.bf16x2.f32 %0, %1, %2;" : "=r"(h) : "f"(b), "f"(a));
    float ra = a - __uint_as_float(h << 16);
    float rb = b - __uint_as_float(h & 0xffff0000u);
    asm("cvt.rn.bf16x2.f32 %0, %1, %2;" : "=r"(l) : "f"(rb), "f"(ra));
}
__device__ __forceinline__ void cvtsts(float4 v, uint32_t* baseH, uint32_t* baseL, int idx) {
    uint32_t ph0, ph1, pl0, pl1;
    split2(v.x, v.y, ph0, pl0);
    split2(v.z, v.w, ph1, pl1);
    *reinterpret_cast<uint2*>(baseH + idx) = make_uint2(ph0, ph1);
    *reinterpret_cast<uint2*>(baseL + idx) = make_uint2(pl0, pl1);
}
// fp16 pack (low half = a)
__device__ __forceinline__ uint32_t packf16(float a, float b) {
    __half2 h = __floats2half2_rn(a, b);
    return *reinterpret_cast<uint32_t*>(&h);
}
// fp16 split: hi pair + residual pair
__device__ __forceinline__ void splitf16(float a, float b, uint32_t& h, uint32_t& l) {
    __half2 hh = __floats2half2_rn(a, b);
    float2 bk = __half22float2(hh);
    __half2 ll = __floats2half2_rn(a - bk.x, b - bk.y);
    h = *reinterpret_cast<uint32_t*>(&hh);
    l = *reinterpret_cast<uint32_t*>(&ll);
}

// Scratch. Q/K single fp16 pairs (UNSCALED q; 1/8 applied post-MMA in flash).
// V fp16 hi + residual lo. All [b,h,s,d], 32 u32 per row.
__device__ uint32_t g_Qf[(size_t)BHT*SEQ*HD/2];
__device__ uint32_t g_Kf[(size_t)BHT*SEQ*HD/2];
__device__ uint32_t g_Vh[(size_t)BHT*SEQ*HD/2];
__device__ uint32_t g_Vl[(size_t)BHT*SEQ*HD/2];
__device__ float    g_OH[(size_t)MROWS*DM];      // attention out f32, [b,s,h*64+d]

// ---------------------------------------------------------------------------
// bf16-split mma.sync GEMM: C[8192x768] = A @ W. (unchanged core from R8)
// mode 0: -> g_Qf fp16 (unscaled)   mode 1: -> g_Kf fp16
// mode 2: -> g_Vh/g_Vl fp16 hi/lo   mode 3: A=g_OH -> lin_out f32
// ---------------------------------------------------------------------------
__global__ __launch_bounds__(256) void mma_gemm(
    const float* __restrict__ Ain,
    const float* __restrict__ W0, const float* __restrict__ W1,
    const float* __restrict__ W2,
    float* __restrict__ lin_out, int base_mode)
{
    extern __shared__ uint32_t smg[];
    const uint32_t BUFU = 9472;

    int mode = base_mode + blockIdx.z;
    const float* W = (mode == 0) ? W0 : (mode == 1) ? W1 : (mode == 2) ? W2 : W0;
    const float* A = (mode == 3) ? (const float*)g_OH : Ain;

    int tid  = threadIdx.x;
    int wid  = tid >> 5, lane = tid & 31;
    int warpM = wid & 1, warpN = wid >> 1;
    int m0 = blockIdx.y * 128, n0 = blockIdx.x * 128;

    float acc[4][4][4];
    #pragma unroll
    for (int i = 0; i < 4; i++)
        #pragma unroll
        for (int j = 0; j < 4; j++)
            #pragma unroll
            for (int k = 0; k < 4; k++) acc[i][j][k] = 0.f;

    uint32_t sbg = s2u(smg);
    uint32_t aLane = (uint32_t)((lane & 15) * 80 + (lane >> 4) * 16 + warpM * 5120);
    uint32_t bLane = (uint32_t)((lane & 15) * 272 + (lane >> 4) * 16 + warpN * 64);

    float4 av[4], bv[4];
    #pragma unroll
    for (int it = 0; it < 4; it++) {
        int i = tid + it * 256;
        int r = i >> 3, c4 = (i & 7) * 4;
        av[it] = *reinterpret_cast<const float4*>(A + (size_t)(m0 + r) * DM + c4);
        int rb = i >> 5, cb = (i & 31) * 4;
        bv[it] = *reinterpret_cast<const float4*>(W + (size_t)rb * DM + n0 + cb);
    }
    #pragma unroll
    for (int it = 0; it < 4; it++) {
        int i = tid + it * 256;
        int r = i >> 3, c4 = (i & 7) * 4;
        cvtsts(av[it], smg, smg + 2560, r * 20 + (c4 >> 1));
        int rb = i >> 5, cb = (i & 31) * 4;
        cvtsts(bv[it], smg + 5120, smg + 7296, rb * 68 + (cb >> 1));
    }
    #pragma unroll
    for (int it = 0; it < 4; it++) {
        int i = tid + it * 256;
        int r = i >> 3, c4 = (i & 7) * 4;
        av[it] = *reinterpret_cast<const float4*>(A + (size_t)(m0 + r) * DM + 32 + c4);
        int rb = i >> 5, cb = (i & 31) * 4;
        bv[it] = *reinterpret_cast<const float4*>(W + (size_t)(32 + rb) * DM + n0 + cb);
    }
    __syncthreads();

    for (int c = 0; c < 24; c++) {
        if (c < 23) {
            uint32_t* base = smg + ((c + 1) & 1) * BUFU;
            #pragma unroll
            for (int it = 0; it < 4; it++) {
                int i = tid + it * 256;
                int r = i >> 3, c4 = (i & 7) * 4;
                cvtsts(av[it], base, base + 2560, r * 20 + (c4 >> 1));
                int rb = i >> 5, cb = (i & 31) * 4;
                cvtsts(bv[it], base + 5120, base + 7296, rb * 68 + (cb >> 1));
            }
        }
        if (c < 22) {
            int k0n = (c + 2) * 32;
            #pragma unroll
            for (int it = 0; it < 4; it++) {
                int i = tid + it * 256;
                int r = i >> 3, c4 = (i & 7) * 4;
                av[it] = *reinterpret_cast<const float4*>(
                    A + (size_t)(m0 + r) * DM + k0n + c4);
                int rb = i >> 5, cb = (i & 31) * 4;
                bv[it] = *reinterpret_cast<const float4*>(
                    W + (size_t)(k0n + rb) * DM + n0 + cb);
            }
        }
        uint32_t off = sbg + (uint32_t)(c & 1) * (BUFU * 4);
        uint32_t aH = off, aL = off + 10240, bH = off + 20480, bL = off + 29184;
        #pragma unroll
        for (int ks = 0; ks < 2; ks++) {
            uint32_t bh[4][2], bl[4][2];
            #pragma unroll
            for (int np = 0; np < 2; np++) {
                uint32_t r4[4];
                ldsm_x4t(r4, bH + bLane + ks * 4352 + np * 32);
                bh[np*2][0] = r4[0]; bh[np*2][1] = r4[1];
                bh[np*2+1][0] = r4[2]; bh[np*2+1][1] = r4[3];
                ldsm_x4t(r4, bL + bLane + ks * 4352 + np * 32);
                bl[np*2][0] = r4[0]; bl[np*2][1] = r4[1];
                bl[np*2+1][0] = r4[2]; bl[np*2+1][1] = r4[3];
            }
            #pragma unroll
            for (int mtp = 0; mtp < 2; mtp++) {
                uint32_t a0h[4], a0l[4], a1h[4], a1l[4];
                ldsm_x4(a0h, aH + aLane + (2*mtp) * 1280 + ks * 32);
                ldsm_x4(a1h, aH + aLane + (2*mtp+1) * 1280 + ks * 32);
                ldsm_x4(a0l, aL + aLane + (2*mtp) * 1280 + ks * 32);
                ldsm_x4(a1l, aL + aLane + (2*mtp+1) * 1280 + ks * 32);
                #pragma unroll
                for (int nt = 0; nt < 4; nt++) mma_bf16(acc[2*mtp][nt],   a0h, bh[nt]);
                #pragma unroll
                for (int nt = 0; nt < 4; nt++) mma_bf16(acc[2*mtp+1][nt], a1h, bh[nt]);
                #pragma unroll
                for (int nt = 0; nt < 4; nt++) mma_bf16(acc[2*mtp][nt],   a0h, bl[nt]);
                #pragma unroll
                for (int nt = 0; nt < 4; nt++) mma_bf16(acc[2*mtp+1][nt], a1h, bl[nt]);
                #pragma unroll
                for (int nt = 0; nt < 4; nt++) mma_bf16(acc[2*mtp][nt],   a0l, bh[nt]);
                #pragma unroll
                for (int nt = 0; nt < 4; nt++) mma_bf16(acc[2*mtp+1][nt], a1l, bh[nt]);
            }
        }
        __syncthreads();
    }

    int rl = lane >> 2, cl = (lane & 3) * 2;
    if (mode == 3) {
        #pragma unroll
        for (int mt = 0; mt < 4; mt++) {
            int m = m0 + warpM * 64 + mt * 16 + rl;
            #pragma unroll
            for (int nt = 0; nt < 4; nt++) {
                int n = n0 + warpN * 32 + nt * 8 + cl;
                *reinterpret_cast<float2*>(lin_out + (size_t)m * DM + n) =
                    make_float2(acc[mt][nt][0], acc[mt][nt][1]);
                *reinterpret_cast<float2*>(lin_out + (size_t)(m + 8) * DM + n) =
                    make_float2(acc[mt][nt][2], acc[mt][nt][3]);
            }
        }
    } else if (mode == 2) {
        #pragma unroll
        for (int mt = 0; mt < 4; mt++) {
            int m = m0 + warpM * 64 + mt * 16 + rl;
            int b = m >> 11, s = m & 2047;
            #pragma unroll
            for (int nt = 0; nt < 4; nt++) {
                int n = n0 + warpN * 32 + nt * 8 + cl;
                int h = n >> 6, d = n & 63;
                size_t base = ((size_t)(b * NH + h) * SEQ + s) * 32 + (d >> 1);
                uint32_t hi, lo;
                splitf16(acc[mt][nt][0], acc[mt][nt][1], hi, lo);
                g_Vh[base] = hi; g_Vl[base] = lo;
                splitf16(acc[mt][nt][2], acc[mt][nt][3], hi, lo);
                g_Vh[base + 8 * 32] = hi; g_Vl[base + 8 * 32] = lo;
            }
        }
    } else {
        uint32_t* dst = (mode == 0) ? g_Qf : g_Kf;
        #pragma unroll
        for (int mt = 0; mt < 4; mt++) {
            int m = m0 + warpM * 64 + mt * 16 + rl;
            int b = m >> 11, s = m & 2047;
            #pragma unroll
            for (int nt = 0; nt < 4; nt++) {
                int n = n0 + warpN * 32 + nt * 8 + cl;
                int h = n >> 6, d = n & 63;
                size_t base = ((size_t)(b * NH + h) * SEQ + s) * 32 + (d >> 1);
                dst[base] = packf16(acc[mt][nt][0], acc[mt][nt][1]);
                dst[base + 8 * 32] = packf16(acc[mt][nt][2], acc[mt][nt][3]);
            }
        }
    }
}

// ---------------------------------------------------------------------------
// Flash attention, fp16 path: S = Qf.Kf^T single-term (x0.125 post-MMA),
// P single fp16, O += P.(Vh + Vl) 2-term. Double-buffered K/V/kmask,
// one sync + one wait per tile. 74KB smem -> 2 CTAs/SM.
// ---------------------------------------------------------------------------
__global__ __launch_bounds__(256, 2) void flash_mma(
    const float* __restrict__ q_mask, float* __restrict__ logits)
{
    extern __shared__ uint32_t sm32[];
    uint32_t sb = s2u(sm32);
    // byte offsets, rows padded to 144B (128B data + 16 pad)
    const uint32_t oQ = 0;                                   // 128 x 144
    const uint32_t oK[2]  = {18432u, 27648u};                // 64 x 144 each
    const uint32_t oVH[2] = {36864u, 46080u};
    const uint32_t oVL[2] = {55296u, 64512u};
    const uint32_t oKM[2] = {73728u, 73984u};

    int bh = blockIdx.y;
    int b  = bh / NH;
    int h  = bh - b * NH;
    int q0 = blockIdx.x * 128;
    int tid = threadIdx.x;
    int w = tid >> 5, lane = tid & 31;
    int rq = lane >> 2, cq = lane & 3;

    // prologue: Q + tile-0 K/V/km, one commit group
    #pragma unroll
    for (int it = 0; it < 4; it++) {
        int i = tid + it * 256;
        int r = i >> 3, ch = i & 7;
        size_t src = ((size_t)(bh * SEQ + q0 + r)) * 32 + ch * 4;
        cpa16(sb + oQ + r * 144 + ch * 16, g_Qf + src);
    }
    #pragma unroll
    for (int it = 0; it < 2; it++) {
        int i = tid + it * 256;
        int r = i >> 3, ch = i & 7;
        size_t src = ((size_t)(bh * SEQ + r)) * 32 + ch * 4;
        cpa16(sb + oK[0]  + r * 144 + ch * 16, g_Kf + src);
        cpa16(sb + oVH[0] + r * 144 + ch * 16, g_Vh + src);
        cpa16(sb + oVL[0] + r * 144 + ch * 16, g_Vl + src);
    }
    if (tid < 16)
        cpa16(sb + oKM[0] + tid * 16, q_mask + (size_t)b * SEQ + tid * 4);
    CP_COMMIT();

    int rowA = 16 * w + rq;
    float qmA = q_mask[(size_t)b * SEQ + q0 + rowA];
    float qmB = q_mask[(size_t)b * SEQ + q0 + rowA + 8];
    float mA = -3.0e38f, mB = -3.0e38f, sA = 0.f, sB = 0.f;
    float o[8][4];
    #pragma unroll
    for (int i = 0; i < 8; i++)
        #pragma unroll
        for (int j = 0; j < 4; j++) o[i][j] = 0.f;
    uint32_t qh[4][4];

    float* LA = logits + ((size_t)bh * SEQ + q0 + rowA) * SEQ + 2 * cq;
    float* LB = LA + (size_t)8 * SEQ;

    for (int t = 0; t < 32; t++) {
        int k0 = t * 64;
        int bi = t & 1;
        CP_WAIT0();
        __syncthreads();

        if (t == 0) {
            uint32_t qoff = (uint32_t)((16 * w + (lane & 15)) * 144 + (lane >> 4) * 16);
            #pragma unroll
            for (int ks = 0; ks < 4; ks++)
                ldsm_x4(qh[ks], sb + oQ + qoff + ks * 32);
        }
        if (t + 1 < 32) {
            int nb = (t + 1) & 1;
            int k1 = k0 + 64;
            #pragma unroll
            for (int it = 0; it < 2; it++) {
                int i = tid + it * 256;
                int r = i >> 3, ch = i & 7;
                size_t src = ((size_t)(bh * SEQ + k1 + r)) * 32 + ch * 4;
                cpa16(sb + oK[nb]  + r * 144 + ch * 16, g_Kf + src);
                cpa16(sb + oVH[nb] + r * 144 + ch * 16, g_Vh + src);
                cpa16(sb + oVL[nb] + r * 144 + ch * 16, g_Vl + src);
            }
            if (tid < 16)
                cpa16(sb + oKM[nb] + tid * 16, q_mask + (size_t)b * SEQ + k1 + tid * 4);
            CP_COMMIT();
        }

        // ---- S = Q.K^T (single fp16 term, 8 distinct accs per pass) ----
        uint32_t kb = sb + oK[bi];
        float s[8][4];
        #pragma unroll
        for (int i = 0; i < 8; i++)
            #pragma unroll
            for (int j = 0; j < 4; j++) s[i][j] = 0.f;
        #pragma unroll
        for (int ks = 0; ks < 4; ks++) {
            uint32_t kf[4][4];
            #pragma unroll
            for (int g = 0; g < 4; g++) {
                uint32_t koff = (uint32_t)((16 * g + (lane & 15)) * 144
                                           + (lane >> 4) * 16 + ks * 32);
                ldsm_x4(kf[g], kb + koff);
            }
            #pragma unroll
            for (int g = 0; g < 4; g++) { uint32_t b2[2] = {kf[g][0], kf[g][2]}; mma_f16(s[2*g],   qh[ks], b2); }
            #pragma unroll
            for (int g = 0; g < 4; g++) { uint32_t b2[2] = {kf[g][1], kf[g][3]}; mma_f16(s[2*g+1], qh[ks], b2); }
        }

        // scale by 1/8 (deferred q scaling), write raw logits
        #pragma unroll
        for (int j = 0; j < 8; j++) {
            s[j][0] *= 0.125f; s[j][1] *= 0.125f;
            s[j][2] *= 0.125f; s[j][3] *= 0.125f;
            *reinterpret_cast<float2*>(LA + k0 + 8 * j) = make_float2(s[j][0], s[j][1]);
            *reinterpret_cast<float2*>(LB + k0 + 8 * j) = make_float2(s[j][2], s[j][3]);
        }

        // ---- mask + online softmax (cancellation-free) ----
        const float* smKM = reinterpret_cast<const float*>(
            reinterpret_cast<const char*>(sm32) + oKM[bi]);
        float mxA = -3.0e38f, mxB = -3.0e38f;
        #pragma unroll
        for (int j = 0; j < 8; j++) {
            float km0 = smKM[8 * j + 2 * cq], km1 = smKM[8 * j + 2 * cq + 1];
            float uA0 = 1.0f - qmA * km0, uA1 = 1.0f - qmA * km1;
            float uB0 = 1.0f - qmB * km0, uB1 = 1.0f - qmB * km1;
            s[j][0] = fmaf(-1e5f, uA0, s[j][0]);
            s[j][1] = fmaf(-1e5f, uA1, s[j][1]);
            s[j][2] = fmaf(-1e5f, uB0, s[j][2]);
            s[j][3] = fmaf(-1e5f, uB1, s[j][3]);
            mxA = fmaxf(mxA, fmaxf(s[j][0], s[j][1]));
            mxB = fmaxf(mxB, fmaxf(s[j][2], s[j][3]));
        }
        mxA = fmaxf(mxA, __shfl_xor_sync(0xffffffffu, mxA, 1));
        mxA = fmaxf(mxA, __shfl_xor_sync(0xffffffffu, mxA, 2));
        mxB = fmaxf(mxB, __shfl_xor_sync(0xffffffffu, mxB, 1));
        mxB = fmaxf(mxB, __shfl_xor_sync(0xffffffffu, mxB, 2));
        float mnA = fmaxf(mA, mxA), mnB = fmaxf(mB, mxB);
        float rsA = __expf(mA - mnA), rsB = __expf(mB - mnB);
        mA = mnA; mB = mnB;
        sA *= rsA; sB *= rsB;
        #pragma unroll
        for (int j = 0; j < 8; j++) {
            s[j][0] = __expf(s[j][0] - mnA);
            s[j][1] = __expf(s[j][1] - mnA);
            s[j][2] = __expf(s[j][2] - mnB);
            s[j][3] = __expf(s[j][3] - mnB);
            sA += s[j][0] + s[j][1];
            sB += s[j][2] + s[j][3];
        }
        #pragma unroll
        for (int dt = 0; dt < 8; dt++) {
            o[dt][0] *= rsA; o[dt][1] *= rsA;
            o[dt][2] *= rsB; o[dt][3] *= rsB;
        }

        // ---- O += P.V (P single fp16, V hi + lo) ----
        uint32_t vbH = sb + oVH[bi], vbL = sb + oVL[bi];
        #pragma unroll
        for (int ks = 0; ks < 4; ks++) {
            uint32_t pa[4];
            pa[0] = packf16(s[2*ks][0],   s[2*ks][1]);
            pa[1] = packf16(s[2*ks][2],   s[2*ks][3]);
            pa[2] = packf16(s[2*ks+1][0], s[2*ks+1][1]);
            pa[3] = packf16(s[2*ks+1][2], s[2*ks+1][3]);
            uint32_t vf[4][4], wf[4][4];
            #pragma unroll
            for (int dg = 0; dg < 4; dg++) {
                uint32_t voff = (uint32_t)((16 * ks + (lane & 15)) * 144
                                           + (lane >> 4) * 16 + dg * 32);
                ldsm_x4t(vf[dg], vbH + voff);
                ldsm_x4t(wf[dg], vbL + voff);
            }
            #pragma unroll
            for (int dg = 0; dg < 4; dg++) { uint32_t b2[2] = {vf[dg][0], vf[dg][1]}; mma_f16(o[2*dg],   pa, b2); }
            #pragma unroll
            for (int dg = 0; dg < 4; dg++) { uint32_t b2[2] = {vf[dg][2], vf[dg][3]}; mma_f16(o[2*dg+1], pa, b2); }
            #pragma unroll
            for (int dg = 0; dg < 4; dg++) { uint32_t b2[2] = {wf[dg][0], wf[dg][1]}; mma_f16(o[2*dg],   pa, b2); }
            #pragma unroll
            for (int dg = 0; dg < 4; dg++) { uint32_t b2[2] = {wf[dg][2], wf[dg][3]}; mma_f16(o[2*dg+1], pa, b2); }
        }
    }

    // final sum reduce + normalize + store
    sA += __shfl_xor_sync(0xffffffffu, sA, 1);
    sA += __shfl_xor_sync(0xffffffffu, sA, 2);
    sB += __shfl_xor_sync(0xffffffffu, sB, 1);
    sB += __shfl_xor_sync(0xffffffffu, sB, 2);
    float invA = 1.0f / sA, invB = 1.0f / sB;
    float* OA = g_OH + ((size_t)b * SEQ + q0 + rowA) * DM + h * HD + 2 * cq;
    float* OB = OA + (size_t)8 * DM;
    #pragma unroll
    for (int dt = 0; dt < 8; dt++) {
        *reinterpret_cast<float2*>(OA + 8 * dt) =
            make_float2(o[dt][0] * invA, o[dt][1] * invA);
        *reinterpret_cast<float2*>(OB + 8 * dt) =
            make_float2(o[dt][2] * invB, o[dt][3] * invB);
    }
}

// ---------------------------------------------------------------------------
// Launch. Output: [out (4*2048*768)] then [logits_raw (48*2048*2048)]
// ---------------------------------------------------------------------------
extern "C" void kernel_launch(void* const* d_in, const int* in_sizes, int n_in,
                              void* d_out, int out_size)
{
    const float* x  = (const float*)d_in[0];
    const float* qm = (const float*)d_in[1];
    const float* Wq = (const float*)d_in[2];
    const float* Wk = (const float*)d_in[3];
    const float* Wv = (const float*)d_in[4];
    const float* Wo = (const float*)d_in[5];

    float* out    = (float*)d_out;
    float* logits = out + (size_t)MROWS * DM;

    const int GEMM_SMEM  = 75776;   // 2 x 9472 u32
    const int FLASH_SMEM = 74240;
    cudaFuncSetAttribute(mma_gemm,
                         cudaFuncAttributeMaxDynamicSharedMemorySize, GEMM_SMEM);
    cudaFuncSetAttribute(flash_mma,
                         cudaFuncAttributeMaxDynamicSharedMemorySize, FLASH_SMEM);

    mma_gemm <<<dim3(6, 64, 3), 256, GEMM_SMEM>>>(x, Wq, Wk, Wv, nullptr, 0);
    flash_mma<<<dim3(16, 48), 256, FLASH_SMEM>>>(qm, logits);
    mma_gemm <<<dim3(6, 64, 1), 256, GEMM_SMEM>>>(nullptr, Wo, Wo, Wo, out, 3);
}

// round 10
// speedup vs baseline: 8.0559x; 1.1354x over previous
#include <cuda_runtime.h>
#include <cuda_fp16.h>
#include <math.h>
#include <stdint.h>

#define BATCH 4
#define SEQ   2048
#define DM    768
#define NH    12
#define HD    64
#define MROWS (BATCH*SEQ)   // 8192
#define BHT   (BATCH*NH)    // 48

// ---------------- misc helpers ----------------
__device__ __forceinline__ uint32_t s2u(const void* p) {
    uint32_t a;
    asm("{ .reg .u64 t; cvta.to.shared.u64 t, %1; cvt.u32.u64 %0, t; }"
        : "=r"(a) : "l"(p));
    return a;
}
// cp.async 16B (sm_80 PTX)
__device__ __forceinline__ void cpa16(uint32_t dst, const void* src) {
    asm volatile("cp.async.cg.shared.global [%0], [%1], 16;"
                 :: "r"(dst), "l"(src) : "memory");
}
#define CP_COMMIT() asm volatile("cp.async.commit_group;" ::: "memory")
#define CP_WAIT0()  asm volatile("cp.async.wait_group 0;" ::: "memory")

// ---------------- mma.sync helpers (sm_80 PTX, legacy HMMA) ----------------
__device__ __forceinline__ void ldsm_x4(uint32_t* r, uint32_t addr) {
    asm volatile("ldmatrix.sync.aligned.m8n8.x4.shared.b16 {%0,%1,%2,%3}, [%4];"
                 : "=r"(r[0]), "=r"(r[1]), "=r"(r[2]), "=r"(r[3]) : "r"(addr));
}
__device__ __forceinline__ void ldsm_x4t(uint32_t* r, uint32_t addr) {
    asm volatile("ldmatrix.sync.aligned.m8n8.x4.trans.shared.b16 {%0,%1,%2,%3}, [%4];"
                 : "=r"(r[0]), "=r"(r[1]), "=r"(r[2]), "=r"(r[3]) : "r"(addr));
}
// bf16 mma (projection GEMMs, 3-term split)
__device__ __forceinline__ void mma_bf16(float* c, const uint32_t* a, const uint32_t* b) {
    asm volatile(
        "mma.sync.aligned.m16n8k16.row.col.f32.bf16.bf16.f32 "
        "{%0,%1,%2,%3}, {%4,%5,%6,%7}, {%8,%9}, {%0,%1,%2,%3};"
        : "+f"(c[0]), "+f"(c[1]), "+f"(c[2]), "+f"(c[3])
        : "r"(a[0]), "r"(a[1]), "r"(a[2]), "r"(a[3]), "r"(b[0]), "r"(b[1]));
}
// fp16 mma (flash)
__device__ __forceinline__ void mma_f16(float* c, const uint32_t* a, const uint32_t* b) {
    asm volatile(
        "mma.sync.aligned.m16n8k16.row.col.f32.f16.f16.f32 "
        "{%0,%1,%2,%3}, {%4,%5,%6,%7}, {%8,%9}, {%0,%1,%2,%3};"
        : "+f"(c[0]), "+f"(c[1]), "+f"(c[2]), "+f"(c[3])
        : "r"(a[0]), "r"(a[1]), "r"(a[2]), "r"(a[3]), "r"(b[0]), "r"(b[1]));
}
// bf16 split (a,b) -> hi word + residual lo word (low half = a)
__device__ __forceinline__ void split2(float a, float b, uint32_t& h, uint32_t& l) {
    asm("cvt.rn.bf16x2.f32 %0, %1, %2;" : "=r"(h) : "f"(b), "f"(a));
    float ra = a - __uint_as_float(h << 16);
    float rb = b - __uint_as_float(h & 0xffff0000u);
    asm("cvt.rn.bf16x2.f32 %0, %1, %2;" : "=r"(l) : "f"(rb), "f"(ra));
}
__device__ __forceinline__ void cvtsts(float4 v, uint32_t* baseH, uint32_t* baseL, int idx) {
    uint32_t ph0, ph1, pl0, pl1;
    split2(v.x, v.y, ph0, pl0);
    split2(v.z, v.w, ph1, pl1);
    *reinterpret_cast<uint2*>(baseH + idx) = make_uint2(ph0, ph1);
    *reinterpret_cast<uint2*>(baseL + idx) = make_uint2(pl0, pl1);
}
// fp16 pack (low half = a)
__device__ __forceinline__ uint32_t packf16(float a, float b) {
    __half2 h = __floats2half2_rn(a, b);
    return *reinterpret_cast<uint32_t*>(&h);
}

// Scratch. Q/K/V single fp16 pairs (UNSCALED q; 1/8 applied post-MMA in flash).
// All [b,h,s,d], 32 u32 per row.
__device__ uint32_t g_Qf[(size_t)BHT*SEQ*HD/2];
__device__ uint32_t g_Kf[(size_t)BHT*SEQ*HD/2];
__device__ uint32_t g_Vf[(size_t)BHT*SEQ*HD/2];
__device__ float    g_OH[(size_t)MROWS*DM];      // attention out f32, [b,s,h*64+d]

// ---------------------------------------------------------------------------
// bf16-split mma.sync GEMM: C[8192x768] = A @ W. (unchanged core from R9)
// mode 0: -> g_Qf fp16 (unscaled)   mode 1: -> g_Kf fp16
// mode 2: -> g_Vf fp16              mode 3: A=g_OH -> lin_out f32
// ---------------------------------------------------------------------------
__global__ __launch_bounds__(256) void mma_gemm(
    const float* __restrict__ Ain,
    const float* __restrict__ W0, const float* __restrict__ W1,
    const float* __restrict__ W2,
    float* __restrict__ lin_out, int base_mode)
{
    extern __shared__ uint32_t smg[];
    const uint32_t BUFU = 9472;

    int mode = base_mode + blockIdx.z;
    const float* W = (mode == 0) ? W0 : (mode == 1) ? W1 : (mode == 2) ? W2 : W0;
    const float* A = (mode == 3) ? (const float*)g_OH : Ain;

    int tid  = threadIdx.x;
    int wid  = tid >> 5, lane = tid & 31;
    int warpM = wid & 1, warpN = wid >> 1;
    int m0 = blockIdx.y * 128, n0 = blockIdx.x * 128;

    float acc[4][4][4];
    #pragma unroll
    for (int i = 0; i < 4; i++)
        #pragma unroll
        for (int j = 0; j < 4; j++)
            #pragma unroll
            for (int k = 0; k < 4; k++) acc[i][j][k] = 0.f;

    uint32_t sbg = s2u(smg);
    uint32_t aLane = (uint32_t)((lane & 15) * 80 + (lane >> 4) * 16 + warpM * 5120);
    uint32_t bLane = (uint32_t)((lane & 15) * 272 + (lane >> 4) * 16 + warpN * 64);

    float4 av[4], bv[4];
    #pragma unroll
    for (int it = 0; it < 4; it++) {
        int i = tid + it * 256;
        int r = i >> 3, c4 = (i & 7) * 4;
        av[it] = *reinterpret_cast<const float4*>(A + (size_t)(m0 + r) * DM + c4);
        int rb = i >> 5, cb = (i & 31) * 4;
        bv[it] = *reinterpret_cast<const float4*>(W + (size_t)rb * DM + n0 + cb);
    }
    #pragma unroll
    for (int it = 0; it < 4; it++) {
        int i = tid + it * 256;
        int r = i >> 3, c4 = (i & 7) * 4;
        cvtsts(av[it], smg, smg + 2560, r * 20 + (c4 >> 1));
        int rb = i >> 5, cb = (i & 31) * 4;
        cvtsts(bv[it], smg + 5120, smg + 7296, rb * 68 + (cb >> 1));
    }
    #pragma unroll
    for (int it = 0; it < 4; it++) {
        int i = tid + it * 256;
        int r = i >> 3, c4 = (i & 7) * 4;
        av[it] = *reinterpret_cast<const float4*>(A + (size_t)(m0 + r) * DM + 32 + c4);
        int rb = i >> 5, cb = (i & 31) * 4;
        bv[it] = *reinterpret_cast<const float4*>(W + (size_t)(32 + rb) * DM + n0 + cb);
    }
    __syncthreads();

    for (int c = 0; c < 24; c++) {
        if (c < 23) {
            uint32_t* base = smg + ((c + 1) & 1) * BUFU;
            #pragma unroll
            for (int it = 0; it < 4; it++) {
                int i = tid + it * 256;
                int r = i >> 3, c4 = (i & 7) * 4;
                cvtsts(av[it], base, base + 2560, r * 20 + (c4 >> 1));
                int rb = i >> 5, cb = (i & 31) * 4;
                cvtsts(bv[it], base + 5120, base + 7296, rb * 68 + (cb >> 1));
            }
        }
        if (c < 22) {
            int k0n = (c + 2) * 32;
            #pragma unroll
            for (int it = 0; it < 4; it++) {
                int i = tid + it * 256;
                int r = i >> 3, c4 = (i & 7) * 4;
                av[it] = *reinterpret_cast<const float4*>(
                    A + (size_t)(m0 + r) * DM + k0n + c4);
                int rb = i >> 5, cb = (i & 31) * 4;
                bv[it] = *reinterpret_cast<const float4*>(
                    W + (size_t)(k0n + rb) * DM + n0 + cb);
            }
        }
        uint32_t off = sbg + (uint32_t)(c & 1) * (BUFU * 4);
        uint32_t aH = off, aL = off + 10240, bH = off + 20480, bL = off + 29184;
        #pragma unroll
        for (int ks = 0; ks < 2; ks++) {
            uint32_t bh[4][2], bl[4][2];
            #pragma unroll
            for (int np = 0; np < 2; np++) {
                uint32_t r4[4];
                ldsm_x4t(r4, bH + bLane + ks * 4352 + np * 32);
                bh[np*2][0] = r4[0]; bh[np*2][1] = r4[1];
                bh[np*2+1][0] = r4[2]; bh[np*2+1][1] = r4[3];
                ldsm_x4t(r4, bL + bLane + ks * 4352 + np * 32);
                bl[np*2][0] = r4[0]; bl[np*2][1] = r4[1];
                bl[np*2+1][0] = r4[2]; bl[np*2+1][1] = r4[3];
            }
            #pragma unroll
            for (int mtp = 0; mtp < 2; mtp++) {
                uint32_t a0h[4], a0l[4], a1h[4], a1l[4];
                ldsm_x4(a0h, aH + aLane + (2*mtp) * 1280 + ks * 32);
                ldsm_x4(a1h, aH + aLane + (2*mtp+1) * 1280 + ks * 32);
                ldsm_x4(a0l, aL + aLane + (2*mtp) * 1280 + ks * 32);
                ldsm_x4(a1l, aL + aLane + (2*mtp+1) * 1280 + ks * 32);
                #pragma unroll
                for (int nt = 0; nt < 4; nt++) mma_bf16(acc[2*mtp][nt],   a0h, bh[nt]);
                #pragma unroll
                for (int nt = 0; nt < 4; nt++) mma_bf16(acc[2*mtp+1][nt], a1h, bh[nt]);
                #pragma unroll
                for (int nt = 0; nt < 4; nt++) mma_bf16(acc[2*mtp][nt],   a0h, bl[nt]);
                #pragma unroll
                for (int nt = 0; nt < 4; nt++) mma_bf16(acc[2*mtp+1][nt], a1h, bl[nt]);
                #pragma unroll
                for (int nt = 0; nt < 4; nt++) mma_bf16(acc[2*mtp][nt],   a0l, bh[nt]);
                #pragma unroll
                for (int nt = 0; nt < 4; nt++) mma_bf16(acc[2*mtp+1][nt], a1l, bh[nt]);
            }
        }
        __syncthreads();
    }

    int rl = lane >> 2, cl = (lane & 3) * 2;
    if (mode == 3) {
        #pragma unroll
        for (int mt = 0; mt < 4; mt++) {
            int m = m0 + warpM * 64 + mt * 16 + rl;
            #pragma unroll
            for (int nt = 0; nt < 4; nt++) {
                int n = n0 + warpN * 32 + nt * 8 + cl;
                *reinterpret_cast<float2*>(lin_out + (size_t)m * DM + n) =
                    make_float2(acc[mt][nt][0], acc[mt][nt][1]);
                *reinterpret_cast<float2*>(lin_out + (size_t)(m + 8) * DM + n) =
                    make_float2(acc[mt][nt][2], acc[mt][nt][3]);
            }
        }
    } else {
        uint32_t* dst = (mode == 0) ? g_Qf : (mode == 1) ? g_Kf : g_Vf;
        #pragma unroll
        for (int mt = 0; mt < 4; mt++) {
            int m = m0 + warpM * 64 + mt * 16 + rl;
            int b = m >> 11, s = m & 2047;
            #pragma unroll
            for (int nt = 0; nt < 4; nt++) {
                int n = n0 + warpN * 32 + nt * 8 + cl;
                int h = n >> 6, d = n & 63;
                size_t base = ((size_t)(b * NH + h) * SEQ + s) * 32 + (d >> 1);
                dst[base] = packf16(acc[mt][nt][0], acc[mt][nt][1]);
                dst[base + 8 * 32] = packf16(acc[mt][nt][2], acc[mt][nt][3]);
            }
        }
    }
}

// ---------------------------------------------------------------------------
// Flash attention, fp16 path: S = Qf.Kf^T single-term (x0.125 post-MMA),
// P single fp16, O += P.V with single-fp16 V. Double-buffered K/V/kmask,
// one sync + one wait per tile. ~56KB smem.
// ---------------------------------------------------------------------------
__global__ __launch_bounds__(256, 2) void flash_mma(
    const float* __restrict__ q_mask, float* __restrict__ logits)
{
    extern __shared__ uint32_t sm32[];
    uint32_t sb = s2u(sm32);
    // byte offsets, rows padded to 144B (128B data + 16 pad)
    const uint32_t oQ = 0;                                   // 128 x 144
    const uint32_t oK[2]  = {18432u, 27648u};                // 64 x 144 each
    const uint32_t oV[2]  = {36864u, 46080u};
    const uint32_t oKM[2] = {55296u, 55552u};

    int bh = blockIdx.y;
    int b  = bh / NH;
    int h  = bh - b * NH;
    int q0 = blockIdx.x * 128;
    int tid = threadIdx.x;
    int w = tid >> 5, lane = tid & 31;
    int rq = lane >> 2, cq = lane & 3;

    // prologue: Q + tile-0 K/V/km, one commit group
    #pragma unroll
    for (int it = 0; it < 4; it++) {
        int i = tid + it * 256;
        int r = i >> 3, ch = i & 7;
        size_t src = ((size_t)(bh * SEQ + q0 + r)) * 32 + ch * 4;
        cpa16(sb + oQ + r * 144 + ch * 16, g_Qf + src);
    }
    #pragma unroll
    for (int it = 0; it < 2; it++) {
        int i = tid + it * 256;
        int r = i >> 3, ch = i & 7;
        size_t src = ((size_t)(bh * SEQ + r)) * 32 + ch * 4;
        cpa16(sb + oK[0] + r * 144 + ch * 16, g_Kf + src);
        cpa16(sb + oV[0] + r * 144 + ch * 16, g_Vf + src);
    }
    if (tid < 16)
        cpa16(sb + oKM[0] + tid * 16, q_mask + (size_t)b * SEQ + tid * 4);
    CP_COMMIT();

    int rowA = 16 * w + rq;
    float qmA = q_mask[(size_t)b * SEQ + q0 + rowA];
    float qmB = q_mask[(size_t)b * SEQ + q0 + rowA + 8];
    float mA = -3.0e38f, mB = -3.0e38f, sA = 0.f, sB = 0.f;
    float o[8][4];
    #pragma unroll
    for (int i = 0; i < 8; i++)
        #pragma unroll
        for (int j = 0; j < 4; j++) o[i][j] = 0.f;
    uint32_t qh[4][4];

    float* LA = logits + ((size_t)bh * SEQ + q0 + rowA) * SEQ + 2 * cq;
    float* LB = LA + (size_t)8 * SEQ;

    for (int t = 0; t < 32; t++) {
        int k0 = t * 64;
        int bi = t & 1;
        CP_WAIT0();
        __syncthreads();

        if (t == 0) {
            uint32_t qoff = (uint32_t)((16 * w + (lane & 15)) * 144 + (lane >> 4) * 16);
            #pragma unroll
            for (int ks = 0; ks < 4; ks++)
                ldsm_x4(qh[ks], sb + oQ + qoff + ks * 32);
        }
        if (t + 1 < 32) {
            int nb = (t + 1) & 1;
            int k1 = k0 + 64;
            #pragma unroll
            for (int it = 0; it < 2; it++) {
                int i = tid + it * 256;
                int r = i >> 3, ch = i & 7;
                size_t src = ((size_t)(bh * SEQ + k1 + r)) * 32 + ch * 4;
                cpa16(sb + oK[nb] + r * 144 + ch * 16, g_Kf + src);
                cpa16(sb + oV[nb] + r * 144 + ch * 16, g_Vf + src);
            }
            if (tid < 16)
                cpa16(sb + oKM[nb] + tid * 16, q_mask + (size_t)b * SEQ + k1 + tid * 4);
            CP_COMMIT();
        }

        // ---- S = Q.K^T (single fp16 term, 8 distinct accs per pass) ----
        uint32_t kb = sb + oK[bi];
        float s[8][4];
        #pragma unroll
        for (int i = 0; i < 8; i++)
            #pragma unroll
            for (int j = 0; j < 4; j++) s[i][j] = 0.f;
        #pragma unroll
        for (int ks = 0; ks < 4; ks++) {
            uint32_t kf[4][4];
            #pragma unroll
            for (int g = 0; g < 4; g++) {
                uint32_t koff = (uint32_t)((16 * g + (lane & 15)) * 144
                                           + (lane >> 4) * 16 + ks * 32);
                ldsm_x4(kf[g], kb + koff);
            }
            #pragma unroll
            for (int g = 0; g < 4; g++) { uint32_t b2[2] = {kf[g][0], kf[g][2]}; mma_f16(s[2*g],   qh[ks], b2); }
            #pragma unroll
            for (int g = 0; g < 4; g++) { uint32_t b2[2] = {kf[g][1], kf[g][3]}; mma_f16(s[2*g+1], qh[ks], b2); }
        }

        // scale by 1/8 (deferred q scaling), write raw logits
        #pragma unroll
        for (int j = 0; j < 8; j++) {
            s[j][0] *= 0.125f; s[j][1] *= 0.125f;
            s[j][2] *= 0.125f; s[j][3] *= 0.125f;
            *reinterpret_cast<float2*>(LA + k0 + 8 * j) = make_float2(s[j][0], s[j][1]);
            *reinterpret_cast<float2*>(LB + k0 + 8 * j) = make_float2(s[j][2], s[j][3]);
        }

        // ---- mask + online softmax (cancellation-free) ----
        const float* smKM = reinterpret_cast<const float*>(
            reinterpret_cast<const char*>(sm32) + oKM[bi]);
        float mxA = -3.0e38f, mxB = -3.0e38f;
        #pragma unroll
        for (int j = 0; j < 8; j++) {
            float km0 = smKM[8 * j + 2 * cq], km1 = smKM[8 * j + 2 * cq + 1];
            float uA0 = 1.0f - qmA * km0, uA1 = 1.0f - qmA * km1;
            float uB0 = 1.0f - qmB * km0, uB1 = 1.0f - qmB * km1;
            s[j][0] = fmaf(-1e5f, uA0, s[j][0]);
            s[j][1] = fmaf(-1e5f, uA1, s[j][1]);
            s[j][2] = fmaf(-1e5f, uB0, s[j][2]);
            s[j][3] = fmaf(-1e5f, uB1, s[j][3]);
            mxA = fmaxf(mxA, fmaxf(s[j][0], s[j][1]));
            mxB = fmaxf(mxB, fmaxf(s[j][2], s[j][3]));
        }
        mxA = fmaxf(mxA, __shfl_xor_sync(0xffffffffu, mxA, 1));
        mxA = fmaxf(mxA, __shfl_xor_sync(0xffffffffu, mxA, 2));
        mxB = fmaxf(mxB, __shfl_xor_sync(0xffffffffu, mxB, 1));
        mxB = fmaxf(mxB, __shfl_xor_sync(0xffffffffu, mxB, 2));
        float mnA = fmaxf(mA, mxA), mnB = fmaxf(mB, mxB);
        float rsA = __expf(mA - mnA), rsB = __expf(mB - mnB);
        mA = mnA; mB = mnB;
        sA *= rsA; sB *= rsB;
        #pragma unroll
        for (int j = 0; j < 8; j++) {
            s[j][0] = __expf(s[j][0] - mnA);
            s[j][1] = __expf(s[j][1] - mnA);
            s[j][2] = __expf(s[j][2] - mnB);
            s[j][3] = __expf(s[j][3] - mnB);
            sA += s[j][0] + s[j][1];
            sB += s[j][2] + s[j][3];
        }
        #pragma unroll
        for (int dt = 0; dt < 8; dt++) {
            o[dt][0] *= rsA; o[dt][1] *= rsA;
            o[dt][2] *= rsB; o[dt][3] *= rsB;
        }

        // ---- O += P.V (P single fp16, V single fp16) ----
        uint32_t vb = sb + oV[bi];
        #pragma unroll
        for (int ks = 0; ks < 4; ks++) {
            uint32_t pa[4];
            pa[0] = packf16(s[2*ks][0],   s[2*ks][1]);
            pa[1] = packf16(s[2*ks][2],   s[2*ks][3]);
            pa[2] = packf16(s[2*ks+1][0], s[2*ks+1][1]);
            pa[3] = packf16(s[2*ks+1][2], s[2*ks+1][3]);
            uint32_t vf[4][4];
            #pragma unroll
            for (int dg = 0; dg < 4; dg++) {
                uint32_t voff = (uint32_t)((16 * ks + (lane & 15)) * 144
                                           + (lane >> 4) * 16 + dg * 32);
                ldsm_x4t(vf[dg], vb + voff);
            }
            #pragma unroll
            for (int dg = 0; dg < 4; dg++) { uint32_t b2[2] = {vf[dg][0], vf[dg][1]}; mma_f16(o[2*dg],   pa, b2); }
            #pragma unroll
            for (int dg = 0; dg < 4; dg++) { uint32_t b2[2] = {vf[dg][2], vf[dg][3]}; mma_f16(o[2*dg+1], pa, b2); }
        }
    }

    // final sum reduce + normalize + store
    sA += __shfl_xor_sync(0xffffffffu, sA, 1);
    sA += __shfl_xor_sync(0xffffffffu, sA, 2);
    sB += __shfl_xor_sync(0xffffffffu, sB, 1);
    sB += __shfl_xor_sync(0xffffffffu, sB, 2);
    float invA = 1.0f / sA, invB = 1.0f / sB;
    float* OA = g_OH + ((size_t)b * SEQ + q0 + rowA) * DM + h * HD + 2 * cq;
    float* OB = OA + (size_t)8 * DM;
    #pragma unroll
    for (int dt = 0; dt < 8; dt++) {
        *reinterpret_cast<float2*>(OA + 8 * dt) =
            make_float2(o[dt][0] * invA, o[dt][1] * invA);
        *reinterpret_cast<float2*>(OB + 8 * dt) =
            make_float2(o[dt][2] * invB, o[dt][3] * invB);
    }
}

// ---------------------------------------------------------------------------
// Launch. Output: [out (4*2048*768)] then [logits_raw (48*2048*2048)]
// ---------------------------------------------------------------------------
extern "C" void kernel_launch(void* const* d_in, const int* in_sizes, int n_in,
                              void* d_out, int out_size)
{
    const float* x  = (const float*)d_in[0];
    const float* qm = (const float*)d_in[1];
    const float* Wq = (const float*)d_in[2];
    const float* Wk = (const float*)d_in[3];
    const float* Wv = (const float*)d_in[4];
    const float* Wo = (const float*)d_in[5];

    float* out    = (float*)d_out;
    float* logits = out + (size_t)MROWS * DM;

    const int GEMM_SMEM  = 75776;   // 2 x 9472 u32
    const int FLASH_SMEM = 55808;
    cudaFuncSetAttribute(mma_gemm,
                         cudaFuncAttributeMaxDynamicSharedMemorySize, GEMM_SMEM);
    cudaFuncSetAttribute(flash_mma,
                         cudaFuncAttributeMaxDynamicSharedMemorySize, FLASH_SMEM);

    mma_gemm <<<dim3(6, 64, 3), 256, GEMM_SMEM>>>(x, Wq, Wk, Wv, nullptr, 0);
    flash_mma<<<dim3(16, 48), 256, FLASH_SMEM>>>(qm, logits);
    mma_gemm <<<dim3(6, 64, 1), 256, GEMM_SMEM>>>(nullptr, Wo, Wo, Wo, out, 3);
}

// round 11
// speedup vs baseline: 9.0900x; 1.1284x over previous
#include <cuda_runtime.h>
#include <cuda_fp16.h>
#include <math.h>
#include <stdint.h>

#define BATCH 4
#define SEQ   2048
#define DM    768
#define NH    12
#define HD    64
#define MROWS (BATCH*SEQ)   // 8192
#define BHT   (BATCH*NH)    // 48

// ---------------- misc helpers ----------------
__device__ __forceinline__ uint32_t s2u(const void* p) {
    uint32_t a;
    asm("{ .reg .u64 t; cvta.to.shared.u64 t, %1; cvt.u32.u64 %0, t; }"
        : "=r"(a) : "l"(p));
    return a;
}
// cp.async 16B (sm_80 PTX)
__device__ __forceinline__ void cpa16(uint32_t dst, const void* src) {
    asm volatile("cp.async.cg.shared.global [%0], [%1], 16;"
                 :: "r"(dst), "l"(src) : "memory");
}
#define CP_COMMIT() asm volatile("cp.async.commit_group;" ::: "memory")
#define CP_WAIT0()  asm volatile("cp.async.wait_group 0;" ::: "memory")

// ---------------- mma.sync helpers (sm_80 PTX, legacy HMMA) ----------------
__device__ __forceinline__ void ldsm_x4(uint32_t* r, uint32_t addr) {
    asm volatile("ldmatrix.sync.aligned.m8n8.x4.shared.b16 {%0,%1,%2,%3}, [%4];"
                 : "=r"(r[0]), "=r"(r[1]), "=r"(r[2]), "=r"(r[3]) : "r"(addr));
}
__device__ __forceinline__ void ldsm_x4t(uint32_t* r, uint32_t addr) {
    asm volatile("ldmatrix.sync.aligned.m8n8.x4.trans.shared.b16 {%0,%1,%2,%3}, [%4];"
                 : "=r"(r[0]), "=r"(r[1]), "=r"(r[2]), "=r"(r[3]) : "r"(addr));
}
// fp16 mma
__device__ __forceinline__ void mma_f16(float* c, const uint32_t* a, const uint32_t* b) {
    asm volatile(
        "mma.sync.aligned.m16n8k16.row.col.f32.f16.f16.f32 "
        "{%0,%1,%2,%3}, {%4,%5,%6,%7}, {%8,%9}, {%0,%1,%2,%3};"
        : "+f"(c[0]), "+f"(c[1]), "+f"(c[2]), "+f"(c[3])
        : "r"(a[0]), "r"(a[1]), "r"(a[2]), "r"(a[3]), "r"(b[0]), "r"(b[1]));
}
// fp16 pack (low half = a)
__device__ __forceinline__ uint32_t packf16(float a, float b) {
    __half2 h = __floats2half2_rn(a, b);
    return *reinterpret_cast<uint32_t*>(&h);
}
// fp16 split: hi pair + residual pair
__device__ __forceinline__ void splitf16(float a, float b, uint32_t& h, uint32_t& l) {
    __half2 hh = __floats2half2_rn(a, b);
    float2 bk = __half22float2(hh);
    __half2 ll = __floats2half2_rn(a - bk.x, b - bk.y);
    h = *reinterpret_cast<uint32_t*>(&hh);
    l = *reinterpret_cast<uint32_t*>(&ll);
}
// STS A: single fp16 (no residual)
__device__ __forceinline__ void stsA(float4 v, uint32_t* base, int idx) {
    *reinterpret_cast<uint2*>(base + idx) =
        make_uint2(packf16(v.x, v.y), packf16(v.z, v.w));
}
// STS B: fp16 hi + residual lo
__device__ __forceinline__ void stsB(float4 v, uint32_t* bH, uint32_t* bL, int idx) {
    uint32_t h0, l0, h1, l1;
    splitf16(v.x, v.y, h0, l0);
    splitf16(v.z, v.w, h1, l1);
    *reinterpret_cast<uint2*>(bH + idx) = make_uint2(h0, h1);
    *reinterpret_cast<uint2*>(bL + idx) = make_uint2(l0, l1);
}

// Scratch. Q/K/V single fp16 pairs (UNSCALED q; 1/8 applied post-MMA in flash).
__device__ uint32_t g_Qf[(size_t)BHT*SEQ*HD/2];
__device__ uint32_t g_Kf[(size_t)BHT*SEQ*HD/2];
__device__ uint32_t g_Vf[(size_t)BHT*SEQ*HD/2];
__device__ float    g_OH[(size_t)MROWS*DM];      // attention out f32, [b,s,h*64+d]

// ---------------------------------------------------------------------------
// fp16 2-term mma.sync GEMM: C[8192x768] = A @ W.
// A single fp16, B = Bh + Bl residual; C = Ah.Bh + Ah.Bl.
// 128x128 CTA tile, BK=32, 8 warps (2M x 4N), double-buffered smem.
// mode 0/1/2: -> g_{Q,K,V}f fp16   mode 3: A=g_OH -> lin_out f32
// ---------------------------------------------------------------------------
__global__ __launch_bounds__(256) void mma_gemm(
    const float* __restrict__ Ain,
    const float* __restrict__ W0, const float* __restrict__ W1,
    const float* __restrict__ W2,
    float* __restrict__ lin_out, int base_mode)
{
    extern __shared__ uint32_t smg[];
    // per-buffer (u32): A 0 (128x20), Bh 2560 (32x68), Bl 4736; stride 6912
    const uint32_t BUFU = 6912;

    int mode = base_mode + blockIdx.z;
    const float* W = (mode == 0) ? W0 : (mode == 1) ? W1 : (mode == 2) ? W2 : W0;
    const float* A = (mode == 3) ? (const float*)g_OH : Ain;

    int tid  = threadIdx.x;
    int wid  = tid >> 5, lane = tid & 31;
    int warpM = wid & 1, warpN = wid >> 1;
    int m0 = blockIdx.y * 128, n0 = blockIdx.x * 128;

    float acc[4][4][4];
    #pragma unroll
    for (int i = 0; i < 4; i++)
        #pragma unroll
        for (int j = 0; j < 4; j++)
            #pragma unroll
            for (int k = 0; k < 4; k++) acc[i][j][k] = 0.f;

    uint32_t sbg = s2u(smg);
    uint32_t aLane = (uint32_t)((lane & 15) * 80 + (lane >> 4) * 16 + warpM * 5120);
    uint32_t bLane = (uint32_t)((lane & 15) * 272 + (lane >> 4) * 16 + warpN * 64);

    float4 av[4], bv[4];
    // LDG chunk 0, STS buf0
    #pragma unroll
    for (int it = 0; it < 4; it++) {
        int i = tid + it * 256;
        int r = i >> 3, c4 = (i & 7) * 4;
        av[it] = *reinterpret_cast<const float4*>(A + (size_t)(m0 + r) * DM + c4);
        int rb = i >> 5, cb = (i & 31) * 4;
        bv[it] = *reinterpret_cast<const float4*>(W + (size_t)rb * DM + n0 + cb);
    }
    #pragma unroll
    for (int it = 0; it < 4; it++) {
        int i = tid + it * 256;
        int r = i >> 3, c4 = (i & 7) * 4;
        stsA(av[it], smg, r * 20 + (c4 >> 1));
        int rb = i >> 5, cb = (i & 31) * 4;
        stsB(bv[it], smg + 2560, smg + 4736, rb * 68 + (cb >> 1));
    }
    // LDG chunk 1 into regs
    #pragma unroll
    for (int it = 0; it < 4; it++) {
        int i = tid + it * 256;
        int r = i >> 3, c4 = (i & 7) * 4;
        av[it] = *reinterpret_cast<const float4*>(A + (size_t)(m0 + r) * DM + 32 + c4);
        int rb = i >> 5, cb = (i & 31) * 4;
        bv[it] = *reinterpret_cast<const float4*>(W + (size_t)(32 + rb) * DM + n0 + cb);
    }
    __syncthreads();

    for (int c = 0; c < 24; c++) {
        if (c < 23) {
            uint32_t* base = smg + ((c + 1) & 1) * BUFU;
            #pragma unroll
            for (int it = 0; it < 4; it++) {
                int i = tid + it * 256;
                int r = i >> 3, c4 = (i & 7) * 4;
                stsA(av[it], base, r * 20 + (c4 >> 1));
                int rb = i >> 5, cb = (i & 31) * 4;
                stsB(bv[it], base + 2560, base + 4736, rb * 68 + (cb >> 1));
            }
        }
        if (c < 22) {
            int k0n = (c + 2) * 32;
            #pragma unroll
            for (int it = 0; it < 4; it++) {
                int i = tid + it * 256;
                int r = i >> 3, c4 = (i & 7) * 4;
                av[it] = *reinterpret_cast<const float4*>(
                    A + (size_t)(m0 + r) * DM + k0n + c4);
                int rb = i >> 5, cb = (i & 31) * 4;
                bv[it] = *reinterpret_cast<const float4*>(
                    W + (size_t)(k0n + rb) * DM + n0 + cb);
            }
        }
        uint32_t off = sbg + (uint32_t)(c & 1) * (BUFU * 4);
        uint32_t aH = off, bH = off + 10240, bL = off + 18944;
        #pragma unroll
        for (int ks = 0; ks < 2; ks++) {
            uint32_t bh[4][2], bl[4][2];
            #pragma unroll
            for (int np = 0; np < 2; np++) {
                uint32_t r4[4];
                ldsm_x4t(r4, bH + bLane + ks * 4352 + np * 32);
                bh[np*2][0] = r4[0]; bh[np*2][1] = r4[1];
                bh[np*2+1][0] = r4[2]; bh[np*2+1][1] = r4[3];
                ldsm_x4t(r4, bL + bLane + ks * 4352 + np * 32);
                bl[np*2][0] = r4[0]; bl[np*2][1] = r4[1];
                bl[np*2+1][0] = r4[2]; bl[np*2+1][1] = r4[3];
            }
            #pragma unroll
            for (int mtp = 0; mtp < 2; mtp++) {
                uint32_t a0h[4], a1h[4];
                ldsm_x4(a0h, aH + aLane + (2*mtp) * 1280 + ks * 32);
                ldsm_x4(a1h, aH + aLane + (2*mtp+1) * 1280 + ks * 32);
                // pass 1: ah x bh (8 distinct accs)
                #pragma unroll
                for (int nt = 0; nt < 4; nt++) mma_f16(acc[2*mtp][nt],   a0h, bh[nt]);
                #pragma unroll
                for (int nt = 0; nt < 4; nt++) mma_f16(acc[2*mtp+1][nt], a1h, bh[nt]);
                // pass 2: ah x bl
                #pragma unroll
                for (int nt = 0; nt < 4; nt++) mma_f16(acc[2*mtp][nt],   a0h, bl[nt]);
                #pragma unroll
                for (int nt = 0; nt < 4; nt++) mma_f16(acc[2*mtp+1][nt], a1h, bl[nt]);
            }
        }
        __syncthreads();
    }

    int rl = lane >> 2, cl = (lane & 3) * 2;
    if (mode == 3) {
        #pragma unroll
        for (int mt = 0; mt < 4; mt++) {
            int m = m0 + warpM * 64 + mt * 16 + rl;
            #pragma unroll
            for (int nt = 0; nt < 4; nt++) {
                int n = n0 + warpN * 32 + nt * 8 + cl;
                *reinterpret_cast<float2*>(lin_out + (size_t)m * DM + n) =
                    make_float2(acc[mt][nt][0], acc[mt][nt][1]);
                *reinterpret_cast<float2*>(lin_out + (size_t)(m + 8) * DM + n) =
                    make_float2(acc[mt][nt][2], acc[mt][nt][3]);
            }
        }
    } else {
        uint32_t* dst = (mode == 0) ? g_Qf : (mode == 1) ? g_Kf : g_Vf;
        #pragma unroll
        for (int mt = 0; mt < 4; mt++) {
            int m = m0 + warpM * 64 + mt * 16 + rl;
            int b = m >> 11, s = m & 2047;
            #pragma unroll
            for (int nt = 0; nt < 4; nt++) {
                int n = n0 + warpN * 32 + nt * 8 + cl;
                int h = n >> 6, d = n & 63;
                size_t base = ((size_t)(b * NH + h) * SEQ + s) * 32 + (d >> 1);
                dst[base] = packf16(acc[mt][nt][0], acc[mt][nt][1]);
                dst[base + 8 * 32] = packf16(acc[mt][nt][2], acc[mt][nt][3]);
            }
        }
    }
}

// ---------------------------------------------------------------------------
// Flash attention (unchanged from R10): fp16 single-term S (x0.125 post-MMA),
// P single fp16, V single fp16. Double-buffered K/V/kmask, one sync + one
// wait per tile. ~56KB smem, 2 CTAs/SM.
// ---------------------------------------------------------------------------
__global__ __launch_bounds__(256, 2) void flash_mma(
    const float* __restrict__ q_mask, float* __restrict__ logits)
{
    extern __shared__ uint32_t sm32[];
    uint32_t sb = s2u(sm32);
    const uint32_t oQ = 0;
    const uint32_t oK[2]  = {18432u, 27648u};
    const uint32_t oV[2]  = {36864u, 46080u};
    const uint32_t oKM[2] = {55296u, 55552u};

    int bh = blockIdx.y;
    int b  = bh / NH;
    int h  = bh - b * NH;
    int q0 = blockIdx.x * 128;
    int tid = threadIdx.x;
    int w = tid >> 5, lane = tid & 31;
    int rq = lane >> 2, cq = lane & 3;

    #pragma unroll
    for (int it = 0; it < 4; it++) {
        int i = tid + it * 256;
        int r = i >> 3, ch = i & 7;
        size_t src = ((size_t)(bh * SEQ + q0 + r)) * 32 + ch * 4;
        cpa16(sb + oQ + r * 144 + ch * 16, g_Qf + src);
    }
    #pragma unroll
    for (int it = 0; it < 2; it++) {
        int i = tid + it * 256;
        int r = i >> 3, ch = i & 7;
        size_t src = ((size_t)(bh * SEQ + r)) * 32 + ch * 4;
        cpa16(sb + oK[0] + r * 144 + ch * 16, g_Kf + src);
        cpa16(sb + oV[0] + r * 144 + ch * 16, g_Vf + src);
    }
    if (tid < 16)
        cpa16(sb + oKM[0] + tid * 16, q_mask + (size_t)b * SEQ + tid * 4);
    CP_COMMIT();

    int rowA = 16 * w + rq;
    float qmA = q_mask[(size_t)b * SEQ + q0 + rowA];
    float qmB = q_mask[(size_t)b * SEQ + q0 + rowA + 8];
    float mA = -3.0e38f, mB = -3.0e38f, sA = 0.f, sB = 0.f;
    float o[8][4];
    #pragma unroll
    for (int i = 0; i < 8; i++)
        #pragma unroll
        for (int j = 0; j < 4; j++) o[i][j] = 0.f;
    uint32_t qh[4][4];

    float* LA = logits + ((size_t)bh * SEQ + q0 + rowA) * SEQ + 2 * cq;
    float* LB = LA + (size_t)8 * SEQ;

    for (int t = 0; t < 32; t++) {
        int k0 = t * 64;
        int bi = t & 1;
        CP_WAIT0();
        __syncthreads();

        if (t == 0) {
            uint32_t qoff = (uint32_t)((16 * w + (lane & 15)) * 144 + (lane >> 4) * 16);
            #pragma unroll
            for (int ks = 0; ks < 4; ks++)
                ldsm_x4(qh[ks], sb + oQ + qoff + ks * 32);
        }
        if (t + 1 < 32) {
            int nb = (t + 1) & 1;
            int k1 = k0 + 64;
            #pragma unroll
            for (int it = 0; it < 2; it++) {
                int i = tid + it * 256;
                int r = i >> 3, ch = i & 7;
                size_t src = ((size_t)(bh * SEQ + k1 + r)) * 32 + ch * 4;
                cpa16(sb + oK[nb] + r * 144 + ch * 16, g_Kf + src);
                cpa16(sb + oV[nb] + r * 144 + ch * 16, g_Vf + src);
            }
            if (tid < 16)
                cpa16(sb + oKM[nb] + tid * 16, q_mask + (size_t)b * SEQ + k1 + tid * 4);
            CP_COMMIT();
        }

        // ---- S = Q.K^T ----
        uint32_t kb = sb + oK[bi];
        float s[8][4];
        #pragma unroll
        for (int i = 0; i < 8; i++)
            #pragma unroll
            for (int j = 0; j < 4; j++) s[i][j] = 0.f;
        #pragma unroll
        for (int ks = 0; ks < 4; ks++) {
            uint32_t kf[4][4];
            #pragma unroll
            for (int g = 0; g < 4; g++) {
                uint32_t koff = (uint32_t)((16 * g + (lane & 15)) * 144
                                           + (lane >> 4) * 16 + ks * 32);
                ldsm_x4(kf[g], kb + koff);
            }
            #pragma unroll
            for (int g = 0; g < 4; g++) { uint32_t b2[2] = {kf[g][0], kf[g][2]}; mma_f16(s[2*g],   qh[ks], b2); }
            #pragma unroll
            for (int g = 0; g < 4; g++) { uint32_t b2[2] = {kf[g][1], kf[g][3]}; mma_f16(s[2*g+1], qh[ks], b2); }
        }

        #pragma unroll
        for (int j = 0; j < 8; j++) {
            s[j][0] *= 0.125f; s[j][1] *= 0.125f;
            s[j][2] *= 0.125f; s[j][3] *= 0.125f;
            *reinterpret_cast<float2*>(LA + k0 + 8 * j) = make_float2(s[j][0], s[j][1]);
            *reinterpret_cast<float2*>(LB + k0 + 8 * j) = make_float2(s[j][2], s[j][3]);
        }

        const float* smKM = reinterpret_cast<const float*>(
            reinterpret_cast<const char*>(sm32) + oKM[bi]);
        float mxA = -3.0e38f, mxB = -3.0e38f;
        #pragma unroll
        for (int j = 0; j < 8; j++) {
            float km0 = smKM[8 * j + 2 * cq], km1 = smKM[8 * j + 2 * cq + 1];
            float uA0 = 1.0f - qmA * km0, uA1 = 1.0f - qmA * km1;
            float uB0 = 1.0f - qmB * km0, uB1 = 1.0f - qmB * km1;
            s[j][0] = fmaf(-1e5f, uA0, s[j][0]);
            s[j][1] = fmaf(-1e5f, uA1, s[j][1]);
            s[j][2] = fmaf(-1e5f, uB0, s[j][2]);
            s[j][3] = fmaf(-1e5f, uB1, s[j][3]);
            mxA = fmaxf(mxA, fmaxf(s[j][0], s[j][1]));
            mxB = fmaxf(mxB, fmaxf(s[j][2], s[j][3]));
        }
        mxA = fmaxf(mxA, __shfl_xor_sync(0xffffffffu, mxA, 1));
        mxA = fmaxf(mxA, __shfl_xor_sync(0xffffffffu, mxA, 2));
        mxB = fmaxf(mxB, __shfl_xor_sync(0xffffffffu, mxB, 1));
        mxB = fmaxf(mxB, __shfl_xor_sync(0xffffffffu, mxB, 2));
        float mnA = fmaxf(mA, mxA), mnB = fmaxf(mB, mxB);
        float rsA = __expf(mA - mnA), rsB = __expf(mB - mnB);
        mA = mnA; mB = mnB;
        sA *= rsA; sB *= rsB;
        #pragma unroll
        for (int j = 0; j < 8; j++) {
            s[j][0] = __expf(s[j][0] - mnA);
            s[j][1] = __expf(s[j][1] - mnA);
            s[j][2] = __expf(s[j][2] - mnB);
            s[j][3] = __expf(s[j][3] - mnB);
            sA += s[j][0] + s[j][1];
            sB += s[j][2] + s[j][3];
        }
        #pragma unroll
        for (int dt = 0; dt < 8; dt++) {
            o[dt][0] *= rsA; o[dt][1] *= rsA;
            o[dt][2] *= rsB; o[dt][3] *= rsB;
        }

        // ---- O += P.V ----
        uint32_t vb = sb + oV[bi];
        #pragma unroll
        for (int ks = 0; ks < 4; ks++) {
            uint32_t pa[4];
            pa[0] = packf16(s[2*ks][0],   s[2*ks][1]);
            pa[1] = packf16(s[2*ks][2],   s[2*ks][3]);
            pa[2] = packf16(s[2*ks+1][0], s[2*ks+1][1]);
            pa[3] = packf16(s[2*ks+1][2], s[2*ks+1][3]);
            uint32_t vf[4][4];
            #pragma unroll
            for (int dg = 0; dg < 4; dg++) {
                uint32_t voff = (uint32_t)((16 * ks + (lane & 15)) * 144
                                           + (lane >> 4) * 16 + dg * 32);
                ldsm_x4t(vf[dg], vb + voff);
            }
            #pragma unroll
            for (int dg = 0; dg < 4; dg++) { uint32_t b2[2] = {vf[dg][0], vf[dg][1]}; mma_f16(o[2*dg],   pa, b2); }
            #pragma unroll
            for (int dg = 0; dg < 4; dg++) { uint32_t b2[2] = {vf[dg][2], vf[dg][3]}; mma_f16(o[2*dg+1], pa, b2); }
        }
    }

    sA += __shfl_xor_sync(0xffffffffu, sA, 1);
    sA += __shfl_xor_sync(0xffffffffu, sA, 2);
    sB += __shfl_xor_sync(0xffffffffu, sB, 1);
    sB += __shfl_xor_sync(0xffffffffu, sB, 2);
    float invA = 1.0f / sA, invB = 1.0f / sB;
    float* OA = g_OH + ((size_t)b * SEQ + q0 + rowA) * DM + h * HD + 2 * cq;
    float* OB = OA + (size_t)8 * DM;
    #pragma unroll
    for (int dt = 0; dt < 8; dt++) {
        *reinterpret_cast<float2*>(OA + 8 * dt) =
            make_float2(o[dt][0] * invA, o[dt][1] * invA);
        *reinterpret_cast<float2*>(OB + 8 * dt) =
            make_float2(o[dt][2] * invB, o[dt][3] * invB);
    }
}

// ---------------------------------------------------------------------------
// Launch. Output: [out (4*2048*768)] then [logits_raw (48*2048*2048)]
// ---------------------------------------------------------------------------
extern "C" void kernel_launch(void* const* d_in, const int* in_sizes, int n_in,
                              void* d_out, int out_size)
{
    const float* x  = (const float*)d_in[0];
    const float* qm = (const float*)d_in[1];
    const float* Wq = (const float*)d_in[2];
    const float* Wk = (const float*)d_in[3];
    const float* Wv = (const float*)d_in[4];
    const float* Wo = (const float*)d_in[5];

    float* out    = (float*)d_out;
    float* logits = out + (size_t)MROWS * DM;

    const int GEMM_SMEM  = 55296;   // 2 x 6912 u32
    const int FLASH_SMEM = 55808;
    cudaFuncSetAttribute(mma_gemm,
                         cudaFuncAttributeMaxDynamicSharedMemorySize, GEMM_SMEM);
    cudaFuncSetAttribute(flash_mma,
                         cudaFuncAttributeMaxDynamicSharedMemorySize, FLASH_SMEM);

    mma_gemm <<<dim3(6, 64, 3), 256, GEMM_SMEM>>>(x, Wq, Wk, Wv, nullptr, 0);
    flash_mma<<<dim3(16, 48), 256, FLASH_SMEM>>>(qm, logits);
    mma_gemm <<<dim3(6, 64, 1), 256, GEMM_SMEM>>>(nullptr, Wo, Wo, Wo, out, 3);
}

// round 12
// speedup vs baseline: 9.3522x; 1.0288x over previous
#include <cuda_runtime.h>
#include <cuda_fp16.h>
#include <math.h>
#include <stdint.h>

#define BATCH 4
#define SEQ   2048
#define DM    768
#define NH    12
#define HD    64
#define MROWS (BATCH*SEQ)   // 8192
#define BHT   (BATCH*NH)    // 48

// ---------------- misc helpers ----------------
__device__ __forceinline__ uint32_t s2u(const void* p) {
    uint32_t a;
    asm("{ .reg .u64 t; cvta.to.shared.u64 t, %1; cvt.u32.u64 %0, t; }"
        : "=r"(a) : "l"(p));
    return a;
}
// cp.async 16B (sm_80 PTX)
__device__ __forceinline__ void cpa16(uint32_t dst, const void* src) {
    asm volatile("cp.async.cg.shared.global [%0], [%1], 16;"
                 :: "r"(dst), "l"(src) : "memory");
}
#define CP_COMMIT() asm volatile("cp.async.commit_group;" ::: "memory")
#define CP_WAIT0()  asm volatile("cp.async.wait_group 0;" ::: "memory")

// ---------------- mma.sync helpers (sm_80 PTX, legacy HMMA) ----------------
__device__ __forceinline__ void ldsm_x4(uint32_t* r, uint32_t addr) {
    asm volatile("ldmatrix.sync.aligned.m8n8.x4.shared.b16 {%0,%1,%2,%3}, [%4];"
                 : "=r"(r[0]), "=r"(r[1]), "=r"(r[2]), "=r"(r[3]) : "r"(addr));
}
__device__ __forceinline__ void ldsm_x4t(uint32_t* r, uint32_t addr) {
    asm volatile("ldmatrix.sync.aligned.m8n8.x4.trans.shared.b16 {%0,%1,%2,%3}, [%4];"
                 : "=r"(r[0]), "=r"(r[1]), "=r"(r[2]), "=r"(r[3]) : "r"(addr));
}
// fp16 mma
__device__ __forceinline__ void mma_f16(float* c, const uint32_t* a, const uint32_t* b) {
    asm volatile(
        "mma.sync.aligned.m16n8k16.row.col.f32.f16.f16.f32 "
        "{%0,%1,%2,%3}, {%4,%5,%6,%7}, {%8,%9}, {%0,%1,%2,%3};"
        : "+f"(c[0]), "+f"(c[1]), "+f"(c[2]), "+f"(c[3])
        : "r"(a[0]), "r"(a[1]), "r"(a[2]), "r"(a[3]), "r"(b[0]), "r"(b[1]));
}
// fp16 pack (low half = a)
__device__ __forceinline__ uint32_t packf16(float a, float b) {
    __half2 h = __floats2half2_rn(a, b);
    return *reinterpret_cast<uint32_t*>(&h);
}
// fp16 split: hi pair + residual pair
__device__ __forceinline__ void splitf16(float a, float b, uint32_t& h, uint32_t& l) {
    __half2 hh = __floats2half2_rn(a, b);
    float2 bk = __half22float2(hh);
    __half2 ll = __floats2half2_rn(a - bk.x, b - bk.y);
    h = *reinterpret_cast<uint32_t*>(&hh);
    l = *reinterpret_cast<uint32_t*>(&ll);
}
// STS A: single fp16 (no residual)
__device__ __forceinline__ void stsA(float4 v, uint32_t* base, int idx) {
    *reinterpret_cast<uint2*>(base + idx) =
        make_uint2(packf16(v.x, v.y), packf16(v.z, v.w));
}
// STS B: fp16 hi + residual lo
__device__ __forceinline__ void stsB(float4 v, uint32_t* bH, uint32_t* bL, int idx) {
    uint32_t h0, l0, h1, l1;
    splitf16(v.x, v.y, h0, l0);
    splitf16(v.z, v.w, h1, l1);
    *reinterpret_cast<uint2*>(bH + idx) = make_uint2(h0, h1);
    *reinterpret_cast<uint2*>(bL + idx) = make_uint2(l0, l1);
}

// Scratch. Q/K/V single fp16 pairs. Q PRE-SCALED by 1/8 (exact, power of 2).
__device__ uint32_t g_Qf[(size_t)BHT*SEQ*HD/2];
__device__ uint32_t g_Kf[(size_t)BHT*SEQ*HD/2];
__device__ uint32_t g_Vf[(size_t)BHT*SEQ*HD/2];
__device__ float    g_OH[(size_t)MROWS*DM];      // attention out f32, [b,s,h*64+d]

// ---------------------------------------------------------------------------
// fp16 2-term mma.sync GEMM: C[8192x768] = A @ W.
// A single fp16, B = Bh + Bl residual; C = Ah.Bh + Ah.Bl.
// 128x128 CTA tile, BK=32, 8 warps (2M x 4N), double-buffered smem.
// __launch_bounds__(256,2): cap 128 regs -> 2 CTAs/SM.
// mode 0/1/2: -> g_{Q,K,V}f fp16 (Q scaled 1/8)   mode 3: A=g_OH -> lin_out
// ---------------------------------------------------------------------------
__global__ __launch_bounds__(256, 2) void mma_gemm(
    const float* __restrict__ Ain,
    const float* __restrict__ W0, const float* __restrict__ W1,
    const float* __restrict__ W2,
    float* __restrict__ lin_out, int base_mode)
{
    extern __shared__ uint32_t smg[];
    // per-buffer (u32): A 0 (128x20), Bh 2560 (32x68), Bl 4736; stride 6912
    const uint32_t BUFU = 6912;

    int mode = base_mode + blockIdx.z;
    const float* W = (mode == 0) ? W0 : (mode == 1) ? W1 : (mode == 2) ? W2 : W0;
    const float* A = (mode == 3) ? (const float*)g_OH : Ain;

    int tid  = threadIdx.x;
    int wid  = tid >> 5, lane = tid & 31;
    int warpM = wid & 1, warpN = wid >> 1;
    int m0 = blockIdx.y * 128, n0 = blockIdx.x * 128;

    float acc[4][4][4];
    #pragma unroll
    for (int i = 0; i < 4; i++)
        #pragma unroll
        for (int j = 0; j < 4; j++)
            #pragma unroll
            for (int k = 0; k < 4; k++) acc[i][j][k] = 0.f;

    uint32_t sbg = s2u(smg);
    uint32_t aLane = (uint32_t)((lane & 15) * 80 + (lane >> 4) * 16 + warpM * 5120);
    uint32_t bLane = (uint32_t)((lane & 15) * 272 + (lane >> 4) * 16 + warpN * 64);

    float4 av[4], bv[4];
    // LDG chunk 0, STS buf0
    #pragma unroll
    for (int it = 0; it < 4; it++) {
        int i = tid + it * 256;
        int r = i >> 3, c4 = (i & 7) * 4;
        av[it] = *reinterpret_cast<const float4*>(A + (size_t)(m0 + r) * DM + c4);
        int rb = i >> 5, cb = (i & 31) * 4;
        bv[it] = *reinterpret_cast<const float4*>(W + (size_t)rb * DM + n0 + cb);
    }
    #pragma unroll
    for (int it = 0; it < 4; it++) {
        int i = tid + it * 256;
        int r = i >> 3, c4 = (i & 7) * 4;
        stsA(av[it], smg, r * 20 + (c4 >> 1));
        int rb = i >> 5, cb = (i & 31) * 4;
        stsB(bv[it], smg + 2560, smg + 4736, rb * 68 + (cb >> 1));
    }
    // LDG chunk 1 into regs
    #pragma unroll
    for (int it = 0; it < 4; it++) {
        int i = tid + it * 256;
        int r = i >> 3, c4 = (i & 7) * 4;
        av[it] = *reinterpret_cast<const float4*>(A + (size_t)(m0 + r) * DM + 32 + c4);
        int rb = i >> 5, cb = (i & 31) * 4;
        bv[it] = *reinterpret_cast<const float4*>(W + (size_t)(32 + rb) * DM + n0 + cb);
    }
    __syncthreads();

    for (int c = 0; c < 24; c++) {
        if (c < 23) {
            uint32_t* base = smg + ((c + 1) & 1) * BUFU;
            #pragma unroll
            for (int it = 0; it < 4; it++) {
                int i = tid + it * 256;
                int r = i >> 3, c4 = (i & 7) * 4;
                stsA(av[it], base, r * 20 + (c4 >> 1));
                int rb = i >> 5, cb = (i & 31) * 4;
                stsB(bv[it], base + 2560, base + 4736, rb * 68 + (cb >> 1));
            }
        }
        if (c < 22) {
            int k0n = (c + 2) * 32;
            #pragma unroll
            for (int it = 0; it < 4; it++) {
                int i = tid + it * 256;
                int r = i >> 3, c4 = (i & 7) * 4;
                av[it] = *reinterpret_cast<const float4*>(
                    A + (size_t)(m0 + r) * DM + k0n + c4);
                int rb = i >> 5, cb = (i & 31) * 4;
                bv[it] = *reinterpret_cast<const float4*>(
                    W + (size_t)(k0n + rb) * DM + n0 + cb);
            }
        }
        uint32_t off = sbg + (uint32_t)(c & 1) * (BUFU * 4);
        uint32_t aH = off, bH = off + 10240, bL = off + 18944;
        #pragma unroll
        for (int ks = 0; ks < 2; ks++) {
            uint32_t bh[4][2], bl[4][2];
            #pragma unroll
            for (int np = 0; np < 2; np++) {
                uint32_t r4[4];
                ldsm_x4t(r4, bH + bLane + ks * 4352 + np * 32);
                bh[np*2][0] = r4[0]; bh[np*2][1] = r4[1];
                bh[np*2+1][0] = r4[2]; bh[np*2+1][1] = r4[3];
                ldsm_x4t(r4, bL + bLane + ks * 4352 + np * 32);
                bl[np*2][0] = r4[0]; bl[np*2][1] = r4[1];
                bl[np*2+1][0] = r4[2]; bl[np*2+1][1] = r4[3];
            }
            #pragma unroll
            for (int mtp = 0; mtp < 2; mtp++) {
                uint32_t a0h[4], a1h[4];
                ldsm_x4(a0h, aH + aLane + (2*mtp) * 1280 + ks * 32);
                ldsm_x4(a1h, aH + aLane + (2*mtp+1) * 1280 + ks * 32);
                #pragma unroll
                for (int nt = 0; nt < 4; nt++) mma_f16(acc[2*mtp][nt],   a0h, bh[nt]);
                #pragma unroll
                for (int nt = 0; nt < 4; nt++) mma_f16(acc[2*mtp+1][nt], a1h, bh[nt]);
                #pragma unroll
                for (int nt = 0; nt < 4; nt++) mma_f16(acc[2*mtp][nt],   a0h, bl[nt]);
                #pragma unroll
                for (int nt = 0; nt < 4; nt++) mma_f16(acc[2*mtp+1][nt], a1h, bl[nt]);
            }
        }
        __syncthreads();
    }

    int rl = lane >> 2, cl = (lane & 3) * 2;
    if (mode == 3) {
        #pragma unroll
        for (int mt = 0; mt < 4; mt++) {
            int m = m0 + warpM * 64 + mt * 16 + rl;
            #pragma unroll
            for (int nt = 0; nt < 4; nt++) {
                int n = n0 + warpN * 32 + nt * 8 + cl;
                *reinterpret_cast<float2*>(lin_out + (size_t)m * DM + n) =
                    make_float2(acc[mt][nt][0], acc[mt][nt][1]);
                *reinterpret_cast<float2*>(lin_out + (size_t)(m + 8) * DM + n) =
                    make_float2(acc[mt][nt][2], acc[mt][nt][3]);
            }
        }
    } else {
        // Q pre-scaled by 1/8 (exact power-of-2; bit-equivalent to post-scale)
        float alpha = (mode == 0) ? 0.125f : 1.0f;
        uint32_t* dst = (mode == 0) ? g_Qf : (mode == 1) ? g_Kf : g_Vf;
        #pragma unroll
        for (int mt = 0; mt < 4; mt++) {
            int m = m0 + warpM * 64 + mt * 16 + rl;
            int b = m >> 11, s = m & 2047;
            #pragma unroll
            for (int nt = 0; nt < 4; nt++) {
                int n = n0 + warpN * 32 + nt * 8 + cl;
                int h = n >> 6, d = n & 63;
                size_t base = ((size_t)(b * NH + h) * SEQ + s) * 32 + (d >> 1);
                dst[base] = packf16(acc[mt][nt][0] * alpha, acc[mt][nt][1] * alpha);
                dst[base + 8 * 32] = packf16(acc[mt][nt][2] * alpha, acc[mt][nt][3] * alpha);
            }
        }
    }
}

// ---------------------------------------------------------------------------
// Flash attention: fp16 single-term S (Q pre-scaled -> S is final logits),
// P single fp16, V single fp16. Double-buffered K/V/kmask, one sync + one
// wait per tile. ~56KB smem, 2 CTAs/SM.
// ---------------------------------------------------------------------------
__global__ __launch_bounds__(256, 2) void flash_mma(
    const float* __restrict__ q_mask, float* __restrict__ logits)
{
    extern __shared__ uint32_t sm32[];
    uint32_t sb = s2u(sm32);
    const uint32_t oQ = 0;
    const uint32_t oK[2]  = {18432u, 27648u};
    const uint32_t oV[2]  = {36864u, 46080u};
    const uint32_t oKM[2] = {55296u, 55552u};

    int bh = blockIdx.y;
    int b  = bh / NH;
    int h  = bh - b * NH;
    int q0 = blockIdx.x * 128;
    int tid = threadIdx.x;
    int w = tid >> 5, lane = tid & 31;
    int rq = lane >> 2, cq = lane & 3;

    #pragma unroll
    for (int it = 0; it < 4; it++) {
        int i = tid + it * 256;
        int r = i >> 3, ch = i & 7;
        size_t src = ((size_t)(bh * SEQ + q0 + r)) * 32 + ch * 4;
        cpa16(sb + oQ + r * 144 + ch * 16, g_Qf + src);
    }
    #pragma unroll
    for (int it = 0; it < 2; it++) {
        int i = tid + it * 256;
        int r = i >> 3, ch = i & 7;
        size_t src = ((size_t)(bh * SEQ + r)) * 32 + ch * 4;
        cpa16(sb + oK[0] + r * 144 + ch * 16, g_Kf + src);
        cpa16(sb + oV[0] + r * 144 + ch * 16, g_Vf + src);
    }
    if (tid < 16)
        cpa16(sb + oKM[0] + tid * 16, q_mask + (size_t)b * SEQ + tid * 4);
    CP_COMMIT();

    int rowA = 16 * w + rq;
    float qmA = q_mask[(size_t)b * SEQ + q0 + rowA];
    float qmB = q_mask[(size_t)b * SEQ + q0 + rowA + 8];
    float mA = -3.0e38f, mB = -3.0e38f, sA = 0.f, sB = 0.f;
    float o[8][4];
    #pragma unroll
    for (int i = 0; i < 8; i++)
        #pragma unroll
        for (int j = 0; j < 4; j++) o[i][j] = 0.f;
    uint32_t qh[4][4];

    float* LA = logits + ((size_t)bh * SEQ + q0 + rowA) * SEQ + 2 * cq;
    float* LB = LA + (size_t)8 * SEQ;

    for (int t = 0; t < 32; t++) {
        int k0 = t * 64;
        int bi = t & 1;
        CP_WAIT0();
        __syncthreads();

        if (t == 0) {
            uint32_t qoff = (uint32_t)((16 * w + (lane & 15)) * 144 + (lane >> 4) * 16);
            #pragma unroll
            for (int ks = 0; ks < 4; ks++)
                ldsm_x4(qh[ks], sb + oQ + qoff + ks * 32);
        }
        if (t + 1 < 32) {
            int nb = (t + 1) & 1;
            int k1 = k0 + 64;
            #pragma unroll
            for (int it = 0; it < 2; it++) {
                int i = tid + it * 256;
                int r = i >> 3, ch = i & 7;
                size_t src = ((size_t)(bh * SEQ + k1 + r)) * 32 + ch * 4;
                cpa16(sb + oK[nb] + r * 144 + ch * 16, g_Kf + src);
                cpa16(sb + oV[nb] + r * 144 + ch * 16, g_Vf + src);
            }
            if (tid < 16)
                cpa16(sb + oKM[nb] + tid * 16, q_mask + (size_t)b * SEQ + k1 + tid * 4);
            CP_COMMIT();
        }

        // ---- S = Q.K^T (Q pre-scaled: S is final raw logits) ----
        uint32_t kb = sb + oK[bi];
        float s[8][4];
        #pragma unroll
        for (int i = 0; i < 8; i++)
            #pragma unroll
            for (int j = 0; j < 4; j++) s[i][j] = 0.f;
        #pragma unroll
        for (int ks = 0; ks < 4; ks++) {
            uint32_t kf[4][4];
            #pragma unroll
            for (int g = 0; g < 4; g++) {
                uint32_t koff = (uint32_t)((16 * g + (lane & 15)) * 144
                                           + (lane >> 4) * 16 + ks * 32);
                ldsm_x4(kf[g], kb + koff);
            }
            #pragma unroll
            for (int g = 0; g < 4; g++) { uint32_t b2[2] = {kf[g][0], kf[g][2]}; mma_f16(s[2*g],   qh[ks], b2); }
            #pragma unroll
            for (int g = 0; g < 4; g++) { uint32_t b2[2] = {kf[g][1], kf[g][3]}; mma_f16(s[2*g+1], qh[ks], b2); }
        }

        #pragma unroll
        for (int j = 0; j < 8; j++) {
            *reinterpret_cast<float2*>(LA + k0 + 8 * j) = make_float2(s[j][0], s[j][1]);
            *reinterpret_cast<float2*>(LB + k0 + 8 * j) = make_float2(s[j][2], s[j][3]);
        }

        const float* smKM = reinterpret_cast<const float*>(
            reinterpret_cast<const char*>(sm32) + oKM[bi]);
        float mxA = -3.0e38f, mxB = -3.0e38f;
        #pragma unroll
        for (int j = 0; j < 8; j++) {
            float km0 = smKM[8 * j + 2 * cq], km1 = smKM[8 * j + 2 * cq + 1];
            float uA0 = 1.0f - qmA * km0, uA1 = 1.0f - qmA * km1;
            float uB0 = 1.0f - qmB * km0, uB1 = 1.0f - qmB * km1;
            s[j][0] = fmaf(-1e5f, uA0, s[j][0]);
            s[j][1] = fmaf(-1e5f, uA1, s[j][1]);
            s[j][2] = fmaf(-1e5f, uB0, s[j][2]);
            s[j][3] = fmaf(-1e5f, uB1, s[j][3]);
            mxA = fmaxf(mxA, fmaxf(s[j][0], s[j][1]));
            mxB = fmaxf(mxB, fmaxf(s[j][2], s[j][3]));
        }
        mxA = fmaxf(mxA, __shfl_xor_sync(0xffffffffu, mxA, 1));
        mxA = fmaxf(mxA, __shfl_xor_sync(0xffffffffu, mxA, 2));
        mxB = fmaxf(mxB, __shfl_xor_sync(0xffffffffu, mxB, 1));
        mxB = fmaxf(mxB, __shfl_xor_sync(0xffffffffu, mxB, 2));
        float mnA = fmaxf(mA, mxA), mnB = fmaxf(mB, mxB);
        float rsA = __expf(mA - mnA), rsB = __expf(mB - mnB);
        mA = mnA; mB = mnB;
        sA *= rsA; sB *= rsB;
        #pragma unroll
        for (int j = 0; j < 8; j++) {
            s[j][0] = __expf(s[j][0] - mnA);
            s[j][1] = __expf(s[j][1] - mnA);
            s[j][2] = __expf(s[j][2] - mnB);
            s[j][3] = __expf(s[j][3] - mnB);
            sA += s[j][0] + s[j][1];
            sB += s[j][2] + s[j][3];
        }
        #pragma unroll
        for (int dt = 0; dt < 8; dt++) {
            o[dt][0] *= rsA; o[dt][1] *= rsA;
            o[dt][2] *= rsB; o[dt][3] *= rsB;
        }

        // ---- O += P.V ----
        uint32_t vb = sb + oV[bi];
        #pragma unroll
        for (int ks = 0; ks < 4; ks++) {
            uint32_t pa[4];
            pa[0] = packf16(s[2*ks][0],   s[2*ks][1]);
            pa[1] = packf16(s[2*ks][2],   s[2*ks][3]);
            pa[2] = packf16(s[2*ks+1][0], s[2*ks+1][1]);
            pa[3] = packf16(s[2*ks+1][2], s[2*ks+1][3]);
            uint32_t vf[4][4];
            #pragma unroll
            for (int dg = 0; dg < 4; dg++) {
                uint32_t voff = (uint32_t)((16 * ks + (lane & 15)) * 144
                                           + (lane >> 4) * 16 + dg * 32);
                ldsm_x4t(vf[dg], vb + voff);
            }
            #pragma unroll
            for (int dg = 0; dg < 4; dg++) { uint32_t b2[2] = {vf[dg][0], vf[dg][1]}; mma_f16(o[2*dg],   pa, b2); }
            #pragma unroll
            for (int dg = 0; dg < 4; dg++) { uint32_t b2[2] = {vf[dg][2], vf[dg][3]}; mma_f16(o[2*dg+1], pa, b2); }
        }
    }

    sA += __shfl_xor_sync(0xffffffffu, sA, 1);
    sA += __shfl_xor_sync(0xffffffffu, sA, 2);
    sB += __shfl_xor_sync(0xffffffffu, sB, 1);
    sB += __shfl_xor_sync(0xffffffffu, sB, 2);
    float invA = 1.0f / sA, invB = 1.0f / sB;
    float* OA = g_OH + ((size_t)b * SEQ + q0 + rowA) * DM + h * HD + 2 * cq;
    float* OB = OA + (size_t)8 * DM;
    #pragma unroll
    for (int dt = 0; dt < 8; dt++) {
        *reinterpret_cast<float2*>(OA + 8 * dt) =
            make_float2(o[dt][0] * invA, o[dt][1] * invA);
        *reinterpret_cast<float2*>(OB + 8 * dt) =
            make_float2(o[dt][2] * invB, o[dt][3] * invB);
    }
}

// ---------------------------------------------------------------------------
// Launch. Output: [out (4*2048*768)] then [logits_raw (48*2048*2048)]
// ---------------------------------------------------------------------------
extern "C" void kernel_launch(void* const* d_in, const int* in_sizes, int n_in,
                              void* d_out, int out_size)
{
    const float* x  = (const float*)d_in[0];
    const float* qm = (const float*)d_in[1];
    const float* Wq = (const float*)d_in[2];
    const float* Wk = (const float*)d_in[3];
    const float* Wv = (const float*)d_in[4];
    const float* Wo = (const float*)d_in[5];

    float* out    = (float*)d_out;
    float* logits = out + (size_t)MROWS * DM;

    const int GEMM_SMEM  = 55296;   // 2 x 6912 u32
    const int FLASH_SMEM = 55808;
    cudaFuncSetAttribute(mma_gemm,
                         cudaFuncAttributeMaxDynamicSharedMemorySize, GEMM_SMEM);
    cudaFuncSetAttribute(flash_mma,
                         cudaFuncAttributeMaxDynamicSharedMemorySize, FLASH_SMEM);

    mma_gemm <<<dim3(6, 64, 3), 256, GEMM_SMEM>>>(x, Wq, Wk, Wv, nullptr, 0);
    flash_mma<<<dim3(16, 48), 256, FLASH_SMEM>>>(qm, logits);
    mma_gemm <<<dim3(6, 64, 1), 256, GEMM_SMEM>>>(nullptr, Wo, Wo, Wo, out, 3);
}